// round 1
// baseline (speedup 1.0000x reference)
#include <cuda_runtime.h>

#define EPS 1e-5f

// Problem constants: B=8, S=1024, E=512, H=8, dh=64, M = B*S = 8192
static const int E_ = 512;

// ---------------- scratch (no allocation allowed) ----------------
__device__ float g_qin [8192 * 512];
__device__ float g_kvin[8192 * 512];
__device__ float g_q   [8192 * 512];
__device__ float g_kv  [8192 * 1024];
__device__ float g_attn[64LL * 1024 * 1024];   // [b*8+h][q][k] fp32, 256 MB
__device__ float g_ctx [8192 * 512];
__device__ float g_x   [8192 * 512];
__device__ float g_xn  [8192 * 512];
__device__ float g_ff  [8192 * 512];

// ---------------- LayerNorm (row = 512 elems, 128 threads) -------
// out = LN(x [+ x2]) * w + b
__global__ void ln_kernel(const float* __restrict__ x, const float* __restrict__ x2,
                          const float* __restrict__ w, const float* __restrict__ bb,
                          float* __restrict__ out)
{
    int row = blockIdx.x;
    int t = threadIdx.x;                     // 128 threads * float4 = 512
    const float4* xr = (const float4*)(x + (long)row * 512);
    float4 v = xr[t];
    if (x2) {
        float4 v2 = ((const float4*)(x2 + (long)row * 512))[t];
        v.x += v2.x; v.y += v2.y; v.z += v2.z; v.w += v2.w;
    }
    float s  = v.x + v.y + v.z + v.w;
    float sq = v.x*v.x + v.y*v.y + v.z*v.z + v.w*v.w;
    #pragma unroll
    for (int o = 16; o > 0; o >>= 1) {
        s  += __shfl_xor_sync(0xffffffffu, s,  o);
        sq += __shfl_xor_sync(0xffffffffu, sq, o);
    }
    __shared__ float ss[4], ssq[4];
    int wid = t >> 5, lane = t & 31;
    if (lane == 0) { ss[wid] = s; ssq[wid] = sq; }
    __syncthreads();
    s  = ss[0]  + ss[1]  + ss[2]  + ss[3];
    sq = ssq[0] + ssq[1] + ssq[2] + ssq[3];
    float mu  = s  * (1.0f / 512.0f);
    float var = sq * (1.0f / 512.0f) - mu * mu;
    float inv = rsqrtf(var + EPS);
    float4 wv = ((const float4*)w)[t];
    float4 bv = ((const float4*)bb)[t];
    float4 o4;
    o4.x = (v.x - mu) * inv * wv.x + bv.x;
    o4.y = (v.y - mu) * inv * wv.y + bv.y;
    o4.z = (v.z - mu) * inv * wv.z + bv.z;
    o4.w = (v.w - mu) * inv * wv.w + bv.w;
    ((float4*)(out + (long)row * 512))[t] = o4;
}

// ---------------- generic NT GEMM: C = scale * A @ B^T (+bias)(+resid) ----
// A[m][k] with lda, B[n][k] with ldb (both K-contiguous). Batched over z:
// z -> (b = z/Hn, h = z%Hn); base offsets A += b*sAb + h*sAh, same for B;
// C += z*sCz. 64x64 tile, BK=16, 256 threads, 4x4 per thread.
// All dims assumed multiples of tile sizes (true for this problem).
__global__ void gemm_nt(const float* __restrict__ A, int lda, long sAb, long sAh,
                        const float* __restrict__ Bm, int ldb, long sBb, long sBh,
                        float* __restrict__ C, int ldc, long sCz,
                        int K, float scale,
                        const float* __restrict__ bias,
                        const float* __restrict__ resid,
                        int Hn)
{
    int z = blockIdx.z;
    int b_ = z / Hn, h_ = z % Hn;
    const float* Ab = A  + (long)b_ * sAb + (long)h_ * sAh;
    const float* Bb = Bm + (long)b_ * sBb + (long)h_ * sBh;
    float* Cb = C + (long)z * sCz;

    __shared__ float As[16][68];
    __shared__ float Bs[16][68];

    int bm = blockIdx.y * 64, bn = blockIdx.x * 64;
    int tid = threadIdx.x;
    int ty = tid >> 4, tx = tid & 15;

    float acc[4][4] = {{0.f}};

    for (int k0 = 0; k0 < K; k0 += 16) {
        #pragma unroll
        for (int i = 0; i < 4; i++) {
            int idx = tid + i * 256;
            int m = idx >> 4, kk = idx & 15;
            As[kk][m] = Ab[(long)(bm + m) * lda + k0 + kk];
            Bs[kk][m] = Bb[(long)(bn + m) * ldb + k0 + kk];
        }
        __syncthreads();
        #pragma unroll
        for (int kk = 0; kk < 16; kk++) {
            float a[4], bt[4];
            #pragma unroll
            for (int i = 0; i < 4; i++) a[i]  = As[kk][ty * 4 + i];
            #pragma unroll
            for (int j = 0; j < 4; j++) bt[j] = Bs[kk][tx * 4 + j];
            #pragma unroll
            for (int i = 0; i < 4; i++)
                #pragma unroll
                for (int j = 0; j < 4; j++)
                    acc[i][j] += a[i] * bt[j];
        }
        __syncthreads();
    }

    #pragma unroll
    for (int i = 0; i < 4; i++) {
        int m = bm + ty * 4 + i;
        #pragma unroll
        for (int j = 0; j < 4; j++) {
            int n = bn + tx * 4 + j;
            float v = acc[i][j] * scale;
            if (bias)  v += bias[n];
            if (resid) v += resid[(long)m * ldc + n];
            Cb[(long)m * ldc + n] = v;
        }
    }
}

// ---------------- ctx = P @ V (NN) per (b,h) ----------------------
// P: [1024,1024] contiguous at g_attn + z*1M. V: rows k, cols n at
// kv + b*1M + 512 + h*64, ld 1024. C: ctx + b*S*512 + h*64, ld 512.
__global__ void gemm_nn_ctx(const float* __restrict__ P, const float* __restrict__ V,
                            float* __restrict__ C)
{
    int z = blockIdx.z;
    int b_ = z >> 3, h_ = z & 7;
    const float* Pb = P + (long)z * 1024 * 1024;
    const float* Vb = V + (long)b_ * 1024 * 1024 + 512 + h_ * 64;
    float* Cb = C + (long)b_ * 1024 * 512 + h_ * 64;

    __shared__ float Ps[16][68];
    __shared__ float Vs[16][68];

    int bm = blockIdx.x * 64;
    int tid = threadIdx.x;
    int ty = tid >> 4, tx = tid & 15;

    float acc[4][4] = {{0.f}};

    for (int k0 = 0; k0 < 1024; k0 += 16) {
        #pragma unroll
        for (int i = 0; i < 4; i++) {
            int idx = tid + i * 256;
            { int m = idx >> 4, kk = idx & 15;
              Ps[kk][m] = Pb[(long)(bm + m) * 1024 + k0 + kk]; }
            { int kk = idx >> 6, n = idx & 63;
              Vs[kk][n] = Vb[(long)(k0 + kk) * 1024 + n]; }
        }
        __syncthreads();
        #pragma unroll
        for (int kk = 0; kk < 16; kk++) {
            float a[4], bt[4];
            #pragma unroll
            for (int i = 0; i < 4; i++) a[i]  = Ps[kk][ty * 4 + i];
            #pragma unroll
            for (int j = 0; j < 4; j++) bt[j] = Vs[kk][tx * 4 + j];
            #pragma unroll
            for (int i = 0; i < 4; i++)
                #pragma unroll
                for (int j = 0; j < 4; j++)
                    acc[i][j] += a[i] * bt[j];
        }
        __syncthreads();
    }

    #pragma unroll
    for (int i = 0; i < 4; i++)
        #pragma unroll
        for (int j = 0; j < 4; j++)
            Cb[(long)(bm + ty * 4 + i) * 512 + tx * 4 + j] = acc[i][j];
}

// ---------------- softmax over last dim (1024), in place ----------
__global__ void softmax_kernel(float* __restrict__ attn)
{
    long row = (long)blockIdx.y * 1024 + blockIdx.x;   // z*1024 + q
    float* p = attn + row * 1024;
    int t = threadIdx.x;                                // 256 threads * 4
    float4 v = ((float4*)p)[t];

    float mx = fmaxf(fmaxf(v.x, v.y), fmaxf(v.z, v.w));
    #pragma unroll
    for (int o = 16; o > 0; o >>= 1)
        mx = fmaxf(mx, __shfl_xor_sync(0xffffffffu, mx, o));
    __shared__ float sm[8];
    int wid = t >> 5, lane = t & 31;
    if (lane == 0) sm[wid] = mx;
    __syncthreads();
    mx = sm[0];
    #pragma unroll
    for (int i = 1; i < 8; i++) mx = fmaxf(mx, sm[i]);

    float4 e;
    e.x = __expf(v.x - mx); e.y = __expf(v.y - mx);
    e.z = __expf(v.z - mx); e.w = __expf(v.w - mx);
    float s = e.x + e.y + e.z + e.w;
    #pragma unroll
    for (int o = 16; o > 0; o >>= 1)
        s += __shfl_xor_sync(0xffffffffu, s, o);
    __shared__ float ssum[8];
    if (lane == 0) ssum[wid] = s;
    __syncthreads();
    s = ssum[0] + ssum[1] + ssum[2] + ssum[3] + ssum[4] + ssum[5] + ssum[6] + ssum[7];
    float inv = 1.0f / s;
    e.x *= inv; e.y *= inv; e.z *= inv; e.w *= inv;
    ((float4*)p)[t] = e;
}

// ---------------- attn_weights = mean over H --------------------
__global__ void mean_heads(const float* __restrict__ attn, float* __restrict__ out)
{
    long i = (long)blockIdx.x * blockDim.x + threadIdx.x;   // over 8M = B*S*S
    long b_ = i >> 20;                 // / (1024*1024)
    long rem = i & 1048575;
    const float* p = attn + (b_ << 23) + rem;   // b*8*1M + rem
    float s = 0.f;
    #pragma unroll
    for (int h = 0; h < 8; h++) s += p[(long)h << 20];
    out[i] = s * 0.125f;
}

// ---------------- launch ----------------------------------------
extern "C" void kernel_launch(void* const* d_in, const int* in_sizes, int n_in,
                              void* d_out, int out_size)
{
    (void)in_sizes; (void)n_in; (void)out_size;
    const float* Zab   = (const float*)d_in[0];
    const float* Za    = (const float*)d_in[1];
    const float* ln_w  = (const float*)d_in[2];
    const float* ln_b  = (const float*)d_in[3];
    const float* in_w  = (const float*)d_in[4];
    const float* in_b  = (const float*)d_in[5];
    const float* out_w = (const float*)d_in[6];
    const float* out_b = (const float*)d_in[7];
    const float* ff_w  = (const float*)d_in[8];
    const float* ff_b  = (const float*)d_in[9];

    float* out_final = (float*)d_out;                      // 8192*512
    float* out_attnw = (float*)d_out + 8192L * 512;        // 8*1024*1024

    float *qin, *kvin, *q, *kv, *attn, *ctx, *x, *xn, *ff;
    cudaGetSymbolAddress((void**)&qin,  g_qin);
    cudaGetSymbolAddress((void**)&kvin, g_kvin);
    cudaGetSymbolAddress((void**)&q,    g_q);
    cudaGetSymbolAddress((void**)&kv,   g_kv);
    cudaGetSymbolAddress((void**)&attn, g_attn);
    cudaGetSymbolAddress((void**)&ctx,  g_ctx);
    cudaGetSymbolAddress((void**)&x,    g_x);
    cudaGetSymbolAddress((void**)&xn,   g_xn);
    cudaGetSymbolAddress((void**)&ff,   g_ff);

    // 1) LayerNorms of both inputs
    ln_kernel<<<8192, 128>>>(Zab, nullptr, ln_w, ln_b, qin);
    ln_kernel<<<8192, 128>>>(Za,  nullptr, ln_w, ln_b, kvin);

    // 2) q = qin @ Wq^T + bq     (M=8192, N=512, K=512)
    gemm_nt<<<dim3(8, 128, 1), 256>>>(qin, 512, 0, 0,
                                      in_w, 512, 0, 0,
                                      q, 512, 0,
                                      512, 1.0f, in_b, nullptr, 1);
    // 3) kv = kvin @ [Wk;Wv]^T + [bk;bv]   (N=1024)
    gemm_nt<<<dim3(16, 128, 1), 256>>>(kvin, 512, 0, 0,
                                       in_w + 512L * 512, 512, 0, 0,
                                       kv, 1024, 0,
                                       512, 1.0f, in_b + 512, nullptr, 1);

    // 4) scores = scale * q @ k^T, per (b,h)  -> attn [64][1024][1024]
    gemm_nt<<<dim3(16, 16, 64), 256>>>(q, 512, 1024L * 512, 64,
                                       kv, 1024, 1024L * 1024, 64,
                                       attn, 1024, 1024L * 1024,
                                       64, 0.125f, nullptr, nullptr, 8);

    // 5) softmax rows (in place)
    softmax_kernel<<<dim3(1024, 64), 256>>>(attn);

    // 6) attn_weights = mean over heads
    mean_heads<<<32768, 256>>>(attn, out_attnw);

    // 7) ctx = attn @ v, per (b,h)
    gemm_nn_ctx<<<dim3(16, 1, 64), 256>>>(attn, kv, ctx);

    // 8) x = ctx @ Wo^T + bo + Zab   (residual fused)
    gemm_nt<<<dim3(8, 128, 1), 256>>>(ctx, 512, 0, 0,
                                      out_w, 512, 0, 0,
                                      x, 512, 0,
                                      512, 1.0f, out_b, Zab, 1);

    // 9) x_n = LN(x)
    ln_kernel<<<8192, 128>>>(x, nullptr, ln_w, ln_b, xn);

    // 10) ff = x_n @ ff_w^T + ff_b
    gemm_nt<<<dim3(8, 128, 1), 256>>>(xn, 512, 0, 0,
                                      ff_w, 512, 0, 0,
                                      ff, 512, 0,
                                      512, 1.0f, ff_b, nullptr, 1);

    // 11) final = LN(x_n + ff)  -> d_out
    ln_kernel<<<8192, 128>>>(xn, ff, ln_w, ln_b, out_final);
}

// round 2
// speedup vs baseline: 1.3360x; 1.3360x over previous
#include <cuda_runtime.h>

#define EPS 1e-5f

// Problem constants: B=8, S=1024, E=512, H=8, dh=64, M = B*S = 8192

// ---------------- scratch (no allocation allowed) ----------------
__device__ float g_qin [8192 * 512];
__device__ float g_kvin[8192 * 512];
__device__ float g_q   [8192 * 512];
__device__ float g_kv  [8192 * 1024];
__device__ float g_attn[64LL * 1024 * 1024];   // [b*8+h][q][k] fp32, 256 MB
__device__ float g_ctx [8192 * 512];
__device__ float g_x   [8192 * 512];
__device__ float g_xn  [8192 * 512];
__device__ float g_ff  [8192 * 512];

// ---------------- LayerNorm (row = 512 elems, 128 threads) -------
__global__ void ln_kernel(const float* __restrict__ x, const float* __restrict__ x2,
                          const float* __restrict__ w, const float* __restrict__ bb,
                          float* __restrict__ out)
{
    int row = blockIdx.x;
    int t = threadIdx.x;                     // 128 threads * float4 = 512
    const float4* xr = (const float4*)(x + (long)row * 512);
    float4 v = xr[t];
    if (x2) {
        float4 v2 = ((const float4*)(x2 + (long)row * 512))[t];
        v.x += v2.x; v.y += v2.y; v.z += v2.z; v.w += v2.w;
    }
    float s  = v.x + v.y + v.z + v.w;
    float sq = v.x*v.x + v.y*v.y + v.z*v.z + v.w*v.w;
    #pragma unroll
    for (int o = 16; o > 0; o >>= 1) {
        s  += __shfl_xor_sync(0xffffffffu, s,  o);
        sq += __shfl_xor_sync(0xffffffffu, sq, o);
    }
    __shared__ float ss[4], ssq[4];
    int wid = t >> 5, lane = t & 31;
    if (lane == 0) { ss[wid] = s; ssq[wid] = sq; }
    __syncthreads();
    s  = ss[0]  + ss[1]  + ss[2]  + ss[3];
    sq = ssq[0] + ssq[1] + ssq[2] + ssq[3];
    float mu  = s  * (1.0f / 512.0f);
    float var = sq * (1.0f / 512.0f) - mu * mu;
    float inv = rsqrtf(var + EPS);
    float4 wv = ((const float4*)w)[t];
    float4 bv = ((const float4*)bb)[t];
    float4 o4;
    o4.x = (v.x - mu) * inv * wv.x + bv.x;
    o4.y = (v.y - mu) * inv * wv.y + bv.y;
    o4.z = (v.z - mu) * inv * wv.z + bv.z;
    o4.w = (v.w - mu) * inv * wv.w + bv.w;
    ((float4*)(out + (long)row * 512))[t] = o4;
}

// ---------------- NT GEMM 128x128, 8x8 micro, BK=16 --------------
// C = scale * A @ B^T (+bias)(+resid).  A[m][k] lda, B[n][k] ldb.
// Batched over z: b = z/Hn, h = z%Hn.  All dims multiples of tiles.
__global__ void __launch_bounds__(256)
gemm_nt128(const float* __restrict__ A, int lda, long sAb, long sAh,
           const float* __restrict__ Bm, int ldb, long sBb, long sBh,
           float* __restrict__ C, int ldc, long sCz,
           int K, float scale,
           const float* __restrict__ bias,
           const float* __restrict__ resid,
           int Hn)
{
    int z = blockIdx.z;
    int b_ = z / Hn, h_ = z % Hn;
    const float* Ab = A  + (long)b_ * sAb + (long)h_ * sAh;
    const float* Bb = Bm + (long)b_ * sBb + (long)h_ * sBh;
    float* Cb = C + (long)z * sCz;

    __shared__ float As[16][128];
    __shared__ float Bs[16][128];

    int bm = blockIdx.y * 128, bn = blockIdx.x * 128;
    int tid = threadIdx.x;
    int ty = tid >> 4, tx = tid & 15;

    // per-thread global-load coordinates: 2 float4 each for A and B
    int rowL[2], colL[2];
    #pragma unroll
    for (int i = 0; i < 2; i++) {
        int idx = tid * 2 + i;
        rowL[i] = idx >> 2;          // 0..127
        colL[i] = (idx & 3) * 4;     // 0,4,8,12
    }

    float4 ra[2], rb[2];
    #pragma unroll
    for (int i = 0; i < 2; i++) {
        ra[i] = *(const float4*)(Ab + (long)(bm + rowL[i]) * lda + colL[i]);
        rb[i] = *(const float4*)(Bb + (long)(bn + rowL[i]) * ldb + colL[i]);
    }

    float acc[8][8];
    #pragma unroll
    for (int i = 0; i < 8; i++)
        #pragma unroll
        for (int j = 0; j < 8; j++) acc[i][j] = 0.f;

    for (int k0 = 0; k0 < K; k0 += 16) {
        #pragma unroll
        for (int i = 0; i < 2; i++) {
            As[colL[i]+0][rowL[i]] = ra[i].x;
            As[colL[i]+1][rowL[i]] = ra[i].y;
            As[colL[i]+2][rowL[i]] = ra[i].z;
            As[colL[i]+3][rowL[i]] = ra[i].w;
            Bs[colL[i]+0][rowL[i]] = rb[i].x;
            Bs[colL[i]+1][rowL[i]] = rb[i].y;
            Bs[colL[i]+2][rowL[i]] = rb[i].z;
            Bs[colL[i]+3][rowL[i]] = rb[i].w;
        }
        __syncthreads();

        if (k0 + 16 < K) {
            #pragma unroll
            for (int i = 0; i < 2; i++) {
                ra[i] = *(const float4*)(Ab + (long)(bm + rowL[i]) * lda + k0 + 16 + colL[i]);
                rb[i] = *(const float4*)(Bb + (long)(bn + rowL[i]) * ldb + k0 + 16 + colL[i]);
            }
        }

        #pragma unroll
        for (int kk = 0; kk < 16; kk++) {
            float4 a0 = *(const float4*)&As[kk][ty * 8];
            float4 a1 = *(const float4*)&As[kk][ty * 8 + 4];
            float4 b0 = *(const float4*)&Bs[kk][tx * 8];
            float4 b1 = *(const float4*)&Bs[kk][tx * 8 + 4];
            float av[8] = {a0.x, a0.y, a0.z, a0.w, a1.x, a1.y, a1.z, a1.w};
            float bv[8] = {b0.x, b0.y, b0.z, b0.w, b1.x, b1.y, b1.z, b1.w};
            #pragma unroll
            for (int i = 0; i < 8; i++)
                #pragma unroll
                for (int j = 0; j < 8; j++)
                    acc[i][j] += av[i] * bv[j];
        }
        __syncthreads();
    }

    #pragma unroll
    for (int i = 0; i < 8; i++) {
        long m = bm + ty * 8 + i;
        #pragma unroll
        for (int jv = 0; jv < 8; jv += 4) {
            int n = bn + tx * 8 + jv;
            float4 v;
            v.x = acc[i][jv+0] * scale;
            v.y = acc[i][jv+1] * scale;
            v.z = acc[i][jv+2] * scale;
            v.w = acc[i][jv+3] * scale;
            if (bias) {
                v.x += bias[n+0]; v.y += bias[n+1];
                v.z += bias[n+2]; v.w += bias[n+3];
            }
            if (resid) {
                float4 r4 = *(const float4*)(resid + m * ldc + n);
                v.x += r4.x; v.y += r4.y; v.z += r4.z; v.w += r4.w;
            }
            *(float4*)(Cb + m * ldc + n) = v;
        }
    }
}

// ---------------- ctx = P @ V (NN) per (b,h), 128x64 tile --------
// P: [1024,1024] at g_attn + z*1M. V rows k at kv + b*1M + 512 + h*64, ld 1024.
// C: ctx + b*S*512 + h*64, ld 512.  8x4 micro, BK=16.
__global__ void __launch_bounds__(256)
gemm_nn_ctx128(const float* __restrict__ P, const float* __restrict__ V,
               float* __restrict__ C)
{
    int z = blockIdx.z;
    int b_ = z >> 3, h_ = z & 7;
    const float* Pb = P + (long)z * 1024 * 1024;
    const float* Vb = V + (long)b_ * 1024 * 1024 + 512 + h_ * 64;
    float* Cb = C + (long)b_ * 1024 * 512 + h_ * 64;

    __shared__ float Ps[16][128];
    __shared__ float Vs[16][64];

    int bm = blockIdx.x * 128;
    int tid = threadIdx.x;
    int ty = tid >> 4, tx = tid & 15;

    int rowL[2], colL[2];
    #pragma unroll
    for (int i = 0; i < 2; i++) {
        int idx = tid * 2 + i;
        rowL[i] = idx >> 2;
        colL[i] = (idx & 3) * 4;
    }
    int vk = tid >> 4;           // 0..15
    int vn = (tid & 15) * 4;     // 0..60

    float4 rp[2], rv;
    #pragma unroll
    for (int i = 0; i < 2; i++)
        rp[i] = *(const float4*)(Pb + (long)(bm + rowL[i]) * 1024 + colL[i]);
    rv = *(const float4*)(Vb + (long)vk * 1024 + vn);

    float acc[8][4];
    #pragma unroll
    for (int i = 0; i < 8; i++)
        #pragma unroll
        for (int j = 0; j < 4; j++) acc[i][j] = 0.f;

    for (int k0 = 0; k0 < 1024; k0 += 16) {
        #pragma unroll
        for (int i = 0; i < 2; i++) {
            Ps[colL[i]+0][rowL[i]] = rp[i].x;
            Ps[colL[i]+1][rowL[i]] = rp[i].y;
            Ps[colL[i]+2][rowL[i]] = rp[i].z;
            Ps[colL[i]+3][rowL[i]] = rp[i].w;
        }
        *(float4*)&Vs[vk][vn] = rv;
        __syncthreads();

        if (k0 + 16 < 1024) {
            #pragma unroll
            for (int i = 0; i < 2; i++)
                rp[i] = *(const float4*)(Pb + (long)(bm + rowL[i]) * 1024 + k0 + 16 + colL[i]);
            rv = *(const float4*)(Vb + (long)(k0 + 16 + vk) * 1024 + vn);
        }

        #pragma unroll
        for (int kk = 0; kk < 16; kk++) {
            float4 a0 = *(const float4*)&Ps[kk][ty * 8];
            float4 a1 = *(const float4*)&Ps[kk][ty * 8 + 4];
            float4 b0 = *(const float4*)&Vs[kk][tx * 4];
            float av[8] = {a0.x, a0.y, a0.z, a0.w, a1.x, a1.y, a1.z, a1.w};
            float bv[4] = {b0.x, b0.y, b0.z, b0.w};
            #pragma unroll
            for (int i = 0; i < 8; i++)
                #pragma unroll
                for (int j = 0; j < 4; j++)
                    acc[i][j] += av[i] * bv[j];
        }
        __syncthreads();
    }

    #pragma unroll
    for (int i = 0; i < 8; i++) {
        long m = bm + ty * 8 + i;
        float4 v;
        v.x = acc[i][0]; v.y = acc[i][1]; v.z = acc[i][2]; v.w = acc[i][3];
        *(float4*)(Cb + m * 512 + tx * 4) = v;
    }
}

// ---------------- softmax over last dim (1024), in place ----------
__global__ void softmax_kernel(float* __restrict__ attn)
{
    long row = (long)blockIdx.y * 1024 + blockIdx.x;   // z*1024 + q
    float* p = attn + row * 1024;
    int t = threadIdx.x;                                // 256 threads * 4
    float4 v = ((float4*)p)[t];

    float mx = fmaxf(fmaxf(v.x, v.y), fmaxf(v.z, v.w));
    #pragma unroll
    for (int o = 16; o > 0; o >>= 1)
        mx = fmaxf(mx, __shfl_xor_sync(0xffffffffu, mx, o));
    __shared__ float sm[8];
    int wid = t >> 5, lane = t & 31;
    if (lane == 0) sm[wid] = mx;
    __syncthreads();
    mx = sm[0];
    #pragma unroll
    for (int i = 1; i < 8; i++) mx = fmaxf(mx, sm[i]);

    float4 e;
    e.x = __expf(v.x - mx); e.y = __expf(v.y - mx);
    e.z = __expf(v.z - mx); e.w = __expf(v.w - mx);
    float s = e.x + e.y + e.z + e.w;
    #pragma unroll
    for (int o = 16; o > 0; o >>= 1)
        s += __shfl_xor_sync(0xffffffffu, s, o);
    __shared__ float ssum[8];
    if (lane == 0) ssum[wid] = s;
    __syncthreads();
    s = ssum[0] + ssum[1] + ssum[2] + ssum[3] + ssum[4] + ssum[5] + ssum[6] + ssum[7];
    float inv = 1.0f / s;
    e.x *= inv; e.y *= inv; e.z *= inv; e.w *= inv;
    ((float4*)p)[t] = e;
}

// ---------------- attn_weights = mean over H --------------------
__global__ void mean_heads(const float* __restrict__ attn, float* __restrict__ out)
{
    long i4 = (long)blockIdx.x * blockDim.x + threadIdx.x;   // over 2M float4
    long i = i4 * 4;
    long b_ = i >> 20;
    long rem = i & 1048575;
    const float* p = attn + (b_ << 23) + rem;
    float4 s = {0.f, 0.f, 0.f, 0.f};
    #pragma unroll
    for (int h = 0; h < 8; h++) {
        float4 v = *(const float4*)(p + ((long)h << 20));
        s.x += v.x; s.y += v.y; s.z += v.z; s.w += v.w;
    }
    s.x *= 0.125f; s.y *= 0.125f; s.z *= 0.125f; s.w *= 0.125f;
    *(float4*)(out + i) = s;
}

// ---------------- launch ----------------------------------------
extern "C" void kernel_launch(void* const* d_in, const int* in_sizes, int n_in,
                              void* d_out, int out_size)
{
    (void)in_sizes; (void)n_in; (void)out_size;
    const float* Zab   = (const float*)d_in[0];
    const float* Za    = (const float*)d_in[1];
    const float* ln_w  = (const float*)d_in[2];
    const float* ln_b  = (const float*)d_in[3];
    const float* in_w  = (const float*)d_in[4];
    const float* in_b  = (const float*)d_in[5];
    const float* out_w = (const float*)d_in[6];
    const float* out_b = (const float*)d_in[7];
    const float* ff_w  = (const float*)d_in[8];
    const float* ff_b  = (const float*)d_in[9];

    float* out_final = (float*)d_out;                      // 8192*512
    float* out_attnw = (float*)d_out + 8192L * 512;        // 8*1024*1024

    float *qin, *kvin, *q, *kv, *attn, *ctx, *x, *xn, *ff;
    cudaGetSymbolAddress((void**)&qin,  g_qin);
    cudaGetSymbolAddress((void**)&kvin, g_kvin);
    cudaGetSymbolAddress((void**)&q,    g_q);
    cudaGetSymbolAddress((void**)&kv,   g_kv);
    cudaGetSymbolAddress((void**)&attn, g_attn);
    cudaGetSymbolAddress((void**)&ctx,  g_ctx);
    cudaGetSymbolAddress((void**)&x,    g_x);
    cudaGetSymbolAddress((void**)&xn,   g_xn);
    cudaGetSymbolAddress((void**)&ff,   g_ff);

    // 1) LayerNorms of both inputs
    ln_kernel<<<8192, 128>>>(Zab, nullptr, ln_w, ln_b, qin);
    ln_kernel<<<8192, 128>>>(Za,  nullptr, ln_w, ln_b, kvin);

    // 2) q = qin @ Wq^T + bq     (M=8192, N=512, K=512)
    gemm_nt128<<<dim3(4, 64, 1), 256>>>(qin, 512, 0, 0,
                                        in_w, 512, 0, 0,
                                        q, 512, 0,
                                        512, 1.0f, in_b, nullptr, 1);
    // 3) kv = kvin @ [Wk;Wv]^T + [bk;bv]   (N=1024)
    gemm_nt128<<<dim3(8, 64, 1), 256>>>(kvin, 512, 0, 0,
                                        in_w + 512L * 512, 512, 0, 0,
                                        kv, 1024, 0,
                                        512, 1.0f, in_b + 512, nullptr, 1);

    // 4) scores = scale * q @ k^T, per (b,h)  -> attn [64][1024][1024]
    gemm_nt128<<<dim3(8, 8, 64), 256>>>(q, 512, 1024L * 512, 64,
                                        kv, 1024, 1024L * 1024, 64,
                                        attn, 1024, 1024L * 1024,
                                        64, 0.125f, nullptr, nullptr, 8);

    // 5) softmax rows (in place)
    softmax_kernel<<<dim3(1024, 64), 256>>>(attn);

    // 6) attn_weights = mean over heads
    mean_heads<<<8192, 256>>>(attn, out_attnw);

    // 7) ctx = attn @ v, per (b,h)
    gemm_nn_ctx128<<<dim3(8, 1, 64), 256>>>(attn, kv, ctx);

    // 8) x = ctx @ Wo^T + bo + Zab   (residual fused)
    gemm_nt128<<<dim3(4, 64, 1), 256>>>(ctx, 512, 0, 0,
                                        out_w, 512, 0, 0,
                                        x, 512, 0,
                                        512, 1.0f, out_b, Zab, 1);

    // 9) x_n = LN(x)
    ln_kernel<<<8192, 128>>>(x, nullptr, ln_w, ln_b, xn);

    // 10) ff = x_n @ ff_w^T + ff_b
    gemm_nt128<<<dim3(4, 64, 1), 256>>>(xn, 512, 0, 0,
                                        ff_w, 512, 0, 0,
                                        ff, 512, 0,
                                        512, 1.0f, ff_b, nullptr, 1);

    // 11) final = LN(x_n + ff)  -> d_out
    ln_kernel<<<8192, 128>>>(xn, ff, ln_w, ln_b, out_final);
}

// round 4
// speedup vs baseline: 2.3737x; 1.7768x over previous
#include <cuda_runtime.h>
#include <cuda_bf16.h>
#include <cstdint>

#define EPS 1e-5f
typedef __nv_bfloat16 bf16;

// ================= scratch (no allocation allowed) =================
__device__ bf16  g_qin_hi [8192L * 512];
__device__ bf16  g_qin_lo [8192L * 512];
__device__ bf16  g_kvin_hi[8192L * 512];
__device__ bf16  g_kvin_lo[8192L * 512];
__device__ bf16  g_inw_hi [1536L * 512];
__device__ bf16  g_inw_lo [1536L * 512];
__device__ bf16  g_outw_hi[512L * 512];
__device__ bf16  g_outw_lo[512L * 512];
__device__ bf16  g_ffw_hi [512L * 512];
__device__ bf16  g_ffw_lo [512L * 512];
__device__ bf16  g_q_hi   [8192L * 512];
__device__ bf16  g_q_lo   [8192L * 512];
__device__ float g_kv     [8192L * 1024];
__device__ bf16  g_k_hi   [8192L * 512];
__device__ bf16  g_k_lo   [8192L * 512];
__device__ bf16  g_vt_hi  [8L * 512 * 1024];
__device__ bf16  g_vt_lo  [8L * 512 * 1024];
__device__ float g_attn   [64LL * 1024 * 1024];   // scores fp32, 256 MB
__device__ bf16  g_p_hi   [64LL * 1024 * 1024];
__device__ bf16  g_p_lo   [64LL * 1024 * 1024];
__device__ float g_ctx    [8192L * 512];
__device__ bf16  g_ctx_hi [8192L * 512];
__device__ bf16  g_ctx_lo [8192L * 512];
__device__ float g_x      [8192L * 512];
__device__ float g_xn     [8192L * 512];
__device__ bf16  g_xn_hi  [8192L * 512];
__device__ bf16  g_xn_lo  [8192L * 512];
__device__ float g_ff     [8192L * 512];

// ================= helpers =================
__device__ __forceinline__ uint32_t smem_u32(const void* p){
    uint32_t a;
    asm("{ .reg .u64 t; cvta.to.shared.u64 t, %1; cvt.u32.u64 %0, t; }" : "=r"(a) : "l"(p));
    return a;
}
#define CP_ASYNC16(dst, src) \
    asm volatile("cp.async.cg.shared.global [%0], [%1], 16;" :: "r"(dst), "l"(src))
#define CP_COMMIT() asm volatile("cp.async.commit_group;" ::: "memory")
#define CP_WAIT(n)  asm volatile("cp.async.wait_group %0;" :: "n"(n) : "memory")

__device__ __forceinline__ void ldsm4(uint32_t addr, uint32_t& r0, uint32_t& r1,
                                      uint32_t& r2, uint32_t& r3){
    asm volatile("ldmatrix.sync.aligned.m8n8.x4.shared.b16 {%0,%1,%2,%3}, [%4];"
                 : "=r"(r0), "=r"(r1), "=r"(r2), "=r"(r3) : "r"(addr));
}
__device__ __forceinline__ void mma16816(float* d, const uint32_t* a, const uint32_t* b){
    asm volatile("mma.sync.aligned.m16n8k16.row.col.f32.bf16.bf16.f32 "
                 "{%0,%1,%2,%3},{%4,%5,%6,%7},{%8,%9},{%0,%1,%2,%3};"
                 : "+f"(d[0]), "+f"(d[1]), "+f"(d[2]), "+f"(d[3])
                 : "r"(a[0]), "r"(a[1]), "r"(a[2]), "r"(a[3]), "r"(b[0]), "r"(b[1]));
}
__device__ __forceinline__ void split1(float v, bf16& h, bf16& l){
    h = __float2bfloat16_rn(v);
    l = __float2bfloat16_rn(v - __bfloat162float(h));
}

// ================= HMMA split-bf16 GEMM =================
// C = scale * A @ B^T (+bias)(+resid). A[m][k] K-major (hi,lo planes),
// B[n][k] K-major (hi,lo planes). 3 phases: (Ah,Bh),(Al,Bh),(Ah,Bl).
// CTA tile 128 x NT, BK=32, 256 threads = 8 warps.
// NT=128: warps 4(M)x2(N), warp 32x64.  NT=64: warp 32x32.
// Batched: z -> b=z/Hn, h=z%Hn.
template<int NT>
__global__ void __launch_bounds__(256)
gemm_mma(const bf16* __restrict__ Ahi, const bf16* __restrict__ Alo,
         long lda, long sAb, long sAh,
         const bf16* __restrict__ Bhi, const bf16* __restrict__ Blo,
         long ldb, long sBb, long sBh,
         float* __restrict__ C, bf16* __restrict__ Chi, bf16* __restrict__ Clo,
         long ldc, long sCb, long sCh,
         int K, int Hn, float scale,
         const float* __restrict__ bias, const float* __restrict__ resid)
{
    constexpr int WN  = (NT == 128) ? 64 : 32;   // warp N tile
    constexpr int NI  = WN / 8;                  // n8 tiles per warp
    constexpr int NI2 = NI / 2;                  // ldmatrix.x4 groups for B
    constexpr int ROWB = 80;                     // bytes per smem row (32 bf16 + 8 pad)
    constexpr int ASZ = 128 * ROWB;
    constexpr int BSZ = NT * ROWB;
    constexpr int STAGE = ASZ + BSZ;
    constexpr int NBLD = (NT * 4) / 256;         // B 16B-chunks per thread

    extern __shared__ char smem[];
    const int tid = threadIdx.x;
    const int wid = tid >> 5, lane = tid & 31;
    const int wm = (wid & 3) * 32;
    const int wn = (wid >> 2) * WN;

    int z  = blockIdx.z;
    int b_ = z / Hn, h_ = z % Hn;
    long bm = (long)blockIdx.y * 128;
    long bn = (long)blockIdx.x * NT;
    const bf16* Ah = Ahi + (long)b_*sAb + (long)h_*sAh + bm*lda;
    const bf16* Al = Alo + (long)b_*sAb + (long)h_*sAh + bm*lda;
    const bf16* Bh = Bhi + (long)b_*sBb + (long)h_*sBh + bn*ldb;
    const bf16* Bl = Blo + (long)b_*sBb + (long)h_*sBh + bn*ldb;
    long cbase = (long)b_*sCb + (long)h_*sCh;

    const uint32_t sb = smem_u32(smem);

    const int Kc = K >> 5;      // 32-wide chunks per phase
    const int Ct = 3 * Kc;

    auto loadc = [&](int c, int s){
        int ph = c / Kc;
        long k0 = (long)(c - ph * Kc) * 32;
        const bf16* pa = (ph == 1) ? Al : Ah;
        const bf16* pb = (ph == 2) ? Bl : Bh;
        uint32_t abuf = sb + s * STAGE;
        uint32_t bbuf = abuf + ASZ;
        #pragma unroll
        for (int i = 0; i < 2; i++) {
            int id = tid + i * 256;
            int r = id >> 2, c16 = id & 3;
            CP_ASYNC16(abuf + r * ROWB + c16 * 16, pa + (long)r * lda + k0 + c16 * 8);
        }
        #pragma unroll
        for (int i = 0; i < NBLD; i++) {
            int id = tid + i * 256;
            int r = id >> 2, c16 = id & 3;
            CP_ASYNC16(bbuf + r * ROWB + c16 * 16, pb + (long)r * ldb + k0 + c16 * 8);
        }
        CP_COMMIT();
    };

    float acc[2 * NI * 4];
    #pragma unroll
    for (int i = 0; i < 2 * NI * 4; i++) acc[i] = 0.f;

    // per-thread ldmatrix row/col selectors
    const int arow = (lane & 7) + ((lane & 8)  ? 8 : 0);
    const int acol = (lane & 16) ? 8 : 0;
    const int brow = (lane & 7) + ((lane & 16) ? 8 : 0);
    const int bcol = (lane & 8) ? 8 : 0;

    loadc(0, 0);

    for (int c = 0; c < Ct; c++) {
        if (c + 1 < Ct) { loadc(c + 1, (c + 1) & 1); CP_WAIT(1); }
        else            { CP_WAIT(0); }
        __syncthreads();

        uint32_t abuf = sb + (c & 1) * STAGE;
        uint32_t bbuf = abuf + ASZ;
        #pragma unroll
        for (int k16 = 0; k16 < 2; k16++) {
            uint32_t af[2][4];
            #pragma unroll
            for (int mi = 0; mi < 2; mi++)
                ldsm4(abuf + (wm + mi * 16 + arow) * ROWB + (k16 * 16 + acol) * 2,
                      af[mi][0], af[mi][1], af[mi][2], af[mi][3]);
            uint32_t bfA[NI2][4];
            #pragma unroll
            for (int n2 = 0; n2 < NI2; n2++)
                ldsm4(bbuf + (wn + n2 * 16 + brow) * ROWB + (k16 * 16 + bcol) * 2,
                      bfA[n2][0], bfA[n2][1], bfA[n2][2], bfA[n2][3]);
            #pragma unroll
            for (int mi = 0; mi < 2; mi++)
                #pragma unroll
                for (int ni = 0; ni < NI; ni++)
                    mma16816(acc + (mi * NI + ni) * 4, af[mi], bfA[ni >> 1] + (ni & 1) * 2);
        }
        __syncthreads();
    }

    // ---------------- epilogue ----------------
    #pragma unroll
    for (int mi = 0; mi < 2; mi++) {
        #pragma unroll
        for (int ni = 0; ni < NI; ni++) {
            const float* a4 = acc + (mi * NI + ni) * 4;
            int n0 = (int)bn + wn + ni * 8 + (lane & 3) * 2;
            #pragma unroll
            for (int half = 0; half < 2; half++) {
                long m = bm + wm + mi * 16 + (lane >> 2) + half * 8;
                float v0 = a4[half * 2 + 0] * scale;
                float v1 = a4[half * 2 + 1] * scale;
                if (bias) { v0 += bias[n0]; v1 += bias[n0 + 1]; }
                if (resid) {
                    float2 rr = *(const float2*)(resid + cbase + m * ldc + n0);
                    v0 += rr.x; v1 += rr.y;
                }
                if (C) {
                    float2 o; o.x = v0; o.y = v1;
                    *(float2*)(C + cbase + m * ldc + n0) = o;
                }
                if (Chi) {
                    bf16 h0, l0, h1, l1;
                    split1(v0, h0, l0); split1(v1, h1, l1);
                    unsigned short hs[2] = {__bfloat16_as_ushort(h0), __bfloat16_as_ushort(h1)};
                    unsigned short ls[2] = {__bfloat16_as_ushort(l0), __bfloat16_as_ushort(l1)};
                    *(uint32_t*)(Chi + cbase + m * ldc + n0) = *(uint32_t*)hs;
                    *(uint32_t*)(Clo + cbase + m * ldc + n0) = *(uint32_t*)ls;
                }
            }
        }
    }
}

// ================= LayerNorm (row=512), optional fp32/hi/lo out =================
__global__ void ln_kernel2(const float* __restrict__ x, const float* __restrict__ x2,
                           const float* __restrict__ w, const float* __restrict__ bb,
                           float* __restrict__ outf, bf16* __restrict__ ohi, bf16* __restrict__ olo)
{
    int row = blockIdx.x;
    int t = threadIdx.x;                     // 128 threads * float4 = 512
    float4 v = ((const float4*)(x + (long)row * 512))[t];
    if (x2) {
        float4 v2 = ((const float4*)(x2 + (long)row * 512))[t];
        v.x += v2.x; v.y += v2.y; v.z += v2.z; v.w += v2.w;
    }
    float s  = v.x + v.y + v.z + v.w;
    float sq = v.x*v.x + v.y*v.y + v.z*v.z + v.w*v.w;
    #pragma unroll
    for (int o = 16; o > 0; o >>= 1) {
        s  += __shfl_xor_sync(0xffffffffu, s,  o);
        sq += __shfl_xor_sync(0xffffffffu, sq, o);
    }
    __shared__ float ss[4], ssq[4];
    int wid = t >> 5, lane = t & 31;
    if (lane == 0) { ss[wid] = s; ssq[wid] = sq; }
    __syncthreads();
    s  = ss[0]  + ss[1]  + ss[2]  + ss[3];
    sq = ssq[0] + ssq[1] + ssq[2] + ssq[3];
    float mu  = s * (1.0f / 512.0f);
    float var = sq * (1.0f / 512.0f) - mu * mu;
    float inv = rsqrtf(var + EPS);
    float4 wv = ((const float4*)w)[t];
    float4 bv = ((const float4*)bb)[t];
    float o4[4];
    o4[0] = (v.x - mu) * inv * wv.x + bv.x;
    o4[1] = (v.y - mu) * inv * wv.y + bv.y;
    o4[2] = (v.z - mu) * inv * wv.z + bv.z;
    o4[3] = (v.w - mu) * inv * wv.w + bv.w;
    long base = (long)row * 512 + t * 4;
    if (outf) *(float4*)(outf + base) = *(float4*)o4;
    if (ohi) {
        unsigned short hs[4], ls[4];
        #pragma unroll
        for (int j = 0; j < 4; j++) {
            bf16 h, l; split1(o4[j], h, l);
            hs[j] = __bfloat16_as_ushort(h);
            ls[j] = __bfloat16_as_ushort(l);
        }
        *(uint2*)(ohi + base) = *(uint2*)hs;
        *(uint2*)(olo + base) = *(uint2*)ls;
    }
}

// ================= split fp32 -> bf16 hi/lo =================
__global__ void split_kernel(const float* __restrict__ x, bf16* __restrict__ hi,
                             bf16* __restrict__ lo)
{
    long i = ((long)blockIdx.x * 256 + threadIdx.x) * 4;
    float4 v = *(const float4*)(x + i);
    float a[4] = {v.x, v.y, v.z, v.w};
    unsigned short hs[4], ls[4];
    #pragma unroll
    for (int j = 0; j < 4; j++) {
        bf16 h, l; split1(a[j], h, l);
        hs[j] = __bfloat16_as_ushort(h);
        ls[j] = __bfloat16_as_ushort(l);
    }
    *(uint2*)(hi + i) = *(uint2*)hs;
    *(uint2*)(lo + i) = *(uint2*)ls;
}

// split K half of kv [8192][1024] (cols 0..511) -> k_hi/k_lo [8192][512]
__global__ void split_k_kernel(const float* __restrict__ kv, bf16* __restrict__ hi,
                               bf16* __restrict__ lo)
{
    long i = ((long)blockIdx.x * 256 + threadIdx.x) * 4;   // over 8192*512
    long r = i >> 9, c = i & 511;
    float4 v = *(const float4*)(kv + r * 1024 + c);
    float a[4] = {v.x, v.y, v.z, v.w};
    unsigned short hs[4], ls[4];
    #pragma unroll
    for (int j = 0; j < 4; j++) {
        bf16 h, l; split1(a[j], h, l);
        hs[j] = __bfloat16_as_ushort(h);
        ls[j] = __bfloat16_as_ushort(l);
    }
    *(uint2*)(hi + i) = *(uint2*)hs;
    *(uint2*)(lo + i) = *(uint2*)ls;
}

// transpose V half of kv: vt[b][n][s] = kv[b][s][512+n], split to hi/lo
__global__ void transpose_v_kernel(const float* __restrict__ kv,
                                   bf16* __restrict__ vhi, bf16* __restrict__ vlo)
{
    __shared__ float t[32][33];
    int b = blockIdx.z;
    int s0 = blockIdx.x * 32, n0 = blockIdx.y * 32;
    int tx = threadIdx.x, ty = threadIdx.y;   // (32, 8)
    #pragma unroll
    for (int i = 0; i < 4; i++) {
        int s = s0 + ty + i * 8;
        t[ty + i * 8][tx] = kv[((long)b * 1024 + s) * 1024 + 512 + n0 + tx];
    }
    __syncthreads();
    #pragma unroll
    for (int i = 0; i < 4; i++) {
        int n = n0 + ty + i * 8;
        float v = t[tx][ty + i * 8];
        bf16 h, l; split1(v, h, l);
        long o = (long)b * 512 * 1024 + (long)n * 1024 + s0 + tx;
        vhi[o] = h; vlo[o] = l;
    }
}

// ================= softmax: fp32 scores -> bf16 hi/lo probabilities ========
__global__ void softmax_kernel(const float* __restrict__ attn,
                               bf16* __restrict__ phi, bf16* __restrict__ plo)
{
    long row = (long)blockIdx.y * 1024 + blockIdx.x;   // z*1024 + q
    const float* p = attn + row * 1024;
    int t = threadIdx.x;                                // 256 threads * 4
    float4 v = ((const float4*)p)[t];

    float mx = fmaxf(fmaxf(v.x, v.y), fmaxf(v.z, v.w));
    #pragma unroll
    for (int o = 16; o > 0; o >>= 1)
        mx = fmaxf(mx, __shfl_xor_sync(0xffffffffu, mx, o));
    __shared__ float sm[8];
    int wid = t >> 5, lane = t & 31;
    if (lane == 0) sm[wid] = mx;
    __syncthreads();
    mx = sm[0];
    #pragma unroll
    for (int i = 1; i < 8; i++) mx = fmaxf(mx, sm[i]);

    float e[4];
    e[0] = __expf(v.x - mx); e[1] = __expf(v.y - mx);
    e[2] = __expf(v.z - mx); e[3] = __expf(v.w - mx);
    float s = e[0] + e[1] + e[2] + e[3];
    #pragma unroll
    for (int o = 16; o > 0; o >>= 1)
        s += __shfl_xor_sync(0xffffffffu, s, o);
    __shared__ float ssum[8];
    if (lane == 0) ssum[wid] = s;
    __syncthreads();
    s = ssum[0] + ssum[1] + ssum[2] + ssum[3] + ssum[4] + ssum[5] + ssum[6] + ssum[7];
    float inv = 1.0f / s;
    unsigned short hs[4], ls[4];
    #pragma unroll
    for (int j = 0; j < 4; j++) {
        float pv = e[j] * inv;
        bf16 h, l; split1(pv, h, l);
        hs[j] = __bfloat16_as_ushort(h);
        ls[j] = __bfloat16_as_ushort(l);
    }
    long base = row * 1024 + t * 4;
    *(uint2*)(phi + base) = *(uint2*)hs;
    *(uint2*)(plo + base) = *(uint2*)ls;
}

// ================= attn_weights = mean over H (from hi+lo) =================
__global__ void mean_heads2(const bf16* __restrict__ phi, const bf16* __restrict__ plo,
                            float* __restrict__ out)
{
    long i = ((long)blockIdx.x * 256 + threadIdx.x) * 4;   // over 8M
    long b = i >> 20;
    long rem = i & 1048575;
    long base = (b << 23) + rem;
    float s[4] = {0.f, 0.f, 0.f, 0.f};
    #pragma unroll
    for (int h = 0; h < 8; h++) {
        long o = base + ((long)h << 20);
        const __nv_bfloat162* h2 = (const __nv_bfloat162*)(phi + o);
        const __nv_bfloat162* l2 = (const __nv_bfloat162*)(plo + o);
        float2 h0 = __bfloat1622float2(h2[0]);
        float2 h1 = __bfloat1622float2(h2[1]);
        float2 l0 = __bfloat1622float2(l2[0]);
        float2 l1 = __bfloat1622float2(l2[1]);
        s[0] += h0.x + l0.x; s[1] += h0.y + l0.y;
        s[2] += h1.x + l1.x; s[3] += h1.y + l1.y;
    }
    float4 o4; o4.x = s[0]*0.125f; o4.y = s[1]*0.125f; o4.z = s[2]*0.125f; o4.w = s[3]*0.125f;
    *(float4*)(out + i) = o4;
}

// ================= launch =================
extern "C" void kernel_launch(void* const* d_in, const int* in_sizes, int n_in,
                              void* d_out, int out_size)
{
    (void)in_sizes; (void)n_in; (void)out_size;
    const float* Zab   = (const float*)d_in[0];
    const float* Za    = (const float*)d_in[1];
    const float* ln_w  = (const float*)d_in[2];
    const float* ln_b  = (const float*)d_in[3];
    const float* in_w  = (const float*)d_in[4];
    const float* in_b  = (const float*)d_in[5];
    const float* out_w = (const float*)d_in[6];
    const float* out_b = (const float*)d_in[7];
    const float* ff_w  = (const float*)d_in[8];
    const float* ff_b  = (const float*)d_in[9];

    float* out_final = (float*)d_out;                    // 8192*512
    float* out_attnw = (float*)d_out + 8192L * 512;      // 8*1024*1024

    bf16 *qin_hi, *qin_lo, *kvin_hi, *kvin_lo, *inw_hi, *inw_lo;
    bf16 *outw_hi, *outw_lo, *ffw_hi, *ffw_lo, *q_hi, *q_lo;
    bf16 *k_hi, *k_lo, *vt_hi, *vt_lo, *p_hi, *p_lo, *ctx_hi, *ctx_lo, *xn_hi, *xn_lo;
    float *kv, *attn, *ctx, *x, *xn, *ff;
    cudaGetSymbolAddress((void**)&qin_hi,  g_qin_hi);
    cudaGetSymbolAddress((void**)&qin_lo,  g_qin_lo);
    cudaGetSymbolAddress((void**)&kvin_hi, g_kvin_hi);
    cudaGetSymbolAddress((void**)&kvin_lo, g_kvin_lo);
    cudaGetSymbolAddress((void**)&inw_hi,  g_inw_hi);
    cudaGetSymbolAddress((void**)&inw_lo,  g_inw_lo);
    cudaGetSymbolAddress((void**)&outw_hi, g_outw_hi);
    cudaGetSymbolAddress((void**)&outw_lo, g_outw_lo);
    cudaGetSymbolAddress((void**)&ffw_hi,  g_ffw_hi);
    cudaGetSymbolAddress((void**)&ffw_lo,  g_ffw_lo);
    cudaGetSymbolAddress((void**)&q_hi,    g_q_hi);
    cudaGetSymbolAddress((void**)&q_lo,    g_q_lo);
    cudaGetSymbolAddress((void**)&k_hi,    g_k_hi);
    cudaGetSymbolAddress((void**)&k_lo,    g_k_lo);
    cudaGetSymbolAddress((void**)&vt_hi,   g_vt_hi);
    cudaGetSymbolAddress((void**)&vt_lo,   g_vt_lo);
    cudaGetSymbolAddress((void**)&p_hi,    g_p_hi);
    cudaGetSymbolAddress((void**)&p_lo,    g_p_lo);
    cudaGetSymbolAddress((void**)&ctx_hi,  g_ctx_hi);
    cudaGetSymbolAddress((void**)&ctx_lo,  g_ctx_lo);
    cudaGetSymbolAddress((void**)&xn_hi,   g_xn_hi);
    cudaGetSymbolAddress((void**)&xn_lo,   g_xn_lo);
    cudaGetSymbolAddress((void**)&kv,   g_kv);
    cudaGetSymbolAddress((void**)&attn, g_attn);
    cudaGetSymbolAddress((void**)&ctx,  g_ctx);
    cudaGetSymbolAddress((void**)&x,    g_x);
    cudaGetSymbolAddress((void**)&xn,   g_xn);
    cudaGetSymbolAddress((void**)&ff,   g_ff);

    const int SMEM128 = 2 * (128 + 128) * 80;   // 40960
    const int SMEM64  = 2 * (128 + 64) * 80;    // 30720
    cudaFuncSetAttribute((const void*)gemm_mma<128>,
                         cudaFuncAttributeMaxDynamicSharedMemorySize, SMEM128);
    cudaFuncSetAttribute((const void*)gemm_mma<64>,
                         cudaFuncAttributeMaxDynamicSharedMemorySize, SMEM64);

    // 1) LN of inputs -> bf16 hi/lo
    ln_kernel2<<<8192, 128>>>(Zab, nullptr, ln_w, ln_b, nullptr, qin_hi, qin_lo);
    ln_kernel2<<<8192, 128>>>(Za,  nullptr, ln_w, ln_b, nullptr, kvin_hi, kvin_lo);

    // 2) split weights
    split_kernel<<<768, 256>>>(in_w,  inw_hi,  inw_lo);    // 1536*512
    split_kernel<<<256, 256>>>(out_w, outw_hi, outw_lo);   // 512*512
    split_kernel<<<256, 256>>>(ff_w,  ffw_hi,  ffw_lo);

    // 3) q = qin @ Wq^T + bq  -> bf16 hi/lo   (M=8192,N=512,K=512)
    gemm_mma<128><<<dim3(4, 64, 1), 256, SMEM128>>>(
        qin_hi, qin_lo, 512, 0, 0,
        inw_hi, inw_lo, 512, 0, 0,
        nullptr, q_hi, q_lo, 512, 0, 0,
        512, 1, 1.0f, in_b, nullptr);

    // 4) kv = kvin @ [Wk;Wv]^T + [bk;bv]  -> fp32  (N=1024)
    gemm_mma<128><<<dim3(8, 64, 1), 256, SMEM128>>>(
        kvin_hi, kvin_lo, 512, 0, 0,
        inw_hi + 512L * 512, inw_lo + 512L * 512, 512, 0, 0,
        kv, nullptr, nullptr, 1024, 0, 0,
        512, 1, 1.0f, in_b + 512, nullptr);

    // 5) k half -> bf16 hi/lo ; V half -> transposed bf16 hi/lo
    split_k_kernel<<<4096, 256>>>(kv, k_hi, k_lo);
    transpose_v_kernel<<<dim3(32, 16, 8), dim3(32, 8)>>>(kv, vt_hi, vt_lo);

    // 6) scores = 0.125 * q @ k^T  per (b,h) -> fp32 attn
    gemm_mma<128><<<dim3(8, 8, 64), 256, SMEM128>>>(
        q_hi, q_lo, 512, 1024L * 512, 64,
        k_hi, k_lo, 512, 1024L * 512, 64,
        attn, nullptr, nullptr, 1024, 8L * 1024 * 1024, 1024L * 1024,
        64, 8, 0.125f, nullptr, nullptr);

    // 7) softmax -> P as bf16 hi/lo
    softmax_kernel<<<dim3(1024, 64), 256>>>(attn, p_hi, p_lo);

    // 8) attn_weights = mean over heads
    mean_heads2<<<8192, 256>>>(p_hi, p_lo, out_attnw);

    // 9) ctx = P @ V  per (b,h)
    gemm_mma<64><<<dim3(1, 8, 64), 256, SMEM64>>>(
        p_hi, p_lo, 1024, 8L * 1024 * 1024, 1024L * 1024,
        vt_hi, vt_lo, 1024, 512L * 1024, 64L * 1024,
        ctx, nullptr, nullptr, 512, 1024L * 512, 64,
        1024, 8, 1.0f, nullptr, nullptr);

    // 10) split ctx for next GEMM
    split_kernel<<<4096, 256>>>(ctx, ctx_hi, ctx_lo);

    // 11) x = ctx @ Wo^T + bo + Zab
    gemm_mma<128><<<dim3(4, 64, 1), 256, SMEM128>>>(
        ctx_hi, ctx_lo, 512, 0, 0,
        outw_hi, outw_lo, 512, 0, 0,
        x, nullptr, nullptr, 512, 0, 0,
        512, 1, 1.0f, out_b, Zab);

    // 12) x_n = LN(x)  -> fp32 + hi/lo
    ln_kernel2<<<8192, 128>>>(x, nullptr, ln_w, ln_b, xn, xn_hi, xn_lo);

    // 13) ff = x_n @ ff_w^T + ff_b
    gemm_mma<128><<<dim3(4, 64, 1), 256, SMEM128>>>(
        xn_hi, xn_lo, 512, 0, 0,
        ffw_hi, ffw_lo, 512, 0, 0,
        ff, nullptr, nullptr, 512, 0, 0,
        512, 1, 1.0f, ff_b, nullptr);

    // 14) final = LN(x_n + ff) -> d_out
    ln_kernel2<<<8192, 128>>>(xn, ff, ln_w, ln_b, out_final, nullptr, nullptr);
}

// round 5
// speedup vs baseline: 2.5100x; 1.0574x over previous
#include <cuda_runtime.h>
#include <cuda_bf16.h>
#include <cstdint>

#define EPS 1e-5f
typedef __nv_bfloat16 bf16;

// ================= scratch (no allocation allowed) =================
__device__ bf16  g_qin_hi [8192L * 512];
__device__ bf16  g_qin_lo [8192L * 512];
__device__ bf16  g_kvin_hi[8192L * 512];
__device__ bf16  g_kvin_lo[8192L * 512];
__device__ bf16  g_inw_hi [1536L * 512];
__device__ bf16  g_inw_lo [1536L * 512];
__device__ bf16  g_outw_hi[512L * 512];
__device__ bf16  g_outw_lo[512L * 512];
__device__ bf16  g_ffw_hi [512L * 512];
__device__ bf16  g_ffw_lo [512L * 512];
__device__ bf16  g_q_hi   [8192L * 512];
__device__ bf16  g_q_lo   [8192L * 512];
__device__ float g_kv     [8192L * 1024];
__device__ bf16  g_k_hi   [8192L * 512];
__device__ bf16  g_k_lo   [8192L * 512];
__device__ bf16  g_vt_hi  [8L * 512 * 1024];
__device__ bf16  g_vt_lo  [8L * 512 * 1024];
__device__ float g_p      [64LL * 1024 * 1024];   // probabilities fp32, 256 MB
__device__ bf16  g_ctx_hi [8192L * 512];
__device__ bf16  g_ctx_lo [8192L * 512];
__device__ float g_x      [8192L * 512];
__device__ float g_xn     [8192L * 512];
__device__ bf16  g_xn_hi  [8192L * 512];
__device__ bf16  g_xn_lo  [8192L * 512];
__device__ float g_ff     [8192L * 512];

// ================= helpers =================
__device__ __forceinline__ uint32_t smem_u32(const void* p){
    uint32_t a;
    asm("{ .reg .u64 t; cvta.to.shared.u64 t, %1; cvt.u32.u64 %0, t; }" : "=r"(a) : "l"(p));
    return a;
}
#define CP_ASYNC16(dst, src) \
    asm volatile("cp.async.cg.shared.global [%0], [%1], 16;" :: "r"(dst), "l"(src))
#define CP_COMMIT() asm volatile("cp.async.commit_group;" ::: "memory")
#define CP_WAIT(n)  asm volatile("cp.async.wait_group %0;" :: "n"(n) : "memory")

__device__ __forceinline__ void ldsm4(uint32_t addr, uint32_t& r0, uint32_t& r1,
                                      uint32_t& r2, uint32_t& r3){
    asm volatile("ldmatrix.sync.aligned.m8n8.x4.shared.b16 {%0,%1,%2,%3}, [%4];"
                 : "=r"(r0), "=r"(r1), "=r"(r2), "=r"(r3) : "r"(addr));
}
__device__ __forceinline__ void mma16816(float* d, const uint32_t* a, const uint32_t* b){
    asm volatile("mma.sync.aligned.m16n8k16.row.col.f32.bf16.bf16.f32 "
                 "{%0,%1,%2,%3},{%4,%5,%6,%7},{%8,%9},{%0,%1,%2,%3};"
                 : "+f"(d[0]), "+f"(d[1]), "+f"(d[2]), "+f"(d[3])
                 : "r"(a[0]), "r"(a[1]), "r"(a[2]), "r"(a[3]), "r"(b[0]), "r"(b[1]));
}
__device__ __forceinline__ void split1(float v, bf16& h, bf16& l){
    h = __float2bfloat16_rn(v);
    l = __float2bfloat16_rn(v - __bfloat162float(h));
}

// ================= phase-inner HMMA split-bf16 GEMM =================
// C = scale * (A @ B^T + bias) (+resid). A[m][k], B[n][k] K-major, hi/lo planes.
// Per 32-wide k-chunk: load Ah,Al,Bh,Bl once; 3 MMA phases (Ah,Bh),(Al,Bh),(Ah,Bl).
template<int NT>
__global__ void __launch_bounds__(256)
gemm_pi(const bf16* __restrict__ Ahi, const bf16* __restrict__ Alo,
        long lda, long sAb, long sAh,
        const bf16* __restrict__ Bhi, const bf16* __restrict__ Blo,
        long ldb, long sBb, long sBh,
        float* __restrict__ C, bf16* __restrict__ Chi, bf16* __restrict__ Clo,
        long ldc, long sCb, long sCh,
        int K, int Hn, float scale,
        const float* __restrict__ bias, const float* __restrict__ resid)
{
    constexpr int WN  = (NT == 128) ? 64 : 32;
    constexpr int NI  = WN / 8;
    constexpr int NI2 = NI / 2;
    constexpr int ROWB = 80;
    constexpr int ASZ = 128 * ROWB;
    constexpr int BSZ = NT * ROWB;
    constexpr int STAGE = 2 * ASZ + 2 * BSZ;
    constexpr int NB = (NT * 4) / 256;

    extern __shared__ char smem[];
    const int tid = threadIdx.x, wid = tid >> 5, lane = tid & 31;
    const int wm = (wid & 3) * 32, wn = (wid >> 2) * WN;

    int z = blockIdx.z;
    int b_ = z / Hn, h_ = z % Hn;
    long bm = (long)blockIdx.y * 128;
    long bn = (long)blockIdx.x * NT;
    const bf16* Ah = Ahi + (long)b_*sAb + (long)h_*sAh + bm*lda;
    const bf16* Al = Alo + (long)b_*sAb + (long)h_*sAh + bm*lda;
    const bf16* Bh = Bhi + (long)b_*sBb + (long)h_*sBh + bn*ldb;
    const bf16* Bl = Blo + (long)b_*sBb + (long)h_*sBh + bn*ldb;
    long cbase = (long)b_*sCb + (long)h_*sCh;

    const uint32_t sb = smem_u32(smem);

    auto loadc = [&](int kc, int s){
        long k0 = (long)kc * 32;
        uint32_t base = sb + s * STAGE;
        #pragma unroll
        for (int i = 0; i < 2; i++) {
            int id = tid + i * 256; int r = id >> 2, c = id & 3;
            CP_ASYNC16(base + r * ROWB + c * 16,       Ah + (long)r * lda + k0 + c * 8);
            CP_ASYNC16(base + ASZ + r * ROWB + c * 16, Al + (long)r * lda + k0 + c * 8);
        }
        #pragma unroll
        for (int i = 0; i < NB; i++) {
            int id = tid + i * 256; int r = id >> 2, c = id & 3;
            CP_ASYNC16(base + 2*ASZ + r * ROWB + c * 16,       Bh + (long)r * ldb + k0 + c * 8);
            CP_ASYNC16(base + 2*ASZ + BSZ + r * ROWB + c * 16, Bl + (long)r * ldb + k0 + c * 8);
        }
        CP_COMMIT();
    };

    float acc[2 * NI * 4];
    #pragma unroll
    for (int i = 0; i < 2 * NI * 4; i++) acc[i] = 0.f;

    const int arow = (lane & 7) + ((lane & 8)  ? 8 : 0);
    const int acol = (lane & 16) ? 8 : 0;
    const int brow = (lane & 7) + ((lane & 16) ? 8 : 0);
    const int bcol = (lane & 8) ? 8 : 0;

    const int KC = K >> 5;
    loadc(0, 0);

    for (int kc = 0; kc < KC; kc++) {
        int s = kc & 1;
        if (kc + 1 < KC) { loadc(kc + 1, s ^ 1); CP_WAIT(1); }
        else             { CP_WAIT(0); }
        __syncthreads();

        uint32_t base = sb + s * STAGE;
        #pragma unroll
        for (int ph = 0; ph < 3; ph++) {
            uint32_t abuf = base + ((ph == 1) ? ASZ : 0);
            uint32_t bbuf = base + 2*ASZ + ((ph == 2) ? BSZ : 0);
            #pragma unroll
            for (int k16 = 0; k16 < 2; k16++) {
                uint32_t af[2][4];
                #pragma unroll
                for (int mi = 0; mi < 2; mi++)
                    ldsm4(abuf + (wm + mi * 16 + arow) * ROWB + (k16 * 16 + acol) * 2,
                          af[mi][0], af[mi][1], af[mi][2], af[mi][3]);
                uint32_t bfr[NI2][4];
                #pragma unroll
                for (int n2 = 0; n2 < NI2; n2++)
                    ldsm4(bbuf + (wn + n2 * 16 + brow) * ROWB + (k16 * 16 + bcol) * 2,
                          bfr[n2][0], bfr[n2][1], bfr[n2][2], bfr[n2][3]);
                #pragma unroll
                for (int mi = 0; mi < 2; mi++)
                    #pragma unroll
                    for (int ni = 0; ni < NI; ni++)
                        mma16816(acc + (mi * NI + ni) * 4, af[mi], bfr[ni >> 1] + (ni & 1) * 2);
            }
        }
        __syncthreads();
    }

    // epilogue: v = (acc + bias) * scale (+resid)
    #pragma unroll
    for (int mi = 0; mi < 2; mi++) {
        #pragma unroll
        for (int ni = 0; ni < NI; ni++) {
            const float* a4 = acc + (mi * NI + ni) * 4;
            int n0 = (int)bn + wn + ni * 8 + (lane & 3) * 2;
            #pragma unroll
            for (int half = 0; half < 2; half++) {
                long m = bm + wm + mi * 16 + (lane >> 2) + half * 8;
                float v0 = a4[half * 2 + 0];
                float v1 = a4[half * 2 + 1];
                if (bias) { v0 += bias[n0]; v1 += bias[n0 + 1]; }
                v0 *= scale; v1 *= scale;
                if (resid) {
                    float2 rr = *(const float2*)(resid + cbase + m * ldc + n0);
                    v0 += rr.x; v1 += rr.y;
                }
                if (C) {
                    float2 o; o.x = v0; o.y = v1;
                    *(float2*)(C + cbase + m * ldc + n0) = o;
                }
                if (Chi) {
                    bf16 h0, l0, h1, l1;
                    split1(v0, h0, l0); split1(v1, h1, l1);
                    unsigned short hs[2] = {__bfloat16_as_ushort(h0), __bfloat16_as_ushort(h1)};
                    unsigned short ls[2] = {__bfloat16_as_ushort(l0), __bfloat16_as_ushort(l1)};
                    *(uint32_t*)(Chi + cbase + m * ldc + n0) = *(uint32_t*)hs;
                    *(uint32_t*)(Clo + cbase + m * ldc + n0) = *(uint32_t*)ls;
                }
            }
        }
    }
}

// ================= fused scores + softmax -> P fp32 =================
// CTA: 128 q rows x one (b,h). Q resident (hi/lo), K streamed twice.
// Pass 1 (k-tiles 0..7): per-thread online (max,sumexp); reduce at end.
// Pass 2 (k-tiles 0..7): recompute S, write P = exp(s-m)/l.
__global__ void __launch_bounds__(256)
attn_fused(const bf16* __restrict__ qhi, const bf16* __restrict__ qlo,
           const bf16* __restrict__ khi, const bf16* __restrict__ klo,
           float* __restrict__ P)
{
    constexpr int PITCH = 144;           // 64 bf16 = 128 B + 16 pad
    constexpr int PLANE = 128 * PITCH;   // 18432
    extern __shared__ char smem[];
    const uint32_t sb  = smem_u32(smem);
    const uint32_t sQH = sb;
    const uint32_t sQL = sb + PLANE;
    const uint32_t sK0 = sb + 2 * PLANE;            // stage s at sK0 + s*2*PLANE (h then l)
    float* stm = (float*)(smem + 6 * PLANE);        // [2][128]
    float* stl = (float*)(smem + 6 * PLANE + 1024); // [2][128]

    const int tid = threadIdx.x, wid = tid >> 5, lane = tid & 31;
    const int wm = (wid & 3) * 32, wn = (wid >> 2) * 64;
    const int z = blockIdx.z, b_ = z >> 3, h_ = z & 7;
    const long qrow0 = (long)b_ * 1024 + blockIdx.x * 128;
    const bf16* Qh = qhi + qrow0 * 512 + h_ * 64;
    const bf16* Ql = qlo + qrow0 * 512 + h_ * 64;
    const bf16* Kh = khi + (long)b_ * 1024 * 512 + h_ * 64;
    const bf16* Kl = klo + (long)b_ * 1024 * 512 + h_ * 64;
    float* Pz = P + ((long)z << 20) + (long)blockIdx.x * 128 * 1024;

    // Q loads (both planes), committed with first K tile
    #pragma unroll
    for (int i = 0; i < 4; i++) {
        int id = tid + i * 256; int r = id >> 3, c = id & 7;
        CP_ASYNC16(sQH + r * PITCH + c * 16, Qh + (long)r * 512 + c * 8);
        CP_ASYNC16(sQL + r * PITCH + c * 16, Ql + (long)r * 512 + c * 8);
    }
    auto loadK = [&](int kt, int s){
        uint32_t dh = sK0 + s * 2 * PLANE, dl = dh + PLANE;
        const bf16* sh = Kh + (long)kt * 128 * 512;
        const bf16* sl = Kl + (long)kt * 128 * 512;
        #pragma unroll
        for (int i = 0; i < 4; i++) {
            int id = tid + i * 256; int r = id >> 3, c = id & 7;
            CP_ASYNC16(dh + r * PITCH + c * 16, sh + (long)r * 512 + c * 8);
            CP_ASYNC16(dl + r * PITCH + c * 16, sl + (long)r * 512 + c * 8);
        }
        CP_COMMIT();
    };
    loadK(0, 0);

    const int arow = (lane & 7) + ((lane & 8)  ? 8 : 0);
    const int acol = (lane & 16) ? 8 : 0;
    const int brow = (lane & 7) + ((lane & 16) ? 8 : 0);
    const int bcol = (lane & 8) ? 8 : 0;

    float m_t[4], l_t[4], mrow[4], invl[4];
    #pragma unroll
    for (int i = 0; i < 4; i++) { m_t[i] = -1e30f; l_t[i] = 0.f; }

    float acc[64];

    for (int it = 0; it < 16; it++) {
        int s = it & 1, kt = it & 7;
        if (it + 1 < 16) { loadK((it + 1) & 7, s ^ 1); CP_WAIT(1); }
        else             { CP_WAIT(0); }
        __syncthreads();

        #pragma unroll
        for (int i = 0; i < 64; i++) acc[i] = 0.f;
        uint32_t kbase = sK0 + s * 2 * PLANE;
        #pragma unroll
        for (int ph = 0; ph < 3; ph++) {
            uint32_t abuf = (ph == 1) ? sQL : sQH;
            uint32_t bbuf = kbase + ((ph == 2) ? PLANE : 0);
            #pragma unroll
            for (int k16 = 0; k16 < 4; k16++) {
                uint32_t af[2][4];
                #pragma unroll
                for (int mi = 0; mi < 2; mi++)
                    ldsm4(abuf + (wm + mi * 16 + arow) * PITCH + (k16 * 16 + acol) * 2,
                          af[mi][0], af[mi][1], af[mi][2], af[mi][3]);
                uint32_t bfr[4][4];
                #pragma unroll
                for (int n2 = 0; n2 < 4; n2++)
                    ldsm4(bbuf + (wn + n2 * 16 + brow) * PITCH + (k16 * 16 + bcol) * 2,
                          bfr[n2][0], bfr[n2][1], bfr[n2][2], bfr[n2][3]);
                #pragma unroll
                for (int mi = 0; mi < 2; mi++)
                    #pragma unroll
                    for (int ni = 0; ni < 8; ni++)
                        mma16816(acc + (mi * 8 + ni) * 4, af[mi], bfr[ni >> 1] + (ni & 1) * 2);
            }
        }

        if (it < 8) {
            #pragma unroll
            for (int mi = 0; mi < 2; mi++)
                #pragma unroll
                for (int half = 0; half < 2; half++) {
                    int idx = mi * 2 + half;
                    float vmax = -1e30f;
                    #pragma unroll
                    for (int ni = 0; ni < 8; ni++) {
                        const float* a4 = acc + (mi * 8 + ni) * 4 + half * 2;
                        vmax = fmaxf(vmax, fmaxf(a4[0], a4[1]));
                    }
                    float mn = fmaxf(m_t[idx], vmax);
                    float sum = 0.f;
                    #pragma unroll
                    for (int ni = 0; ni < 8; ni++) {
                        const float* a4 = acc + (mi * 8 + ni) * 4 + half * 2;
                        sum += __expf(a4[0] - mn) + __expf(a4[1] - mn);
                    }
                    l_t[idx] = l_t[idx] * __expf(m_t[idx] - mn) + sum;
                    m_t[idx] = mn;
                }
            if (it == 7) {
                #pragma unroll
                for (int idx = 0; idx < 4; idx++) {
                    #pragma unroll
                    for (int off = 1; off < 4; off <<= 1) {
                        float mo = __shfl_xor_sync(0xffffffffu, m_t[idx], off);
                        float lo = __shfl_xor_sync(0xffffffffu, l_t[idx], off);
                        float mn = fmaxf(m_t[idx], mo);
                        l_t[idx] = l_t[idx] * __expf(m_t[idx] - mn) + lo * __expf(mo - mn);
                        m_t[idx] = mn;
                    }
                }
                if ((lane & 3) == 0) {
                    int g = wn >> 6;
                    #pragma unroll
                    for (int mi = 0; mi < 2; mi++)
                        #pragma unroll
                        for (int half = 0; half < 2; half++) {
                            int row = wm + mi * 16 + half * 8 + (lane >> 2);
                            stm[g * 128 + row] = m_t[mi * 2 + half];
                            stl[g * 128 + row] = l_t[mi * 2 + half];
                        }
                }
                __syncthreads();
                #pragma unroll
                for (int mi = 0; mi < 2; mi++)
                    #pragma unroll
                    for (int half = 0; half < 2; half++) {
                        int idx = mi * 2 + half;
                        int row = wm + mi * 16 + half * 8 + (lane >> 2);
                        float m1 = stm[row], l1 = stl[row];
                        float m2 = stm[128 + row], l2 = stl[128 + row];
                        float mn = fmaxf(m1, m2);
                        float l = l1 * __expf(m1 - mn) + l2 * __expf(m2 - mn);
                        mrow[idx] = mn; invl[idx] = 1.f / l;
                    }
            }
        } else {
            #pragma unroll
            for (int mi = 0; mi < 2; mi++)
                #pragma unroll
                for (int ni = 0; ni < 8; ni++)
                    #pragma unroll
                    for (int half = 0; half < 2; half++) {
                        int idx = mi * 2 + half;
                        int row = wm + mi * 16 + half * 8 + (lane >> 2);
                        int n0 = kt * 128 + wn + ni * 8 + (lane & 3) * 2;
                        const float* a4 = acc + (mi * 8 + ni) * 4 + half * 2;
                        float2 o;
                        o.x = __expf(a4[0] - mrow[idx]) * invl[idx];
                        o.y = __expf(a4[1] - mrow[idx]) * invl[idx];
                        *(float2*)(Pz + (long)row * 1024 + n0) = o;
                    }
        }
        __syncthreads();
    }
}

// ================= ctx = P(fp32) @ V : split-on-load GEMM =================
// A = P [1024x1024] fp32 per z (read once), B = vt hi/lo [dh=64][1024] K-major.
// C = ctx hi/lo. Tile 128x64, chunk 32, 3 phases over smem copies.
__global__ void __launch_bounds__(256)
gemm_pv(const float* __restrict__ P, const bf16* __restrict__ Vhi,
        const bf16* __restrict__ Vlo, bf16* __restrict__ Chi, bf16* __restrict__ Clo)
{
    constexpr int ROWB = 80;
    constexpr int ASZ = 128 * ROWB, BSZ = 64 * ROWB;
    constexpr int STAGE = 2 * ASZ + 2 * BSZ;

    extern __shared__ char smem[];
    const int tid = threadIdx.x, wid = tid >> 5, lane = tid & 31;
    const int wm = (wid & 3) * 32, wn = (wid >> 2) * 32;   // NI=4

    int z = blockIdx.z, b_ = z >> 3, h_ = z & 7;
    long bm = (long)blockIdx.y * 128;
    const float* Pz = P + ((long)z << 20) + bm * 1024;
    const bf16* Bh = Vhi + (long)b_ * 512 * 1024 + (long)h_ * 64 * 1024;
    const bf16* Bl = Vlo + (long)b_ * 512 * 1024 + (long)h_ * 64 * 1024;
    bf16* Ch = Chi + (long)b_ * 1024 * 512 + h_ * 64 + bm * 512;
    bf16* Cl = Clo + (long)b_ * 1024 * 512 + h_ * 64 + bm * 512;

    const uint32_t sb = smem_u32(smem);

    float4 ra[4];
    auto ldgA = [&](int kc){
        long k0 = (long)kc * 32;
        #pragma unroll
        for (int i = 0; i < 4; i++) {
            int id = tid * 4 + i; int r = id >> 3, c4 = id & 7;
            ra[i] = *(const float4*)(Pz + (long)r * 1024 + k0 + c4 * 4);
        }
    };
    auto stsA = [&](int s){
        char* base = smem + s * STAGE;
        #pragma unroll
        for (int i = 0; i < 4; i++) {
            int id = tid * 4 + i; int r = id >> 3, c4 = id & 7;
            bf16 h0,l0,h1,l1,h2,l2,h3,l3;
            split1(ra[i].x,h0,l0); split1(ra[i].y,h1,l1);
            split1(ra[i].z,h2,l2); split1(ra[i].w,h3,l3);
            unsigned short hs[4] = {__bfloat16_as_ushort(h0), __bfloat16_as_ushort(h1),
                                    __bfloat16_as_ushort(h2), __bfloat16_as_ushort(h3)};
            unsigned short ls[4] = {__bfloat16_as_ushort(l0), __bfloat16_as_ushort(l1),
                                    __bfloat16_as_ushort(l2), __bfloat16_as_ushort(l3)};
            *(uint2*)(base + r * ROWB + c4 * 8)       = *(uint2*)hs;
            *(uint2*)(base + ASZ + r * ROWB + c4 * 8) = *(uint2*)ls;
        }
    };
    auto loadB = [&](int kc, int s){
        long k0 = (long)kc * 32;
        uint32_t base = sb + s * STAGE + 2 * ASZ;
        int r = tid >> 2, c = tid & 3;   // 64 rows x 4 chunks
        CP_ASYNC16(base + r * ROWB + c * 16,       Bh + (long)r * 1024 + k0 + c * 8);
        CP_ASYNC16(base + BSZ + r * ROWB + c * 16, Bl + (long)r * 1024 + k0 + c * 8);
        CP_COMMIT();
    };

    float acc[32];
    #pragma unroll
    for (int i = 0; i < 32; i++) acc[i] = 0.f;

    const int arow = (lane & 7) + ((lane & 8)  ? 8 : 0);
    const int acol = (lane & 16) ? 8 : 0;
    const int brow = (lane & 7) + ((lane & 16) ? 8 : 0);
    const int bcol = (lane & 8) ? 8 : 0;

    ldgA(0); loadB(0, 0);

    for (int kc = 0; kc < 32; kc++) {
        int s = kc & 1;
        stsA(s);
        if (kc + 1 < 32) { ldgA(kc + 1); loadB(kc + 1, s ^ 1); CP_WAIT(1); }
        else             { CP_WAIT(0); }
        __syncthreads();

        uint32_t base = sb + s * STAGE;
        #pragma unroll
        for (int ph = 0; ph < 3; ph++) {
            uint32_t abuf = base + ((ph == 1) ? ASZ : 0);
            uint32_t bbuf = base + 2 * ASZ + ((ph == 2) ? BSZ : 0);
            #pragma unroll
            for (int k16 = 0; k16 < 2; k16++) {
                uint32_t af[2][4];
                #pragma unroll
                for (int mi = 0; mi < 2; mi++)
                    ldsm4(abuf + (wm + mi * 16 + arow) * ROWB + (k16 * 16 + acol) * 2,
                          af[mi][0], af[mi][1], af[mi][2], af[mi][3]);
                uint32_t bfr[2][4];
                #pragma unroll
                for (int n2 = 0; n2 < 2; n2++)
                    ldsm4(bbuf + (wn + n2 * 16 + brow) * ROWB + (k16 * 16 + bcol) * 2,
                          bfr[n2][0], bfr[n2][1], bfr[n2][2], bfr[n2][3]);
                #pragma unroll
                for (int mi = 0; mi < 2; mi++)
                    #pragma unroll
                    for (int ni = 0; ni < 4; ni++)
                        mma16816(acc + (mi * 4 + ni) * 4, af[mi], bfr[ni >> 1] + (ni & 1) * 2);
            }
        }
        __syncthreads();
    }

    #pragma unroll
    for (int mi = 0; mi < 2; mi++)
        #pragma unroll
        for (int ni = 0; ni < 4; ni++) {
            const float* a4 = acc + (mi * 4 + ni) * 4;
            int n0 = wn + ni * 8 + (lane & 3) * 2;
            #pragma unroll
            for (int half = 0; half < 2; half++) {
                long m = wm + mi * 16 + (lane >> 2) + half * 8;
                bf16 h0, l0, h1, l1;
                split1(a4[half * 2 + 0], h0, l0);
                split1(a4[half * 2 + 1], h1, l1);
                unsigned short hs[2] = {__bfloat16_as_ushort(h0), __bfloat16_as_ushort(h1)};
                unsigned short ls[2] = {__bfloat16_as_ushort(l0), __bfloat16_as_ushort(l1)};
                *(uint32_t*)(Ch + m * 512 + n0) = *(uint32_t*)hs;
                *(uint32_t*)(Cl + m * 512 + n0) = *(uint32_t*)ls;
            }
        }
}

// ================= LayerNorm (row=512), optional fp32/hi/lo out =================
__global__ void ln_kernel2(const float* __restrict__ x, const float* __restrict__ x2,
                           const float* __restrict__ w, const float* __restrict__ bb,
                           float* __restrict__ outf, bf16* __restrict__ ohi, bf16* __restrict__ olo)
{
    int row = blockIdx.x;
    int t = threadIdx.x;
    float4 v = ((const float4*)(x + (long)row * 512))[t];
    if (x2) {
        float4 v2 = ((const float4*)(x2 + (long)row * 512))[t];
        v.x += v2.x; v.y += v2.y; v.z += v2.z; v.w += v2.w;
    }
    float s  = v.x + v.y + v.z + v.w;
    float sq = v.x*v.x + v.y*v.y + v.z*v.z + v.w*v.w;
    #pragma unroll
    for (int o = 16; o > 0; o >>= 1) {
        s  += __shfl_xor_sync(0xffffffffu, s,  o);
        sq += __shfl_xor_sync(0xffffffffu, sq, o);
    }
    __shared__ float ss[4], ssq[4];
    int wid = t >> 5, lane = t & 31;
    if (lane == 0) { ss[wid] = s; ssq[wid] = sq; }
    __syncthreads();
    s  = ss[0]  + ss[1]  + ss[2]  + ss[3];
    sq = ssq[0] + ssq[1] + ssq[2] + ssq[3];
    float mu  = s * (1.0f / 512.0f);
    float var = sq * (1.0f / 512.0f) - mu * mu;
    float inv = rsqrtf(var + EPS);
    float4 wv = ((const float4*)w)[t];
    float4 bv = ((const float4*)bb)[t];
    float o4[4];
    o4[0] = (v.x - mu) * inv * wv.x + bv.x;
    o4[1] = (v.y - mu) * inv * wv.y + bv.y;
    o4[2] = (v.z - mu) * inv * wv.z + bv.z;
    o4[3] = (v.w - mu) * inv * wv.w + bv.w;
    long base = (long)row * 512 + t * 4;
    if (outf) *(float4*)(outf + base) = *(float4*)o4;
    if (ohi) {
        unsigned short hs[4], ls[4];
        #pragma unroll
        for (int j = 0; j < 4; j++) {
            bf16 h, l; split1(o4[j], h, l);
            hs[j] = __bfloat16_as_ushort(h);
            ls[j] = __bfloat16_as_ushort(l);
        }
        *(uint2*)(ohi + base) = *(uint2*)hs;
        *(uint2*)(olo + base) = *(uint2*)ls;
    }
}

// ================= split fp32 -> bf16 hi/lo =================
__global__ void split_kernel(const float* __restrict__ x, bf16* __restrict__ hi,
                             bf16* __restrict__ lo)
{
    long i = ((long)blockIdx.x * 256 + threadIdx.x) * 4;
    float4 v = *(const float4*)(x + i);
    float a[4] = {v.x, v.y, v.z, v.w};
    unsigned short hs[4], ls[4];
    #pragma unroll
    for (int j = 0; j < 4; j++) {
        bf16 h, l; split1(a[j], h, l);
        hs[j] = __bfloat16_as_ushort(h);
        ls[j] = __bfloat16_as_ushort(l);
    }
    *(uint2*)(hi + i) = *(uint2*)hs;
    *(uint2*)(lo + i) = *(uint2*)ls;
}

// split K half of kv [8192][1024] (cols 0..511) -> k_hi/k_lo [8192][512]
__global__ void split_k_kernel(const float* __restrict__ kv, bf16* __restrict__ hi,
                               bf16* __restrict__ lo)
{
    long i = ((long)blockIdx.x * 256 + threadIdx.x) * 4;
    long r = i >> 9, c = i & 511;
    float4 v = *(const float4*)(kv + r * 1024 + c);
    float a[4] = {v.x, v.y, v.z, v.w};
    unsigned short hs[4], ls[4];
    #pragma unroll
    for (int j = 0; j < 4; j++) {
        bf16 h, l; split1(a[j], h, l);
        hs[j] = __bfloat16_as_ushort(h);
        ls[j] = __bfloat16_as_ushort(l);
    }
    *(uint2*)(hi + i) = *(uint2*)hs;
    *(uint2*)(lo + i) = *(uint2*)ls;
}

// transpose V half of kv: vt[b][n][s] = kv[b][s][512+n], split to hi/lo
__global__ void transpose_v_kernel(const float* __restrict__ kv,
                                   bf16* __restrict__ vhi, bf16* __restrict__ vlo)
{
    __shared__ float t[32][33];
    int b = blockIdx.z;
    int s0 = blockIdx.x * 32, n0 = blockIdx.y * 32;
    int tx = threadIdx.x, ty = threadIdx.y;
    #pragma unroll
    for (int i = 0; i < 4; i++) {
        int s = s0 + ty + i * 8;
        t[ty + i * 8][tx] = kv[((long)b * 1024 + s) * 1024 + 512 + n0 + tx];
    }
    __syncthreads();
    #pragma unroll
    for (int i = 0; i < 4; i++) {
        int n = n0 + ty + i * 8;
        float v = t[tx][ty + i * 8];
        bf16 h, l; split1(v, h, l);
        long o = (long)b * 512 * 1024 + (long)n * 1024 + s0 + tx;
        vhi[o] = h; vlo[o] = l;
    }
}

// ================= attn_weights = mean over H (fp32 P) =================
__global__ void mean_headsf(const float* __restrict__ P, float* __restrict__ out)
{
    long i = ((long)blockIdx.x * 256 + threadIdx.x) * 4;
    long b = i >> 20;
    long rem = i & 1048575;
    const float* p = P + (b << 23) + rem;
    float4 s = {0.f, 0.f, 0.f, 0.f};
    #pragma unroll
    for (int h = 0; h < 8; h++) {
        float4 v = *(const float4*)(p + ((long)h << 20));
        s.x += v.x; s.y += v.y; s.z += v.z; s.w += v.w;
    }
    s.x *= 0.125f; s.y *= 0.125f; s.z *= 0.125f; s.w *= 0.125f;
    *(float4*)(out + i) = s;
}

// ================= launch =================
extern "C" void kernel_launch(void* const* d_in, const int* in_sizes, int n_in,
                              void* d_out, int out_size)
{
    (void)in_sizes; (void)n_in; (void)out_size;
    const float* Zab   = (const float*)d_in[0];
    const float* Za    = (const float*)d_in[1];
    const float* ln_w  = (const float*)d_in[2];
    const float* ln_b  = (const float*)d_in[3];
    const float* in_w  = (const float*)d_in[4];
    const float* in_b  = (const float*)d_in[5];
    const float* out_w = (const float*)d_in[6];
    const float* out_b = (const float*)d_in[7];
    const float* ff_w  = (const float*)d_in[8];
    const float* ff_b  = (const float*)d_in[9];

    float* out_final = (float*)d_out;
    float* out_attnw = (float*)d_out + 8192L * 512;

    bf16 *qin_hi, *qin_lo, *kvin_hi, *kvin_lo, *inw_hi, *inw_lo;
    bf16 *outw_hi, *outw_lo, *ffw_hi, *ffw_lo, *q_hi, *q_lo;
    bf16 *k_hi, *k_lo, *vt_hi, *vt_lo, *ctx_hi, *ctx_lo, *xn_hi, *xn_lo;
    float *kv, *p, *x, *xn, *ff;
    cudaGetSymbolAddress((void**)&qin_hi,  g_qin_hi);
    cudaGetSymbolAddress((void**)&qin_lo,  g_qin_lo);
    cudaGetSymbolAddress((void**)&kvin_hi, g_kvin_hi);
    cudaGetSymbolAddress((void**)&kvin_lo, g_kvin_lo);
    cudaGetSymbolAddress((void**)&inw_hi,  g_inw_hi);
    cudaGetSymbolAddress((void**)&inw_lo,  g_inw_lo);
    cudaGetSymbolAddress((void**)&outw_hi, g_outw_hi);
    cudaGetSymbolAddress((void**)&outw_lo, g_outw_lo);
    cudaGetSymbolAddress((void**)&ffw_hi,  g_ffw_hi);
    cudaGetSymbolAddress((void**)&ffw_lo,  g_ffw_lo);
    cudaGetSymbolAddress((void**)&q_hi,    g_q_hi);
    cudaGetSymbolAddress((void**)&q_lo,    g_q_lo);
    cudaGetSymbolAddress((void**)&k_hi,    g_k_hi);
    cudaGetSymbolAddress((void**)&k_lo,    g_k_lo);
    cudaGetSymbolAddress((void**)&vt_hi,   g_vt_hi);
    cudaGetSymbolAddress((void**)&vt_lo,   g_vt_lo);
    cudaGetSymbolAddress((void**)&ctx_hi,  g_ctx_hi);
    cudaGetSymbolAddress((void**)&ctx_lo,  g_ctx_lo);
    cudaGetSymbolAddress((void**)&xn_hi,   g_xn_hi);
    cudaGetSymbolAddress((void**)&xn_lo,   g_xn_lo);
    cudaGetSymbolAddress((void**)&kv, g_kv);
    cudaGetSymbolAddress((void**)&p,  g_p);
    cudaGetSymbolAddress((void**)&x,  g_x);
    cudaGetSymbolAddress((void**)&xn, g_xn);
    cudaGetSymbolAddress((void**)&ff, g_ff);

    const int SMEM_PI  = 2 * (2 * 128 * 80 + 2 * 128 * 80);       // 81920
    const int SMEM_PV  = 2 * (2 * 128 * 80 + 2 * 64 * 80);        // 61440
    const int SMEM_ATT = 6 * 128 * 144 + 2048;                    // 112640
    cudaFuncSetAttribute((const void*)gemm_pi<128>,
                         cudaFuncAttributeMaxDynamicSharedMemorySize, SMEM_PI);
    cudaFuncSetAttribute((const void*)gemm_pv,
                         cudaFuncAttributeMaxDynamicSharedMemorySize, SMEM_PV);
    cudaFuncSetAttribute((const void*)attn_fused,
                         cudaFuncAttributeMaxDynamicSharedMemorySize, SMEM_ATT);

    // 1) LN of inputs -> bf16 hi/lo
    ln_kernel2<<<8192, 128>>>(Zab, nullptr, ln_w, ln_b, nullptr, qin_hi, qin_lo);
    ln_kernel2<<<8192, 128>>>(Za,  nullptr, ln_w, ln_b, nullptr, kvin_hi, kvin_lo);

    // 2) split weights
    split_kernel<<<768, 256>>>(in_w,  inw_hi,  inw_lo);
    split_kernel<<<256, 256>>>(out_w, outw_hi, outw_lo);
    split_kernel<<<256, 256>>>(ff_w,  ffw_hi,  ffw_lo);

    // 3) q = 0.125*(qin @ Wq^T + bq)  -> bf16 hi/lo
    gemm_pi<128><<<dim3(4, 64, 1), 256, SMEM_PI>>>(
        qin_hi, qin_lo, 512, 0, 0,
        inw_hi, inw_lo, 512, 0, 0,
        nullptr, q_hi, q_lo, 512, 0, 0,
        512, 1, 0.125f, in_b, nullptr);

    // 4) kv = kvin @ [Wk;Wv]^T + [bk;bv]  -> fp32
    gemm_pi<128><<<dim3(8, 64, 1), 256, SMEM_PI>>>(
        kvin_hi, kvin_lo, 512, 0, 0,
        inw_hi + 512L * 512, inw_lo + 512L * 512, 512, 0, 0,
        kv, nullptr, nullptr, 1024, 0, 0,
        512, 1, 1.0f, in_b + 512, nullptr);

    // 5) k -> hi/lo ; V -> transposed hi/lo
    split_k_kernel<<<4096, 256>>>(kv, k_hi, k_lo);
    transpose_v_kernel<<<dim3(32, 16, 8), dim3(32, 8)>>>(kv, vt_hi, vt_lo);

    // 6) fused scores+softmax -> P fp32
    attn_fused<<<dim3(8, 1, 64), 256, SMEM_ATT>>>(q_hi, q_lo, k_hi, k_lo, p);

    // 7) attn_weights = mean over heads
    mean_headsf<<<8192, 256>>>(p, out_attnw);

    // 8) ctx = P @ V  -> ctx hi/lo
    gemm_pv<<<dim3(1, 8, 64), 256, SMEM_PV>>>(p, vt_hi, vt_lo, ctx_hi, ctx_lo);

    // 9) x = ctx @ Wo^T + bo + Zab
    gemm_pi<128><<<dim3(4, 64, 1), 256, SMEM_PI>>>(
        ctx_hi, ctx_lo, 512, 0, 0,
        outw_hi, outw_lo, 512, 0, 0,
        x, nullptr, nullptr, 512, 0, 0,
        512, 1, 1.0f, out_b, Zab);

    // 10) x_n = LN(x)
    ln_kernel2<<<8192, 128>>>(x, nullptr, ln_w, ln_b, xn, xn_hi, xn_lo);

    // 11) ff = x_n @ ff_w^T + ff_b
    gemm_pi<128><<<dim3(4, 64, 1), 256, SMEM_PI>>>(
        xn_hi, xn_lo, 512, 0, 0,
        ffw_hi, ffw_lo, 512, 0, 0,
        ff, nullptr, nullptr, 512, 0, 0,
        512, 1, 1.0f, ff_b, nullptr);

    // 12) final = LN(x_n + ff) -> d_out
    ln_kernel2<<<8192, 128>>>(xn, ff, ln_w, ln_b, out_final, nullptr, nullptr);
}

// round 6
// speedup vs baseline: 2.6349x; 1.0498x over previous
#include <cuda_runtime.h>
#include <cuda_bf16.h>
#include <cstdint>

#define EPS 1e-5f
typedef __nv_bfloat16 bf16;

// ================= scratch (no allocation allowed) =================
__device__ bf16  g_qin_hi [8192L * 512];
__device__ bf16  g_qin_lo [8192L * 512];
__device__ bf16  g_kvin_hi[8192L * 512];
__device__ bf16  g_kvin_lo[8192L * 512];
__device__ bf16  g_inw_hi [1536L * 512];
__device__ bf16  g_inw_lo [1536L * 512];
__device__ bf16  g_outw_hi[512L * 512];
__device__ bf16  g_outw_lo[512L * 512];
__device__ bf16  g_ffw_hi [512L * 512];
__device__ bf16  g_ffw_lo [512L * 512];
__device__ bf16  g_q_hi   [8192L * 512];
__device__ bf16  g_q_lo   [8192L * 512];
__device__ float g_kv     [8192L * 1024];
__device__ bf16  g_k_hi   [8192L * 512];
__device__ bf16  g_k_lo   [8192L * 512];
__device__ bf16  g_vt_hi  [8L * 512 * 1024];
__device__ bf16  g_vt_lo  [8L * 512 * 1024];
__device__ float g_p      [64LL * 1024 * 1024];   // probabilities fp32, 256 MB
__device__ bf16  g_ctx_hi [8192L * 512];
__device__ bf16  g_ctx_lo [8192L * 512];
__device__ float g_x      [8192L * 512];
__device__ float g_xn     [8192L * 512];
__device__ bf16  g_xn_hi  [8192L * 512];
__device__ bf16  g_xn_lo  [8192L * 512];
__device__ float g_ff     [8192L * 512];

// ================= helpers =================
__device__ __forceinline__ uint32_t smem_u32(const void* p){
    uint32_t a;
    asm("{ .reg .u64 t; cvta.to.shared.u64 t, %1; cvt.u32.u64 %0, t; }" : "=r"(a) : "l"(p));
    return a;
}
#define CP_ASYNC16(dst, src) \
    asm volatile("cp.async.cg.shared.global [%0], [%1], 16;" :: "r"(dst), "l"(src))
#define CP_COMMIT() asm volatile("cp.async.commit_group;" ::: "memory")
#define CP_WAIT(n)  asm volatile("cp.async.wait_group %0;" :: "n"(n) : "memory")

__device__ __forceinline__ void ldsm4(uint32_t addr, uint32_t& r0, uint32_t& r1,
                                      uint32_t& r2, uint32_t& r3){
    asm volatile("ldmatrix.sync.aligned.m8n8.x4.shared.b16 {%0,%1,%2,%3}, [%4];"
                 : "=r"(r0), "=r"(r1), "=r"(r2), "=r"(r3) : "r"(addr));
}
__device__ __forceinline__ void mma16816(float* d, const uint32_t* a, const uint32_t* b){
    asm volatile("mma.sync.aligned.m16n8k16.row.col.f32.bf16.bf16.f32 "
                 "{%0,%1,%2,%3},{%4,%5,%6,%7},{%8,%9},{%0,%1,%2,%3};"
                 : "+f"(d[0]), "+f"(d[1]), "+f"(d[2]), "+f"(d[3])
                 : "r"(a[0]), "r"(a[1]), "r"(a[2]), "r"(a[3]), "r"(b[0]), "r"(b[1]));
}
__device__ __forceinline__ void split1(float v, bf16& h, bf16& l){
    h = __float2bfloat16_rn(v);
    l = __float2bfloat16_rn(v - __bfloat162float(h));
}
__device__ __forceinline__ uint32_t pack_bf2(bf16 a, bf16 b){
    return (uint32_t)__bfloat16_as_ushort(a) | ((uint32_t)__bfloat16_as_ushort(b) << 16);
}

// ================= phase-inner HMMA split-bf16 GEMM =================
template<int NT>
__global__ void __launch_bounds__(256)
gemm_pi(const bf16* __restrict__ Ahi, const bf16* __restrict__ Alo,
        long lda, long sAb, long sAh,
        const bf16* __restrict__ Bhi, const bf16* __restrict__ Blo,
        long ldb, long sBb, long sBh,
        float* __restrict__ C, bf16* __restrict__ Chi, bf16* __restrict__ Clo,
        long ldc, long sCb, long sCh,
        int K, int Hn, float scale,
        const float* __restrict__ bias, const float* __restrict__ resid)
{
    constexpr int WN  = (NT == 128) ? 64 : 32;
    constexpr int NI  = WN / 8;
    constexpr int NI2 = NI / 2;
    constexpr int ROWB = 80;
    constexpr int ASZ = 128 * ROWB;
    constexpr int BSZ = NT * ROWB;
    constexpr int STAGE = 2 * ASZ + 2 * BSZ;
    constexpr int NB = (NT * 4) / 256;

    extern __shared__ char smem[];
    const int tid = threadIdx.x, wid = tid >> 5, lane = tid & 31;
    const int wm = (wid & 3) * 32, wn = (wid >> 2) * WN;

    int z = blockIdx.z;
    int b_ = z / Hn, h_ = z % Hn;
    long bm = (long)blockIdx.y * 128;
    long bn = (long)blockIdx.x * NT;
    const bf16* Ah = Ahi + (long)b_*sAb + (long)h_*sAh + bm*lda;
    const bf16* Al = Alo + (long)b_*sAb + (long)h_*sAh + bm*lda;
    const bf16* Bh = Bhi + (long)b_*sBb + (long)h_*sBh + bn*ldb;
    const bf16* Bl = Blo + (long)b_*sBb + (long)h_*sBh + bn*ldb;
    long cbase = (long)b_*sCb + (long)h_*sCh;

    const uint32_t sb = smem_u32(smem);

    auto loadc = [&](int kc, int s){
        long k0 = (long)kc * 32;
        uint32_t base = sb + s * STAGE;
        #pragma unroll
        for (int i = 0; i < 2; i++) {
            int id = tid + i * 256; int r = id >> 2, c = id & 3;
            CP_ASYNC16(base + r * ROWB + c * 16,       Ah + (long)r * lda + k0 + c * 8);
            CP_ASYNC16(base + ASZ + r * ROWB + c * 16, Al + (long)r * lda + k0 + c * 8);
        }
        #pragma unroll
        for (int i = 0; i < NB; i++) {
            int id = tid + i * 256; int r = id >> 2, c = id & 3;
            CP_ASYNC16(base + 2*ASZ + r * ROWB + c * 16,       Bh + (long)r * ldb + k0 + c * 8);
            CP_ASYNC16(base + 2*ASZ + BSZ + r * ROWB + c * 16, Bl + (long)r * ldb + k0 + c * 8);
        }
        CP_COMMIT();
    };

    float acc[2 * NI * 4];
    #pragma unroll
    for (int i = 0; i < 2 * NI * 4; i++) acc[i] = 0.f;

    const int arow = (lane & 7) + ((lane & 8)  ? 8 : 0);
    const int acol = (lane & 16) ? 8 : 0;
    const int brow = (lane & 7) + ((lane & 16) ? 8 : 0);
    const int bcol = (lane & 8) ? 8 : 0;

    const int KC = K >> 5;
    loadc(0, 0);

    for (int kc = 0; kc < KC; kc++) {
        int s = kc & 1;
        if (kc + 1 < KC) { loadc(kc + 1, s ^ 1); CP_WAIT(1); }
        else             { CP_WAIT(0); }
        __syncthreads();

        uint32_t base = sb + s * STAGE;
        #pragma unroll
        for (int ph = 0; ph < 3; ph++) {
            uint32_t abuf = base + ((ph == 1) ? ASZ : 0);
            uint32_t bbuf = base + 2*ASZ + ((ph == 2) ? BSZ : 0);
            #pragma unroll
            for (int k16 = 0; k16 < 2; k16++) {
                uint32_t af[2][4];
                #pragma unroll
                for (int mi = 0; mi < 2; mi++)
                    ldsm4(abuf + (wm + mi * 16 + arow) * ROWB + (k16 * 16 + acol) * 2,
                          af[mi][0], af[mi][1], af[mi][2], af[mi][3]);
                uint32_t bfr[NI2][4];
                #pragma unroll
                for (int n2 = 0; n2 < NI2; n2++)
                    ldsm4(bbuf + (wn + n2 * 16 + brow) * ROWB + (k16 * 16 + bcol) * 2,
                          bfr[n2][0], bfr[n2][1], bfr[n2][2], bfr[n2][3]);
                #pragma unroll
                for (int mi = 0; mi < 2; mi++)
                    #pragma unroll
                    for (int ni = 0; ni < NI; ni++)
                        mma16816(acc + (mi * NI + ni) * 4, af[mi], bfr[ni >> 1] + (ni & 1) * 2);
            }
        }
        __syncthreads();
    }

    #pragma unroll
    for (int mi = 0; mi < 2; mi++) {
        #pragma unroll
        for (int ni = 0; ni < NI; ni++) {
            const float* a4 = acc + (mi * NI + ni) * 4;
            int n0 = (int)bn + wn + ni * 8 + (lane & 3) * 2;
            #pragma unroll
            for (int half = 0; half < 2; half++) {
                long m = bm + wm + mi * 16 + (lane >> 2) + half * 8;
                float v0 = a4[half * 2 + 0];
                float v1 = a4[half * 2 + 1];
                if (bias) { v0 += bias[n0]; v1 += bias[n0 + 1]; }
                v0 *= scale; v1 *= scale;
                if (resid) {
                    float2 rr = *(const float2*)(resid + cbase + m * ldc + n0);
                    v0 += rr.x; v1 += rr.y;
                }
                if (C) {
                    float2 o; o.x = v0; o.y = v1;
                    *(float2*)(C + cbase + m * ldc + n0) = o;
                }
                if (Chi) {
                    bf16 h0, l0, h1, l1;
                    split1(v0, h0, l0); split1(v1, h1, l1);
                    unsigned short hs[2] = {__bfloat16_as_ushort(h0), __bfloat16_as_ushort(h1)};
                    unsigned short ls[2] = {__bfloat16_as_ushort(l0), __bfloat16_as_ushort(l1)};
                    *(uint32_t*)(Chi + cbase + m * ldc + n0) = *(uint32_t*)hs;
                    *(uint32_t*)(Clo + cbase + m * ldc + n0) = *(uint32_t*)ls;
                }
            }
        }
    }
}

// ================= fused scores + softmax + P@V =================
// CTA: 128 q rows x one (b,h). Q resident (hi/lo), K streamed twice,
// V streamed in pass 2. Pass 1: online (m,l). Pass 2: P = exp(s-m)/l,
// write P fp32 (for head-mean), convert P to bf16 hi/lo A-fragments in
// registers, MMA against V tile (3 phases), accumulate O. Epilogue:
// reduce O across the 2 n-warp groups via smem, write ctx hi/lo.
__global__ void __launch_bounds__(256)
attn_fused_pv(const bf16* __restrict__ qhi, const bf16* __restrict__ qlo,
              const bf16* __restrict__ khi, const bf16* __restrict__ klo,
              const bf16* __restrict__ vhi, const bf16* __restrict__ vlo,
              float* __restrict__ P,
              bf16* __restrict__ ctxhi, bf16* __restrict__ ctxlo)
{
    constexpr int PITCH  = 144;            // 64 bf16 + 16B pad
    constexpr int PLANE  = 128 * PITCH;    // 18432
    constexpr int VPITCH = 272;            // 128 bf16 + 16B pad
    constexpr int VPLANE = 64 * VPITCH;    // 17408
    extern __shared__ char smem[];
    const uint32_t sb  = smem_u32(smem);
    const uint32_t sQH = sb;
    const uint32_t sQL = sb + PLANE;
    const uint32_t sK0 = sb + 2 * PLANE;             // K stage s: 2 planes
    const uint32_t sV0 = sb + 6 * PLANE;             // V stage s: 2 planes
    float* stm = (float*)(smem + 6 * PLANE + 4 * VPLANE);        // [2][128]
    float* stl = (float*)(smem + 6 * PLANE + 4 * VPLANE + 1024);

    const int tid = threadIdx.x, wid = tid >> 5, lane = tid & 31;
    const int wm = (wid & 3) * 32, wn = (wid >> 2) * 64;
    const int z = blockIdx.z, b_ = z >> 3, h_ = z & 7;
    const long qrow0 = (long)b_ * 1024 + blockIdx.x * 128;
    const bf16* Qh = qhi + qrow0 * 512 + h_ * 64;
    const bf16* Ql = qlo + qrow0 * 512 + h_ * 64;
    const bf16* Kh = khi + (long)b_ * 1024 * 512 + h_ * 64;
    const bf16* Kl = klo + (long)b_ * 1024 * 512 + h_ * 64;
    const bf16* Vh = vhi + (long)b_ * 512 * 1024 + (long)h_ * 64 * 1024;
    const bf16* Vl = vlo + (long)b_ * 512 * 1024 + (long)h_ * 64 * 1024;
    float* Pz = P + ((long)z << 20) + (long)blockIdx.x * 128 * 1024;
    bf16* Chb = ctxhi + (qrow0 + blockIdx.x * 0) * 512 + h_ * 64;   // base uses qrow0
    bf16* Clb = ctxlo + qrow0 * 512 + h_ * 64;
    Chb = ctxhi + qrow0 * 512 + h_ * 64;

    // Q loads (both planes), committed with first K tile
    #pragma unroll
    for (int i = 0; i < 4; i++) {
        int id = tid + i * 256; int r = id >> 3, c = id & 7;
        CP_ASYNC16(sQH + r * PITCH + c * 16, Qh + (long)r * 512 + c * 8);
        CP_ASYNC16(sQL + r * PITCH + c * 16, Ql + (long)r * 512 + c * 8);
    }
    auto loadK = [&](int kt, int s){
        uint32_t dh = sK0 + s * 2 * PLANE, dl = dh + PLANE;
        const bf16* sh = Kh + (long)kt * 128 * 512;
        const bf16* sl = Kl + (long)kt * 128 * 512;
        #pragma unroll
        for (int i = 0; i < 4; i++) {
            int id = tid + i * 256; int r = id >> 3, c = id & 7;
            CP_ASYNC16(dh + r * PITCH + c * 16, sh + (long)r * 512 + c * 8);
            CP_ASYNC16(dl + r * PITCH + c * 16, sl + (long)r * 512 + c * 8);
        }
    };
    auto loadV = [&](int kt, int s){
        uint32_t dh = sV0 + s * 2 * VPLANE, dl = dh + VPLANE;
        const bf16* sh = Vh + (long)kt * 128;
        const bf16* sl = Vl + (long)kt * 128;
        #pragma unroll
        for (int i = 0; i < 4; i++) {
            int id = tid + i * 256; int r = id >> 4, c = id & 15;   // 64 rows x 16 chunks
            CP_ASYNC16(dh + r * VPITCH + c * 16, sh + (long)r * 1024 + c * 8);
            CP_ASYNC16(dl + r * VPITCH + c * 16, sl + (long)r * 1024 + c * 8);
        }
    };
    loadK(0, 0);
    CP_COMMIT();

    const int arow = (lane & 7) + ((lane & 8)  ? 8 : 0);
    const int acol = (lane & 16) ? 8 : 0;
    const int brow = (lane & 7) + ((lane & 16) ? 8 : 0);
    const int bcol = (lane & 8) ? 8 : 0;

    float m_t[4], l_t[4], mrow[4], invl[4];
    #pragma unroll
    for (int i = 0; i < 4; i++) { m_t[i] = -1e30f; l_t[i] = 0.f; }

    float oac[64];
    #pragma unroll
    for (int i = 0; i < 64; i++) oac[i] = 0.f;

    float acc[64];

    for (int it = 0; it < 16; it++) {
        int s = it & 1, kt = it & 7;
        if (it + 1 < 16) {
            loadK((it + 1) & 7, s ^ 1);
            if (it + 1 >= 8) loadV((it + 1) & 7, s ^ 1);
            CP_COMMIT();
            CP_WAIT(1);
        } else {
            CP_WAIT(0);
        }
        __syncthreads();

        #pragma unroll
        for (int i = 0; i < 64; i++) acc[i] = 0.f;
        uint32_t kbase = sK0 + s * 2 * PLANE;
        #pragma unroll
        for (int ph = 0; ph < 3; ph++) {
            uint32_t abuf = (ph == 1) ? sQL : sQH;
            uint32_t bbuf = kbase + ((ph == 2) ? PLANE : 0);
            #pragma unroll
            for (int k16 = 0; k16 < 4; k16++) {
                uint32_t af[2][4];
                #pragma unroll
                for (int mi = 0; mi < 2; mi++)
                    ldsm4(abuf + (wm + mi * 16 + arow) * PITCH + (k16 * 16 + acol) * 2,
                          af[mi][0], af[mi][1], af[mi][2], af[mi][3]);
                uint32_t bfr[4][4];
                #pragma unroll
                for (int n2 = 0; n2 < 4; n2++)
                    ldsm4(bbuf + (wn + n2 * 16 + brow) * PITCH + (k16 * 16 + bcol) * 2,
                          bfr[n2][0], bfr[n2][1], bfr[n2][2], bfr[n2][3]);
                #pragma unroll
                for (int mi = 0; mi < 2; mi++)
                    #pragma unroll
                    for (int ni = 0; ni < 8; ni++)
                        mma16816(acc + (mi * 8 + ni) * 4, af[mi], bfr[ni >> 1] + (ni & 1) * 2);
            }
        }

        if (it < 8) {
            // pass 1: online max/sumexp
            #pragma unroll
            for (int mi = 0; mi < 2; mi++)
                #pragma unroll
                for (int half = 0; half < 2; half++) {
                    int idx = mi * 2 + half;
                    float vmax = -1e30f;
                    #pragma unroll
                    for (int ni = 0; ni < 8; ni++) {
                        const float* a4 = acc + (mi * 8 + ni) * 4 + half * 2;
                        vmax = fmaxf(vmax, fmaxf(a4[0], a4[1]));
                    }
                    float mn = fmaxf(m_t[idx], vmax);
                    float sum = 0.f;
                    #pragma unroll
                    for (int ni = 0; ni < 8; ni++) {
                        const float* a4 = acc + (mi * 8 + ni) * 4 + half * 2;
                        sum += __expf(a4[0] - mn) + __expf(a4[1] - mn);
                    }
                    l_t[idx] = l_t[idx] * __expf(m_t[idx] - mn) + sum;
                    m_t[idx] = mn;
                }
            if (it == 7) {
                #pragma unroll
                for (int idx = 0; idx < 4; idx++) {
                    #pragma unroll
                    for (int off = 1; off < 4; off <<= 1) {
                        float mo = __shfl_xor_sync(0xffffffffu, m_t[idx], off);
                        float lo = __shfl_xor_sync(0xffffffffu, l_t[idx], off);
                        float mn = fmaxf(m_t[idx], mo);
                        l_t[idx] = l_t[idx] * __expf(m_t[idx] - mn) + lo * __expf(mo - mn);
                        m_t[idx] = mn;
                    }
                }
                if ((lane & 3) == 0) {
                    int g = wn >> 6;
                    #pragma unroll
                    for (int mi = 0; mi < 2; mi++)
                        #pragma unroll
                        for (int half = 0; half < 2; half++) {
                            int row = wm + mi * 16 + half * 8 + (lane >> 2);
                            stm[g * 128 + row] = m_t[mi * 2 + half];
                            stl[g * 128 + row] = l_t[mi * 2 + half];
                        }
                }
                __syncthreads();
                #pragma unroll
                for (int mi = 0; mi < 2; mi++)
                    #pragma unroll
                    for (int half = 0; half < 2; half++) {
                        int idx = mi * 2 + half;
                        int row = wm + mi * 16 + half * 8 + (lane >> 2);
                        float m1 = stm[row], l1 = stl[row];
                        float m2 = stm[128 + row], l2 = stl[128 + row];
                        float mn = fmaxf(m1, m2);
                        float l = l1 * __expf(m1 - mn) + l2 * __expf(m2 - mn);
                        mrow[idx] = mn; invl[idx] = 1.f / l;
                    }
            }
        } else {
            // pass 2: normalize in place
            #pragma unroll
            for (int mi = 0; mi < 2; mi++)
                #pragma unroll
                for (int ni = 0; ni < 8; ni++)
                    #pragma unroll
                    for (int half = 0; half < 2; half++) {
                        int idx = mi * 2 + half;
                        float* a2 = acc + (mi * 8 + ni) * 4 + half * 2;
                        a2[0] = __expf(a2[0] - mrow[idx]) * invl[idx];
                        a2[1] = __expf(a2[1] - mrow[idx]) * invl[idx];
                    }
            // write P fp32 (head-mean consumes it)
            #pragma unroll
            for (int mi = 0; mi < 2; mi++)
                #pragma unroll
                for (int ni = 0; ni < 8; ni++)
                    #pragma unroll
                    for (int half = 0; half < 2; half++) {
                        int row = wm + mi * 16 + half * 8 + (lane >> 2);
                        int n0 = kt * 128 + wn + ni * 8 + (lane & 3) * 2;
                        const float* a2 = acc + (mi * 8 + ni) * 4 + half * 2;
                        float2 o2; o2.x = a2[0]; o2.y = a2[1];
                        *(float2*)(Pz + (long)row * 1024 + n0) = o2;
                    }
            // P @ V: A-fragments from registers, B from V smem
            uint32_t vb = sV0 + s * 2 * VPLANE;
            #pragma unroll
            for (int j = 0; j < 4; j++) {
                uint32_t ah[2][4], al[2][4];
                #pragma unroll
                for (int mi = 0; mi < 2; mi++) {
                    const float* t0 = acc + (mi * 8 + 2 * j) * 4;
                    const float* t1 = acc + (mi * 8 + 2 * j + 1) * 4;
                    #pragma unroll
                    for (int r = 0; r < 2; r++) {
                        bf16 h0, l0, h1, l1;
                        split1(t0[r * 2 + 0], h0, l0);
                        split1(t0[r * 2 + 1], h1, l1);
                        ah[mi][r] = pack_bf2(h0, h1);
                        al[mi][r] = pack_bf2(l0, l1);
                        bf16 g0, m0, g1, m1;
                        split1(t1[r * 2 + 0], g0, m0);
                        split1(t1[r * 2 + 1], g1, m1);
                        ah[mi][2 + r] = pack_bf2(g0, g1);
                        al[mi][2 + r] = pack_bf2(m0, m1);
                    }
                }
                uint32_t bfr[4][4];
                #pragma unroll
                for (int n2 = 0; n2 < 4; n2++)
                    ldsm4(vb + (n2 * 16 + brow) * VPITCH + (wn + j * 16 + bcol) * 2,
                          bfr[n2][0], bfr[n2][1], bfr[n2][2], bfr[n2][3]);
                #pragma unroll
                for (int mi = 0; mi < 2; mi++)
                    #pragma unroll
                    for (int ni = 0; ni < 8; ni++) {
                        mma16816(oac + (mi * 8 + ni) * 4, ah[mi], bfr[ni >> 1] + (ni & 1) * 2);
                        mma16816(oac + (mi * 8 + ni) * 4, al[mi], bfr[ni >> 1] + (ni & 1) * 2);
                    }
                #pragma unroll
                for (int n2 = 0; n2 < 4; n2++)
                    ldsm4(vb + VPLANE + (n2 * 16 + brow) * VPITCH + (wn + j * 16 + bcol) * 2,
                          bfr[n2][0], bfr[n2][1], bfr[n2][2], bfr[n2][3]);
                #pragma unroll
                for (int mi = 0; mi < 2; mi++)
                    #pragma unroll
                    for (int ni = 0; ni < 8; ni++)
                        mma16816(oac + (mi * 8 + ni) * 4, ah[mi], bfr[ni >> 1] + (ni & 1) * 2);
            }
        }
        __syncthreads();
    }

    // ---------------- epilogue: reduce O across n-warp groups, write ctx ----
    float* ored = (float*)smem;   // 128 x 66 fp32, reuses Q area (done with Q)
    const int g = wid >> 2;
    if (g == 0) {
        #pragma unroll
        for (int mi = 0; mi < 2; mi++)
            #pragma unroll
            for (int ni = 0; ni < 8; ni++)
                #pragma unroll
                for (int half = 0; half < 2; half++) {
                    int row = wm + mi * 16 + half * 8 + (lane >> 2);
                    int col = ni * 8 + (lane & 3) * 2;
                    const float* a2 = oac + (mi * 8 + ni) * 4 + half * 2;
                    ored[row * 66 + col]     = a2[0];
                    ored[row * 66 + col + 1] = a2[1];
                }
    }
    __syncthreads();
    if (g == 1) {
        #pragma unroll
        for (int mi = 0; mi < 2; mi++)
            #pragma unroll
            for (int ni = 0; ni < 8; ni++)
                #pragma unroll
                for (int half = 0; half < 2; half++) {
                    int row = wm + mi * 16 + half * 8 + (lane >> 2);
                    int col = ni * 8 + (lane & 3) * 2;
                    const float* a2 = oac + (mi * 8 + ni) * 4 + half * 2;
                    float v0 = ored[row * 66 + col]     + a2[0];
                    float v1 = ored[row * 66 + col + 1] + a2[1];
                    bf16 h0, l0, h1, l1;
                    split1(v0, h0, l0); split1(v1, h1, l1);
                    unsigned short hs[2] = {__bfloat16_as_ushort(h0), __bfloat16_as_ushort(h1)};
                    unsigned short ls[2] = {__bfloat16_as_ushort(l0), __bfloat16_as_ushort(l1)};
                    *(uint32_t*)(Chb + (long)row * 512 + col) = *(uint32_t*)hs;
                    *(uint32_t*)(Clb + (long)row * 512 + col) = *(uint32_t*)ls;
                }
    }
}

// ================= LayerNorm (row=512), optional fp32/hi/lo out =================
__global__ void ln_kernel2(const float* __restrict__ x, const float* __restrict__ x2,
                           const float* __restrict__ w, const float* __restrict__ bb,
                           float* __restrict__ outf, bf16* __restrict__ ohi, bf16* __restrict__ olo)
{
    int row = blockIdx.x;
    int t = threadIdx.x;
    float4 v = ((const float4*)(x + (long)row * 512))[t];
    if (x2) {
        float4 v2 = ((const float4*)(x2 + (long)row * 512))[t];
        v.x += v2.x; v.y += v2.y; v.z += v2.z; v.w += v2.w;
    }
    float s  = v.x + v.y + v.z + v.w;
    float sq = v.x*v.x + v.y*v.y + v.z*v.z + v.w*v.w;
    #pragma unroll
    for (int o = 16; o > 0; o >>= 1) {
        s  += __shfl_xor_sync(0xffffffffu, s,  o);
        sq += __shfl_xor_sync(0xffffffffu, sq, o);
    }
    __shared__ float ss[4], ssq[4];
    int wid = t >> 5, lane = t & 31;
    if (lane == 0) { ss[wid] = s; ssq[wid] = sq; }
    __syncthreads();
    s  = ss[0]  + ss[1]  + ss[2]  + ss[3];
    sq = ssq[0] + ssq[1] + ssq[2] + ssq[3];
    float mu  = s * (1.0f / 512.0f);
    float var = sq * (1.0f / 512.0f) - mu * mu;
    float inv = rsqrtf(var + EPS);
    float4 wv = ((const float4*)w)[t];
    float4 bv = ((const float4*)bb)[t];
    float o4[4];
    o4[0] = (v.x - mu) * inv * wv.x + bv.x;
    o4[1] = (v.y - mu) * inv * wv.y + bv.y;
    o4[2] = (v.z - mu) * inv * wv.z + bv.z;
    o4[3] = (v.w - mu) * inv * wv.w + bv.w;
    long base = (long)row * 512 + t * 4;
    if (outf) *(float4*)(outf + base) = *(float4*)o4;
    if (ohi) {
        unsigned short hs[4], ls[4];
        #pragma unroll
        for (int j = 0; j < 4; j++) {
            bf16 h, l; split1(o4[j], h, l);
            hs[j] = __bfloat16_as_ushort(h);
            ls[j] = __bfloat16_as_ushort(l);
        }
        *(uint2*)(ohi + base) = *(uint2*)hs;
        *(uint2*)(olo + base) = *(uint2*)ls;
    }
}

// ================= split fp32 -> bf16 hi/lo =================
__global__ void split_kernel(const float* __restrict__ x, bf16* __restrict__ hi,
                             bf16* __restrict__ lo)
{
    long i = ((long)blockIdx.x * 256 + threadIdx.x) * 4;
    float4 v = *(const float4*)(x + i);
    float a[4] = {v.x, v.y, v.z, v.w};
    unsigned short hs[4], ls[4];
    #pragma unroll
    for (int j = 0; j < 4; j++) {
        bf16 h, l; split1(a[j], h, l);
        hs[j] = __bfloat16_as_ushort(h);
        ls[j] = __bfloat16_as_ushort(l);
    }
    *(uint2*)(hi + i) = *(uint2*)hs;
    *(uint2*)(lo + i) = *(uint2*)ls;
}

// split K half of kv [8192][1024] (cols 0..511) -> k_hi/k_lo [8192][512]
__global__ void split_k_kernel(const float* __restrict__ kv, bf16* __restrict__ hi,
                               bf16* __restrict__ lo)
{
    long i = ((long)blockIdx.x * 256 + threadIdx.x) * 4;
    long r = i >> 9, c = i & 511;
    float4 v = *(const float4*)(kv + r * 1024 + c);
    float a[4] = {v.x, v.y, v.z, v.w};
    unsigned short hs[4], ls[4];
    #pragma unroll
    for (int j = 0; j < 4; j++) {
        bf16 h, l; split1(a[j], h, l);
        hs[j] = __bfloat16_as_ushort(h);
        ls[j] = __bfloat16_as_ushort(l);
    }
    *(uint2*)(hi + i) = *(uint2*)hs;
    *(uint2*)(lo + i) = *(uint2*)ls;
}

// transpose V half of kv: vt[b][n][s] = kv[b][s][512+n], split to hi/lo
__global__ void transpose_v_kernel(const float* __restrict__ kv,
                                   bf16* __restrict__ vhi, bf16* __restrict__ vlo)
{
    __shared__ float t[32][33];
    int b = blockIdx.z;
    int s0 = blockIdx.x * 32, n0 = blockIdx.y * 32;
    int tx = threadIdx.x, ty = threadIdx.y;
    #pragma unroll
    for (int i = 0; i < 4; i++) {
        int s = s0 + ty + i * 8;
        t[ty + i * 8][tx] = kv[((long)b * 1024 + s) * 1024 + 512 + n0 + tx];
    }
    __syncthreads();
    #pragma unroll
    for (int i = 0; i < 4; i++) {
        int n = n0 + ty + i * 8;
        float v = t[tx][ty + i * 8];
        bf16 h, l; split1(v, h, l);
        long o = (long)b * 512 * 1024 + (long)n * 1024 + s0 + tx;
        vhi[o] = h; vlo[o] = l;
    }
}

// ================= attn_weights = mean over H (fp32 P) =================
__global__ void mean_headsf(const float* __restrict__ P, float* __restrict__ out)
{
    long i = ((long)blockIdx.x * 256 + threadIdx.x) * 4;
    long b = i >> 20;
    long rem = i & 1048575;
    const float* p = P + (b << 23) + rem;
    float4 s = {0.f, 0.f, 0.f, 0.f};
    #pragma unroll
    for (int h = 0; h < 8; h++) {
        float4 v = *(const float4*)(p + ((long)h << 20));
        s.x += v.x; s.y += v.y; s.z += v.z; s.w += v.w;
    }
    s.x *= 0.125f; s.y *= 0.125f; s.z *= 0.125f; s.w *= 0.125f;
    *(float4*)(out + i) = s;
}

// ================= launch =================
extern "C" void kernel_launch(void* const* d_in, const int* in_sizes, int n_in,
                              void* d_out, int out_size)
{
    (void)in_sizes; (void)n_in; (void)out_size;
    const float* Zab   = (const float*)d_in[0];
    const float* Za    = (const float*)d_in[1];
    const float* ln_w  = (const float*)d_in[2];
    const float* ln_b  = (const float*)d_in[3];
    const float* in_w  = (const float*)d_in[4];
    const float* in_b  = (const float*)d_in[5];
    const float* out_w = (const float*)d_in[6];
    const float* out_b = (const float*)d_in[7];
    const float* ff_w  = (const float*)d_in[8];
    const float* ff_b  = (const float*)d_in[9];

    float* out_final = (float*)d_out;
    float* out_attnw = (float*)d_out + 8192L * 512;

    bf16 *qin_hi, *qin_lo, *kvin_hi, *kvin_lo, *inw_hi, *inw_lo;
    bf16 *outw_hi, *outw_lo, *ffw_hi, *ffw_lo, *q_hi, *q_lo;
    bf16 *k_hi, *k_lo, *vt_hi, *vt_lo, *ctx_hi, *ctx_lo, *xn_hi, *xn_lo;
    float *kv, *p, *x, *xn, *ff;
    cudaGetSymbolAddress((void**)&qin_hi,  g_qin_hi);
    cudaGetSymbolAddress((void**)&qin_lo,  g_qin_lo);
    cudaGetSymbolAddress((void**)&kvin_hi, g_kvin_hi);
    cudaGetSymbolAddress((void**)&kvin_lo, g_kvin_lo);
    cudaGetSymbolAddress((void**)&inw_hi,  g_inw_hi);
    cudaGetSymbolAddress((void**)&inw_lo,  g_inw_lo);
    cudaGetSymbolAddress((void**)&outw_hi, g_outw_hi);
    cudaGetSymbolAddress((void**)&outw_lo, g_outw_lo);
    cudaGetSymbolAddress((void**)&ffw_hi,  g_ffw_hi);
    cudaGetSymbolAddress((void**)&ffw_lo,  g_ffw_lo);
    cudaGetSymbolAddress((void**)&q_hi,    g_q_hi);
    cudaGetSymbolAddress((void**)&q_lo,    g_q_lo);
    cudaGetSymbolAddress((void**)&k_hi,    g_k_hi);
    cudaGetSymbolAddress((void**)&k_lo,    g_k_lo);
    cudaGetSymbolAddress((void**)&vt_hi,   g_vt_hi);
    cudaGetSymbolAddress((void**)&vt_lo,   g_vt_lo);
    cudaGetSymbolAddress((void**)&ctx_hi,  g_ctx_hi);
    cudaGetSymbolAddress((void**)&ctx_lo,  g_ctx_lo);
    cudaGetSymbolAddress((void**)&xn_hi,   g_xn_hi);
    cudaGetSymbolAddress((void**)&xn_lo,   g_xn_lo);
    cudaGetSymbolAddress((void**)&kv, g_kv);
    cudaGetSymbolAddress((void**)&p,  g_p);
    cudaGetSymbolAddress((void**)&x,  g_x);
    cudaGetSymbolAddress((void**)&xn, g_xn);
    cudaGetSymbolAddress((void**)&ff, g_ff);

    const int SMEM_PI  = 2 * (2 * 128 * 80 + 2 * 128 * 80);           // 81920
    const int SMEM_ATT = 6 * 128 * 144 + 4 * 64 * 272 + 2048;         // 182272
    cudaFuncSetAttribute((const void*)gemm_pi<128>,
                         cudaFuncAttributeMaxDynamicSharedMemorySize, SMEM_PI);
    cudaFuncSetAttribute((const void*)attn_fused_pv,
                         cudaFuncAttributeMaxDynamicSharedMemorySize, SMEM_ATT);

    // 1) LN of inputs -> bf16 hi/lo
    ln_kernel2<<<8192, 128>>>(Zab, nullptr, ln_w, ln_b, nullptr, qin_hi, qin_lo);
    ln_kernel2<<<8192, 128>>>(Za,  nullptr, ln_w, ln_b, nullptr, kvin_hi, kvin_lo);

    // 2) split weights
    split_kernel<<<768, 256>>>(in_w,  inw_hi,  inw_lo);
    split_kernel<<<256, 256>>>(out_w, outw_hi, outw_lo);
    split_kernel<<<256, 256>>>(ff_w,  ffw_hi,  ffw_lo);

    // 3) q = 0.125*(qin @ Wq^T + bq)  -> bf16 hi/lo
    gemm_pi<128><<<dim3(4, 64, 1), 256, SMEM_PI>>>(
        qin_hi, qin_lo, 512, 0, 0,
        inw_hi, inw_lo, 512, 0, 0,
        nullptr, q_hi, q_lo, 512, 0, 0,
        512, 1, 0.125f, in_b, nullptr);

    // 4) kv = kvin @ [Wk;Wv]^T + [bk;bv]  -> fp32
    gemm_pi<128><<<dim3(8, 64, 1), 256, SMEM_PI>>>(
        kvin_hi, kvin_lo, 512, 0, 0,
        inw_hi + 512L * 512, inw_lo + 512L * 512, 512, 0, 0,
        kv, nullptr, nullptr, 1024, 0, 0,
        512, 1, 1.0f, in_b + 512, nullptr);

    // 5) k -> hi/lo ; V -> transposed hi/lo
    split_k_kernel<<<4096, 256>>>(kv, k_hi, k_lo);
    transpose_v_kernel<<<dim3(32, 16, 8), dim3(32, 8)>>>(kv, vt_hi, vt_lo);

    // 6) fused scores + softmax + P@V -> P fp32, ctx hi/lo
    attn_fused_pv<<<dim3(8, 1, 64), 256, SMEM_ATT>>>(
        q_hi, q_lo, k_hi, k_lo, vt_hi, vt_lo, p, ctx_hi, ctx_lo);

    // 7) attn_weights = mean over heads
    mean_headsf<<<8192, 256>>>(p, out_attnw);

    // 8) x = ctx @ Wo^T + bo + Zab
    gemm_pi<128><<<dim3(4, 64, 1), 256, SMEM_PI>>>(
        ctx_hi, ctx_lo, 512, 0, 0,
        outw_hi, outw_lo, 512, 0, 0,
        x, nullptr, nullptr, 512, 0, 0,
        512, 1, 1.0f, out_b, Zab);

    // 9) x_n = LN(x)
    ln_kernel2<<<8192, 128>>>(x, nullptr, ln_w, ln_b, xn, xn_hi, xn_lo);

    // 10) ff = x_n @ ff_w^T + ff_b
    gemm_pi<128><<<dim3(4, 64, 1), 256, SMEM_PI>>>(
        xn_hi, xn_lo, 512, 0, 0,
        ffw_hi, ffw_lo, 512, 0, 0,
        ff, nullptr, nullptr, 512, 0, 0,
        512, 1, 1.0f, ff_b, nullptr);

    // 11) final = LN(x_n + ff) -> d_out
    ln_kernel2<<<8192, 128>>>(xn, ff, ln_w, ln_b, out_final, nullptr, nullptr);
}

// round 7
// speedup vs baseline: 2.9580x; 1.1226x over previous
#include <cuda_runtime.h>
#include <cuda_bf16.h>
#include <cstdint>

#define EPS 1e-5f
typedef __nv_bfloat16 bf16;

// ================= scratch (no allocation allowed) =================
__device__ bf16  g_qin_hi [8192L * 512];
__device__ bf16  g_qin_lo [8192L * 512];
__device__ bf16  g_kvin_hi[8192L * 512];
__device__ bf16  g_kvin_lo[8192L * 512];
__device__ bf16  g_inw_hi [1536L * 512];
__device__ bf16  g_inw_lo [1536L * 512];
__device__ bf16  g_outw_hi[512L * 512];
__device__ bf16  g_outw_lo[512L * 512];
__device__ bf16  g_ffw_hi [512L * 512];
__device__ bf16  g_ffw_lo [512L * 512];
__device__ bf16  g_q_hi   [8192L * 512];
__device__ bf16  g_q_lo   [8192L * 512];
__device__ float g_v      [8192L * 512];
__device__ bf16  g_k_hi   [8192L * 512];
__device__ bf16  g_k_lo   [8192L * 512];
__device__ bf16  g_vt_hi  [8L * 512 * 1024];
__device__ bf16  g_vt_lo  [8L * 512 * 1024];
__device__ float g_p      [64LL * 1024 * 1024];   // unnormalized exp, 256 MB
__device__ float g_m      [64L * 8 * 1024];       // m used per (z, tile, qrow)
__device__ float2 g_ml    [64L * 1024];           // final (m, l) per (z, qrow)
__device__ float g_c      [64L * 8 * 1024];       // corr = exp(m_used-m)/l
__device__ bf16  g_ctx_hi [8192L * 512];
__device__ bf16  g_ctx_lo [8192L * 512];
__device__ float g_x      [8192L * 512];
__device__ float g_xn     [8192L * 512];
__device__ bf16  g_xn_hi  [8192L * 512];
__device__ bf16  g_xn_lo  [8192L * 512];
__device__ float g_ff     [8192L * 512];

// ================= helpers =================
__device__ __forceinline__ uint32_t smem_u32(const void* p){
    uint32_t a;
    asm("{ .reg .u64 t; cvta.to.shared.u64 t, %1; cvt.u32.u64 %0, t; }" : "=r"(a) : "l"(p));
    return a;
}
#define CP_ASYNC16(dst, src) \
    asm volatile("cp.async.cg.shared.global [%0], [%1], 16;" :: "r"(dst), "l"(src))
#define CP_COMMIT() asm volatile("cp.async.commit_group;" ::: "memory")
#define CP_WAIT(n)  asm volatile("cp.async.wait_group %0;" :: "n"(n) : "memory")

__device__ __forceinline__ void ldsm4(uint32_t addr, uint32_t& r0, uint32_t& r1,
                                      uint32_t& r2, uint32_t& r3){
    asm volatile("ldmatrix.sync.aligned.m8n8.x4.shared.b16 {%0,%1,%2,%3}, [%4];"
                 : "=r"(r0), "=r"(r1), "=r"(r2), "=r"(r3) : "r"(addr));
}
__device__ __forceinline__ void mma16816(float* d, const uint32_t* a, const uint32_t* b){
    asm volatile("mma.sync.aligned.m16n8k16.row.col.f32.bf16.bf16.f32 "
                 "{%0,%1,%2,%3},{%4,%5,%6,%7},{%8,%9},{%0,%1,%2,%3};"
                 : "+f"(d[0]), "+f"(d[1]), "+f"(d[2]), "+f"(d[3])
                 : "r"(a[0]), "r"(a[1]), "r"(a[2]), "r"(a[3]), "r"(b[0]), "r"(b[1]));
}
__device__ __forceinline__ void split1(float v, bf16& h, bf16& l){
    h = __float2bfloat16_rn(v);
    l = __float2bfloat16_rn(v - __bfloat162float(h));
}
__device__ __forceinline__ uint32_t pack_bf2(bf16 a, bf16 b){
    return (uint32_t)__bfloat16_as_ushort(a) | ((uint32_t)__bfloat16_as_ushort(b) << 16);
}

// ================= phase-inner HMMA split-bf16 GEMM =================
template<int NT>
__global__ void __launch_bounds__(256)
gemm_pi(const bf16* __restrict__ Ahi, const bf16* __restrict__ Alo,
        long lda, long sAb, long sAh,
        const bf16* __restrict__ Bhi, const bf16* __restrict__ Blo,
        long ldb, long sBb, long sBh,
        float* __restrict__ C, bf16* __restrict__ Chi, bf16* __restrict__ Clo,
        long ldc, long sCb, long sCh,
        int K, int Hn, float scale,
        const float* __restrict__ bias, const float* __restrict__ resid)
{
    constexpr int WN  = (NT == 128) ? 64 : 32;
    constexpr int NI  = WN / 8;
    constexpr int NI2 = NI / 2;
    constexpr int ROWB = 80;
    constexpr int ASZ = 128 * ROWB;
    constexpr int BSZ = NT * ROWB;
    constexpr int STAGE = 2 * ASZ + 2 * BSZ;
    constexpr int NB = (NT * 4) / 256;

    extern __shared__ char smem[];
    const int tid = threadIdx.x, wid = tid >> 5, lane = tid & 31;
    const int wm = (wid & 3) * 32, wn = (wid >> 2) * WN;

    int z = blockIdx.z;
    int b_ = z / Hn, h_ = z % Hn;
    long bm = (long)blockIdx.y * 128;
    long bn = (long)blockIdx.x * NT;
    const bf16* Ah = Ahi + (long)b_*sAb + (long)h_*sAh + bm*lda;
    const bf16* Al = Alo + (long)b_*sAb + (long)h_*sAh + bm*lda;
    const bf16* Bh = Bhi + (long)b_*sBb + (long)h_*sBh + bn*ldb;
    const bf16* Bl = Blo + (long)b_*sBb + (long)h_*sBh + bn*ldb;
    long cbase = (long)b_*sCb + (long)h_*sCh;

    const uint32_t sb = smem_u32(smem);

    auto loadc = [&](int kc, int s){
        long k0 = (long)kc * 32;
        uint32_t base = sb + s * STAGE;
        #pragma unroll
        for (int i = 0; i < 2; i++) {
            int id = tid + i * 256; int r = id >> 2, c = id & 3;
            CP_ASYNC16(base + r * ROWB + c * 16,       Ah + (long)r * lda + k0 + c * 8);
            CP_ASYNC16(base + ASZ + r * ROWB + c * 16, Al + (long)r * lda + k0 + c * 8);
        }
        #pragma unroll
        for (int i = 0; i < NB; i++) {
            int id = tid + i * 256; int r = id >> 2, c = id & 3;
            CP_ASYNC16(base + 2*ASZ + r * ROWB + c * 16,       Bh + (long)r * ldb + k0 + c * 8);
            CP_ASYNC16(base + 2*ASZ + BSZ + r * ROWB + c * 16, Bl + (long)r * ldb + k0 + c * 8);
        }
        CP_COMMIT();
    };

    float acc[2 * NI * 4];
    #pragma unroll
    for (int i = 0; i < 2 * NI * 4; i++) acc[i] = 0.f;

    const int arow = (lane & 7) + ((lane & 8)  ? 8 : 0);
    const int acol = (lane & 16) ? 8 : 0;
    const int brow = (lane & 7) + ((lane & 16) ? 8 : 0);
    const int bcol = (lane & 8) ? 8 : 0;

    const int KC = K >> 5;
    loadc(0, 0);

    for (int kc = 0; kc < KC; kc++) {
        int s = kc & 1;
        if (kc + 1 < KC) { loadc(kc + 1, s ^ 1); CP_WAIT(1); }
        else             { CP_WAIT(0); }
        __syncthreads();

        uint32_t base = sb + s * STAGE;
        #pragma unroll
        for (int ph = 0; ph < 3; ph++) {
            uint32_t abuf = base + ((ph == 1) ? ASZ : 0);
            uint32_t bbuf = base + 2*ASZ + ((ph == 2) ? BSZ : 0);
            #pragma unroll
            for (int k16 = 0; k16 < 2; k16++) {
                uint32_t af[2][4];
                #pragma unroll
                for (int mi = 0; mi < 2; mi++)
                    ldsm4(abuf + (wm + mi * 16 + arow) * ROWB + (k16 * 16 + acol) * 2,
                          af[mi][0], af[mi][1], af[mi][2], af[mi][3]);
                uint32_t bfr[NI2][4];
                #pragma unroll
                for (int n2 = 0; n2 < NI2; n2++)
                    ldsm4(bbuf + (wn + n2 * 16 + brow) * ROWB + (k16 * 16 + bcol) * 2,
                          bfr[n2][0], bfr[n2][1], bfr[n2][2], bfr[n2][3]);
                #pragma unroll
                for (int mi = 0; mi < 2; mi++)
                    #pragma unroll
                    for (int ni = 0; ni < NI; ni++)
                        mma16816(acc + (mi * NI + ni) * 4, af[mi], bfr[ni >> 1] + (ni & 1) * 2);
            }
        }
        __syncthreads();
    }

    #pragma unroll
    for (int mi = 0; mi < 2; mi++) {
        #pragma unroll
        for (int ni = 0; ni < NI; ni++) {
            const float* a4 = acc + (mi * NI + ni) * 4;
            int n0 = (int)bn + wn + ni * 8 + (lane & 3) * 2;
            #pragma unroll
            for (int half = 0; half < 2; half++) {
                long m = bm + wm + mi * 16 + (lane >> 2) + half * 8;
                float v0 = a4[half * 2 + 0];
                float v1 = a4[half * 2 + 1];
                if (bias) { v0 += bias[n0]; v1 += bias[n0 + 1]; }
                v0 *= scale; v1 *= scale;
                if (resid) {
                    float2 rr = *(const float2*)(resid + cbase + m * ldc + n0);
                    v0 += rr.x; v1 += rr.y;
                }
                if (C) {
                    float2 o; o.x = v0; o.y = v1;
                    *(float2*)(C + cbase + m * ldc + n0) = o;
                }
                if (Chi) {
                    bf16 h0, l0, h1, l1;
                    split1(v0, h0, l0); split1(v1, h1, l1);
                    unsigned short hs[2] = {__bfloat16_as_ushort(h0), __bfloat16_as_ushort(h1)};
                    unsigned short ls[2] = {__bfloat16_as_ushort(l0), __bfloat16_as_ushort(l1)};
                    *(uint32_t*)(Chi + cbase + m * ldc + n0) = *(uint32_t*)hs;
                    *(uint32_t*)(Clo + cbase + m * ldc + n0) = *(uint32_t*)ls;
                }
            }
        }
    }
}

// ================= single-pass flash attention =================
// CTA: 128 q rows x one (b,h). Q resident, K/V streamed once.
// Per tile: S=QK (3 phases), CTA-wide row max, rescale O accumulator,
// P''=exp(s-m) written unnormalized to global + fed to PV MMA (3 phases).
// m_used per (tile,row) and final (m,l) per row are written for the
// correction kernel. Epilogue: O/l across the 2 n-warp groups -> ctx hi/lo.
__global__ void __launch_bounds__(256)
attn_flash(const bf16* __restrict__ qhi, const bf16* __restrict__ qlo,
           const bf16* __restrict__ khi, const bf16* __restrict__ klo,
           const bf16* __restrict__ vhi, const bf16* __restrict__ vlo,
           float* __restrict__ P, float* __restrict__ Mbuf,
           float2* __restrict__ MLbuf,
           bf16* __restrict__ ctxhi, bf16* __restrict__ ctxlo)
{
    constexpr int PITCH  = 144;
    constexpr int PLANE  = 128 * PITCH;
    constexpr int VPITCH = 272;
    constexpr int VPLANE = 64 * VPITCH;
    extern __shared__ char smem[];
    const uint32_t sb  = smem_u32(smem);
    const uint32_t sQH = sb;
    const uint32_t sQL = sb + PLANE;
    const uint32_t sK0 = sb + 2 * PLANE;
    const uint32_t sV0 = sb + 6 * PLANE;
    float* stm = (float*)(smem + 6 * PLANE + 4 * VPLANE);        // [2][128]
    float* stl = (float*)(smem + 6 * PLANE + 4 * VPLANE + 1024);

    const int tid = threadIdx.x, wid = tid >> 5, lane = tid & 31;
    const int wm = (wid & 3) * 32, wn = (wid >> 2) * 64;
    const int g = wid >> 2;
    const int z = blockIdx.z, b_ = z >> 3, h_ = z & 7;
    const long qrow0 = (long)b_ * 1024 + blockIdx.x * 128;
    const bf16* Qh = qhi + qrow0 * 512 + h_ * 64;
    const bf16* Ql = qlo + qrow0 * 512 + h_ * 64;
    const bf16* Kh = khi + (long)b_ * 1024 * 512 + h_ * 64;
    const bf16* Kl = klo + (long)b_ * 1024 * 512 + h_ * 64;
    const bf16* Vh = vhi + (long)b_ * 512 * 1024 + (long)h_ * 64 * 1024;
    const bf16* Vl = vlo + (long)b_ * 512 * 1024 + (long)h_ * 64 * 1024;
    float* Pz = P + ((long)z << 20) + (long)blockIdx.x * 128 * 1024;
    bf16* Chb = ctxhi + qrow0 * 512 + h_ * 64;
    bf16* Clb = ctxlo + qrow0 * 512 + h_ * 64;

    #pragma unroll
    for (int i = 0; i < 4; i++) {
        int id = tid + i * 256; int r = id >> 3, c = id & 7;
        CP_ASYNC16(sQH + r * PITCH + c * 16, Qh + (long)r * 512 + c * 8);
        CP_ASYNC16(sQL + r * PITCH + c * 16, Ql + (long)r * 512 + c * 8);
    }
    auto loadK = [&](int kt, int s){
        uint32_t dh = sK0 + s * 2 * PLANE, dl = dh + PLANE;
        const bf16* sh = Kh + (long)kt * 128 * 512;
        const bf16* sl = Kl + (long)kt * 128 * 512;
        #pragma unroll
        for (int i = 0; i < 4; i++) {
            int id = tid + i * 256; int r = id >> 3, c = id & 7;
            CP_ASYNC16(dh + r * PITCH + c * 16, sh + (long)r * 512 + c * 8);
            CP_ASYNC16(dl + r * PITCH + c * 16, sl + (long)r * 512 + c * 8);
        }
    };
    auto loadV = [&](int kt, int s){
        uint32_t dh = sV0 + s * 2 * VPLANE, dl = dh + VPLANE;
        const bf16* sh = Vh + (long)kt * 128;
        const bf16* sl = Vl + (long)kt * 128;
        #pragma unroll
        for (int i = 0; i < 4; i++) {
            int id = tid + i * 256; int r = id >> 4, c = id & 15;
            CP_ASYNC16(dh + r * VPITCH + c * 16, sh + (long)r * 1024 + c * 8);
            CP_ASYNC16(dl + r * VPITCH + c * 16, sl + (long)r * 1024 + c * 8);
        }
    };
    loadK(0, 0); loadV(0, 0);
    CP_COMMIT();

    const int arow = (lane & 7) + ((lane & 8)  ? 8 : 0);
    const int acol = (lane & 16) ? 8 : 0;
    const int brow = (lane & 7) + ((lane & 16) ? 8 : 0);
    const int bcol = (lane & 8) ? 8 : 0;

    float m_t[4], l_t[4];
    #pragma unroll
    for (int i = 0; i < 4; i++) { m_t[i] = -1e30f; l_t[i] = 0.f; }

    float oac[64];
    #pragma unroll
    for (int i = 0; i < 64; i++) oac[i] = 0.f;

    float acc[64];

    for (int t = 0; t < 8; t++) {
        int s = t & 1;
        if (t + 1 < 8) {
            loadK(t + 1, s ^ 1); loadV(t + 1, s ^ 1);
            CP_COMMIT(); CP_WAIT(1);
        } else {
            CP_WAIT(0);
        }
        __syncthreads();

        // S = Q K^T (3 phases)
        #pragma unroll
        for (int i = 0; i < 64; i++) acc[i] = 0.f;
        uint32_t kbase = sK0 + s * 2 * PLANE;
        #pragma unroll
        for (int ph = 0; ph < 3; ph++) {
            uint32_t abuf = (ph == 1) ? sQL : sQH;
            uint32_t bbuf = kbase + ((ph == 2) ? PLANE : 0);
            #pragma unroll
            for (int k16 = 0; k16 < 4; k16++) {
                uint32_t af[2][4];
                #pragma unroll
                for (int mi = 0; mi < 2; mi++)
                    ldsm4(abuf + (wm + mi * 16 + arow) * PITCH + (k16 * 16 + acol) * 2,
                          af[mi][0], af[mi][1], af[mi][2], af[mi][3]);
                uint32_t bfr[4][4];
                #pragma unroll
                for (int n2 = 0; n2 < 4; n2++)
                    ldsm4(bbuf + (wn + n2 * 16 + brow) * PITCH + (k16 * 16 + bcol) * 2,
                          bfr[n2][0], bfr[n2][1], bfr[n2][2], bfr[n2][3]);
                #pragma unroll
                for (int mi = 0; mi < 2; mi++)
                    #pragma unroll
                    for (int ni = 0; ni < 8; ni++)
                        mma16816(acc + (mi * 8 + ni) * 4, af[mi], bfr[ni >> 1] + (ni & 1) * 2);
            }
        }

        // CTA-wide row max of this tile
        float tmax[4];
        #pragma unroll
        for (int mi = 0; mi < 2; mi++)
            #pragma unroll
            for (int half = 0; half < 2; half++) {
                int idx = mi * 2 + half;
                float vm = -1e30f;
                #pragma unroll
                for (int ni = 0; ni < 8; ni++) {
                    const float* a2 = acc + (mi * 8 + ni) * 4 + half * 2;
                    vm = fmaxf(vm, fmaxf(a2[0], a2[1]));
                }
                vm = fmaxf(vm, __shfl_xor_sync(0xffffffffu, vm, 1));
                vm = fmaxf(vm, __shfl_xor_sync(0xffffffffu, vm, 2));
                tmax[idx] = vm;
            }
        if ((lane & 3) == 0) {
            #pragma unroll
            for (int mi = 0; mi < 2; mi++)
                #pragma unroll
                for (int half = 0; half < 2; half++) {
                    int row = wm + mi * 16 + half * 8 + (lane >> 2);
                    stm[g * 128 + row] = tmax[mi * 2 + half];
                }
        }
        __syncthreads();

        float alpha[4], mnew[4];
        #pragma unroll
        for (int mi = 0; mi < 2; mi++)
            #pragma unroll
            for (int half = 0; half < 2; half++) {
                int idx = mi * 2 + half;
                int row = wm + mi * 16 + half * 8 + (lane >> 2);
                float tm = fmaxf(stm[row], stm[128 + row]);
                float mn = fmaxf(m_t[idx], tm);
                alpha[idx] = __expf(m_t[idx] - mn);
                mnew[idx] = mn;
                m_t[idx] = mn;
            }
        // record m used for this tile (one writer per row)
        if (g == 0 && (lane & 3) == 0) {
            #pragma unroll
            for (int mi = 0; mi < 2; mi++)
                #pragma unroll
                for (int half = 0; half < 2; half++) {
                    int row = wm + mi * 16 + half * 8 + (lane >> 2);
                    Mbuf[(((long)z * 8 + t) << 10) + blockIdx.x * 128 + row] = mnew[mi * 2 + half];
                }
        }

        // rescale O accumulator and l
        #pragma unroll
        for (int mi = 0; mi < 2; mi++)
            #pragma unroll
            for (int ni = 0; ni < 8; ni++)
                #pragma unroll
                for (int half = 0; half < 2; half++) {
                    float* o2 = oac + (mi * 8 + ni) * 4 + half * 2;
                    float a = alpha[mi * 2 + half];
                    o2[0] *= a; o2[1] *= a;
                }

        // P'' = exp(s - m), accumulate l, write P'' to global
        #pragma unroll
        for (int mi = 0; mi < 2; mi++)
            #pragma unroll
            for (int half = 0; half < 2; half++) {
                int idx = mi * 2 + half;
                float sum = 0.f;
                #pragma unroll
                for (int ni = 0; ni < 8; ni++) {
                    float* a2 = acc + (mi * 8 + ni) * 4 + half * 2;
                    a2[0] = __expf(a2[0] - mnew[idx]);
                    a2[1] = __expf(a2[1] - mnew[idx]);
                    sum += a2[0] + a2[1];
                }
                l_t[idx] = l_t[idx] * alpha[idx] + sum;
            }
        #pragma unroll
        for (int mi = 0; mi < 2; mi++)
            #pragma unroll
            for (int ni = 0; ni < 8; ni++)
                #pragma unroll
                for (int half = 0; half < 2; half++) {
                    int row = wm + mi * 16 + half * 8 + (lane >> 2);
                    int n0 = t * 128 + wn + ni * 8 + (lane & 3) * 2;
                    const float* a2 = acc + (mi * 8 + ni) * 4 + half * 2;
                    float2 o2; o2.x = a2[0]; o2.y = a2[1];
                    *(float2*)(Pz + (long)row * 1024 + n0) = o2;
                }

        // PV: A-fragments from registers, B from V smem (3 phases)
        uint32_t vb = sV0 + s * 2 * VPLANE;
        #pragma unroll
        for (int j = 0; j < 4; j++) {
            uint32_t ah[2][4], al[2][4];
            #pragma unroll
            for (int mi = 0; mi < 2; mi++) {
                const float* t0 = acc + (mi * 8 + 2 * j) * 4;
                const float* t1 = acc + (mi * 8 + 2 * j + 1) * 4;
                #pragma unroll
                for (int r = 0; r < 2; r++) {
                    bf16 h0, l0, h1, l1;
                    split1(t0[r * 2 + 0], h0, l0);
                    split1(t0[r * 2 + 1], h1, l1);
                    ah[mi][r] = pack_bf2(h0, h1);
                    al[mi][r] = pack_bf2(l0, l1);
                    bf16 g0, m0, g1, m1;
                    split1(t1[r * 2 + 0], g0, m0);
                    split1(t1[r * 2 + 1], g1, m1);
                    ah[mi][2 + r] = pack_bf2(g0, g1);
                    al[mi][2 + r] = pack_bf2(m0, m1);
                }
            }
            uint32_t bfr[4][4];
            #pragma unroll
            for (int n2 = 0; n2 < 4; n2++)
                ldsm4(vb + (n2 * 16 + brow) * VPITCH + (wn + j * 16 + bcol) * 2,
                      bfr[n2][0], bfr[n2][1], bfr[n2][2], bfr[n2][3]);
            #pragma unroll
            for (int mi = 0; mi < 2; mi++)
                #pragma unroll
                for (int ni = 0; ni < 8; ni++) {
                    mma16816(oac + (mi * 8 + ni) * 4, ah[mi], bfr[ni >> 1] + (ni & 1) * 2);
                    mma16816(oac + (mi * 8 + ni) * 4, al[mi], bfr[ni >> 1] + (ni & 1) * 2);
                }
            #pragma unroll
            for (int n2 = 0; n2 < 4; n2++)
                ldsm4(vb + VPLANE + (n2 * 16 + brow) * VPITCH + (wn + j * 16 + bcol) * 2,
                      bfr[n2][0], bfr[n2][1], bfr[n2][2], bfr[n2][3]);
            #pragma unroll
            for (int mi = 0; mi < 2; mi++)
                #pragma unroll
                for (int ni = 0; ni < 8; ni++)
                    mma16816(oac + (mi * 8 + ni) * 4, ah[mi], bfr[ni >> 1] + (ni & 1) * 2);
        }
        __syncthreads();
    }

    // merge l across quad + groups
    #pragma unroll
    for (int idx = 0; idx < 4; idx++) {
        l_t[idx] += __shfl_xor_sync(0xffffffffu, l_t[idx], 1);
        l_t[idx] += __shfl_xor_sync(0xffffffffu, l_t[idx], 2);
    }
    if ((lane & 3) == 0) {
        #pragma unroll
        for (int mi = 0; mi < 2; mi++)
            #pragma unroll
            for (int half = 0; half < 2; half++) {
                int row = wm + mi * 16 + half * 8 + (lane >> 2);
                stl[g * 128 + row] = l_t[mi * 2 + half];
            }
    }
    __syncthreads();
    float invl[4];
    #pragma unroll
    for (int mi = 0; mi < 2; mi++)
        #pragma unroll
        for (int half = 0; half < 2; half++) {
            int idx = mi * 2 + half;
            int row = wm + mi * 16 + half * 8 + (lane >> 2);
            float l = stl[row] + stl[128 + row];
            invl[idx] = 1.f / l;
            if (g == 0 && (lane & 3) == 0) {
                float2 ml; ml.x = m_t[idx]; ml.y = l;
                MLbuf[(long)z * 1024 + blockIdx.x * 128 + row] = ml;
            }
        }
    __syncthreads();

    // reduce O across groups, scale by 1/l, write ctx hi/lo
    float* ored = (float*)smem;
    if (g == 0) {
        #pragma unroll
        for (int mi = 0; mi < 2; mi++)
            #pragma unroll
            for (int ni = 0; ni < 8; ni++)
                #pragma unroll
                for (int half = 0; half < 2; half++) {
                    int row = wm + mi * 16 + half * 8 + (lane >> 2);
                    int col = ni * 8 + (lane & 3) * 2;
                    const float* a2 = oac + (mi * 8 + ni) * 4 + half * 2;
                    ored[row * 66 + col]     = a2[0];
                    ored[row * 66 + col + 1] = a2[1];
                }
    }
    __syncthreads();
    if (g == 1) {
        #pragma unroll
        for (int mi = 0; mi < 2; mi++)
            #pragma unroll
            for (int ni = 0; ni < 8; ni++)
                #pragma unroll
                for (int half = 0; half < 2; half++) {
                    int idx = mi * 2 + half;
                    int row = wm + mi * 16 + half * 8 + (lane >> 2);
                    int col = ni * 8 + (lane & 3) * 2;
                    const float* a2 = oac + (mi * 8 + ni) * 4 + half * 2;
                    float v0 = (ored[row * 66 + col]     + a2[0]) * invl[idx];
                    float v1 = (ored[row * 66 + col + 1] + a2[1]) * invl[idx];
                    bf16 h0, l0, h1, l1;
                    split1(v0, h0, l0); split1(v1, h1, l1);
                    unsigned short hs[2] = {__bfloat16_as_ushort(h0), __bfloat16_as_ushort(h1)};
                    unsigned short ls[2] = {__bfloat16_as_ushort(l0), __bfloat16_as_ushort(l1)};
                    *(uint32_t*)(Chb + (long)row * 512 + col) = *(uint32_t*)hs;
                    *(uint32_t*)(Clb + (long)row * 512 + col) = *(uint32_t*)ls;
                }
    }
}

// ================= corr factors: c = exp(m_used - m_fin) / l =================
__global__ void corr_kernel(const float* __restrict__ Mbuf,
                            const float2* __restrict__ MLbuf,
                            float* __restrict__ C)
{
    long i = (long)blockIdx.x * 256 + threadIdx.x;   // over 64*8*1024
    long z = i >> 13, q = i & 1023;
    float2 ml = MLbuf[z * 1024 + q];
    C[i] = __expf(Mbuf[i] - ml.x) / ml.y;
}

// ================= LayerNorm (row=512), optional fp32/hi/lo out =================
__global__ void ln_kernel2(const float* __restrict__ x, const float* __restrict__ x2,
                           const float* __restrict__ w, const float* __restrict__ bb,
                           float* __restrict__ outf, bf16* __restrict__ ohi, bf16* __restrict__ olo)
{
    int row = blockIdx.x;
    int t = threadIdx.x;
    float4 v = ((const float4*)(x + (long)row * 512))[t];
    if (x2) {
        float4 v2 = ((const float4*)(x2 + (long)row * 512))[t];
        v.x += v2.x; v.y += v2.y; v.z += v2.z; v.w += v2.w;
    }
    float s  = v.x + v.y + v.z + v.w;
    float sq = v.x*v.x + v.y*v.y + v.z*v.z + v.w*v.w;
    #pragma unroll
    for (int o = 16; o > 0; o >>= 1) {
        s  += __shfl_xor_sync(0xffffffffu, s,  o);
        sq += __shfl_xor_sync(0xffffffffu, sq, o);
    }
    __shared__ float ss[4], ssq[4];
    int wid = t >> 5, lane = t & 31;
    if (lane == 0) { ss[wid] = s; ssq[wid] = sq; }
    __syncthreads();
    s  = ss[0]  + ss[1]  + ss[2]  + ss[3];
    sq = ssq[0] + ssq[1] + ssq[2] + ssq[3];
    float mu  = s * (1.0f / 512.0f);
    float var = sq * (1.0f / 512.0f) - mu * mu;
    float inv = rsqrtf(var + EPS);
    float4 wv = ((const float4*)w)[t];
    float4 bv = ((const float4*)bb)[t];
    float o4[4];
    o4[0] = (v.x - mu) * inv * wv.x + bv.x;
    o4[1] = (v.y - mu) * inv * wv.y + bv.y;
    o4[2] = (v.z - mu) * inv * wv.z + bv.z;
    o4[3] = (v.w - mu) * inv * wv.w + bv.w;
    long base = (long)row * 512 + t * 4;
    if (outf) *(float4*)(outf + base) = *(float4*)o4;
    if (ohi) {
        unsigned short hs[4], ls[4];
        #pragma unroll
        for (int j = 0; j < 4; j++) {
            bf16 h, l; split1(o4[j], h, l);
            hs[j] = __bfloat16_as_ushort(h);
            ls[j] = __bfloat16_as_ushort(l);
        }
        *(uint2*)(ohi + base) = *(uint2*)hs;
        *(uint2*)(olo + base) = *(uint2*)ls;
    }
}

// ================= split fp32 -> bf16 hi/lo =================
__global__ void split_kernel(const float* __restrict__ x, bf16* __restrict__ hi,
                             bf16* __restrict__ lo)
{
    long i = ((long)blockIdx.x * 256 + threadIdx.x) * 4;
    float4 v = *(const float4*)(x + i);
    float a[4] = {v.x, v.y, v.z, v.w};
    unsigned short hs[4], ls[4];
    #pragma unroll
    for (int j = 0; j < 4; j++) {
        bf16 h, l; split1(a[j], h, l);
        hs[j] = __bfloat16_as_ushort(h);
        ls[j] = __bfloat16_as_ushort(l);
    }
    *(uint2*)(hi + i) = *(uint2*)hs;
    *(uint2*)(lo + i) = *(uint2*)ls;
}

// transpose V: vt[b][n][s] = v[b*1024+s][n], split to hi/lo
__global__ void transpose_v_kernel(const float* __restrict__ v,
                                   bf16* __restrict__ vhi, bf16* __restrict__ vlo)
{
    __shared__ float t[32][33];
    int b = blockIdx.z;
    int s0 = blockIdx.x * 32, n0 = blockIdx.y * 32;
    int tx = threadIdx.x, ty = threadIdx.y;
    #pragma unroll
    for (int i = 0; i < 4; i++) {
        int s = s0 + ty + i * 8;
        t[ty + i * 8][tx] = v[((long)b * 1024 + s) * 512 + n0 + tx];
    }
    __syncthreads();
    #pragma unroll
    for (int i = 0; i < 4; i++) {
        int n = n0 + ty + i * 8;
        float vv = t[tx][ty + i * 8];
        bf16 h, l; split1(vv, h, l);
        long o = (long)b * 512 * 1024 + (long)n * 1024 + s0 + tx;
        vhi[o] = h; vlo[o] = l;
    }
}

// ================= attn_weights = (1/8) sum_h c * P'' =================
__global__ void mean_corr(const float* __restrict__ P, const float* __restrict__ C,
                          float* __restrict__ out)
{
    long i = ((long)blockIdx.x * 256 + threadIdx.x) * 4;   // over 8M
    long b = i >> 20;
    long rem = i & 1048575;
    long q = rem >> 10;
    long k = rem & 1023;
    long t = k >> 7;
    const float* p = P + (b << 23) + rem;
    float4 s = {0.f, 0.f, 0.f, 0.f};
    #pragma unroll
    for (int h = 0; h < 8; h++) {
        long z = b * 8 + h;
        float c = C[((z * 8 + t) << 10) + q];
        float4 v = *(const float4*)(p + ((long)h << 20));
        s.x += c * v.x; s.y += c * v.y; s.z += c * v.z; s.w += c * v.w;
    }
    s.x *= 0.125f; s.y *= 0.125f; s.z *= 0.125f; s.w *= 0.125f;
    *(float4*)(out + i) = s;
}

// ================= launch =================
extern "C" void kernel_launch(void* const* d_in, const int* in_sizes, int n_in,
                              void* d_out, int out_size)
{
    (void)in_sizes; (void)n_in; (void)out_size;
    const float* Zab   = (const float*)d_in[0];
    const float* Za    = (const float*)d_in[1];
    const float* ln_w  = (const float*)d_in[2];
    const float* ln_b  = (const float*)d_in[3];
    const float* in_w  = (const float*)d_in[4];
    const float* in_b  = (const float*)d_in[5];
    const float* out_w = (const float*)d_in[6];
    const float* out_b = (const float*)d_in[7];
    const float* ff_w  = (const float*)d_in[8];
    const float* ff_b  = (const float*)d_in[9];

    float* out_final = (float*)d_out;
    float* out_attnw = (float*)d_out + 8192L * 512;

    bf16 *qin_hi, *qin_lo, *kvin_hi, *kvin_lo, *inw_hi, *inw_lo;
    bf16 *outw_hi, *outw_lo, *ffw_hi, *ffw_lo, *q_hi, *q_lo;
    bf16 *k_hi, *k_lo, *vt_hi, *vt_lo, *ctx_hi, *ctx_lo, *xn_hi, *xn_lo;
    float *v, *p, *x, *xn, *ff, *mb, *cb;
    float2 *mlb;
    cudaGetSymbolAddress((void**)&qin_hi,  g_qin_hi);
    cudaGetSymbolAddress((void**)&qin_lo,  g_qin_lo);
    cudaGetSymbolAddress((void**)&kvin_hi, g_kvin_hi);
    cudaGetSymbolAddress((void**)&kvin_lo, g_kvin_lo);
    cudaGetSymbolAddress((void**)&inw_hi,  g_inw_hi);
    cudaGetSymbolAddress((void**)&inw_lo,  g_inw_lo);
    cudaGetSymbolAddress((void**)&outw_hi, g_outw_hi);
    cudaGetSymbolAddress((void**)&outw_lo, g_outw_lo);
    cudaGetSymbolAddress((void**)&ffw_hi,  g_ffw_hi);
    cudaGetSymbolAddress((void**)&ffw_lo,  g_ffw_lo);
    cudaGetSymbolAddress((void**)&q_hi,    g_q_hi);
    cudaGetSymbolAddress((void**)&q_lo,    g_q_lo);
    cudaGetSymbolAddress((void**)&k_hi,    g_k_hi);
    cudaGetSymbolAddress((void**)&k_lo,    g_k_lo);
    cudaGetSymbolAddress((void**)&vt_hi,   g_vt_hi);
    cudaGetSymbolAddress((void**)&vt_lo,   g_vt_lo);
    cudaGetSymbolAddress((void**)&ctx_hi,  g_ctx_hi);
    cudaGetSymbolAddress((void**)&ctx_lo,  g_ctx_lo);
    cudaGetSymbolAddress((void**)&xn_hi,   g_xn_hi);
    cudaGetSymbolAddress((void**)&xn_lo,   g_xn_lo);
    cudaGetSymbolAddress((void**)&v,   g_v);
    cudaGetSymbolAddress((void**)&p,   g_p);
    cudaGetSymbolAddress((void**)&x,   g_x);
    cudaGetSymbolAddress((void**)&xn,  g_xn);
    cudaGetSymbolAddress((void**)&ff,  g_ff);
    cudaGetSymbolAddress((void**)&mb,  g_m);
    cudaGetSymbolAddress((void**)&mlb, g_ml);
    cudaGetSymbolAddress((void**)&cb,  g_c);

    const int SMEM_PI  = 2 * (2 * 128 * 80 + 2 * 128 * 80);           // 81920
    const int SMEM_ATT = 6 * 128 * 144 + 4 * 64 * 272 + 2048;         // 182272
    cudaFuncSetAttribute((const void*)gemm_pi<128>,
                         cudaFuncAttributeMaxDynamicSharedMemorySize, SMEM_PI);
    cudaFuncSetAttribute((const void*)attn_flash,
                         cudaFuncAttributeMaxDynamicSharedMemorySize, SMEM_ATT);

    // 1) LN of inputs -> bf16 hi/lo
    ln_kernel2<<<8192, 128>>>(Zab, nullptr, ln_w, ln_b, nullptr, qin_hi, qin_lo);
    ln_kernel2<<<8192, 128>>>(Za,  nullptr, ln_w, ln_b, nullptr, kvin_hi, kvin_lo);

    // 2) split weights
    split_kernel<<<768, 256>>>(in_w,  inw_hi,  inw_lo);
    split_kernel<<<256, 256>>>(out_w, outw_hi, outw_lo);
    split_kernel<<<256, 256>>>(ff_w,  ffw_hi,  ffw_lo);

    // 3) q = 0.125*(qin @ Wq^T + bq)  -> bf16 hi/lo
    gemm_pi<128><<<dim3(4, 64, 1), 256, SMEM_PI>>>(
        qin_hi, qin_lo, 512, 0, 0,
        inw_hi, inw_lo, 512, 0, 0,
        nullptr, q_hi, q_lo, 512, 0, 0,
        512, 1, 0.125f, in_b, nullptr);

    // 4a) k = kvin @ Wk^T + bk  -> bf16 hi/lo directly
    gemm_pi<128><<<dim3(4, 64, 1), 256, SMEM_PI>>>(
        kvin_hi, kvin_lo, 512, 0, 0,
        inw_hi + 512L * 512, inw_lo + 512L * 512, 512, 0, 0,
        nullptr, k_hi, k_lo, 512, 0, 0,
        512, 1, 1.0f, in_b + 512, nullptr);
    // 4b) v = kvin @ Wv^T + bv  -> fp32
    gemm_pi<128><<<dim3(4, 64, 1), 256, SMEM_PI>>>(
        kvin_hi, kvin_lo, 512, 0, 0,
        inw_hi + 2 * 512L * 512, inw_lo + 2 * 512L * 512, 512, 0, 0,
        v, nullptr, nullptr, 512, 0, 0,
        512, 1, 1.0f, in_b + 1024, nullptr);

    // 5) V -> transposed hi/lo
    transpose_v_kernel<<<dim3(32, 16, 8), dim3(32, 8)>>>(v, vt_hi, vt_lo);

    // 6) single-pass flash attention -> P'' , m/ml bufs, ctx hi/lo
    attn_flash<<<dim3(8, 1, 64), 256, SMEM_ATT>>>(
        q_hi, q_lo, k_hi, k_lo, vt_hi, vt_lo, p, mb, mlb, ctx_hi, ctx_lo);

    // 7) corr factors, then attn_weights = (1/8) sum_h c * P''
    corr_kernel<<<2048, 256>>>(mb, mlb, cb);
    mean_corr<<<8192, 256>>>(p, cb, out_attnw);

    // 8) x = ctx @ Wo^T + bo + Zab
    gemm_pi<128><<<dim3(4, 64, 1), 256, SMEM_PI>>>(
        ctx_hi, ctx_lo, 512, 0, 0,
        outw_hi, outw_lo, 512, 0, 0,
        x, nullptr, nullptr, 512, 0, 0,
        512, 1, 1.0f, out_b, Zab);

    // 9) x_n = LN(x)
    ln_kernel2<<<8192, 128>>>(x, nullptr, ln_w, ln_b, xn, xn_hi, xn_lo);

    // 10) ff = x_n @ ff_w^T + ff_b
    gemm_pi<128><<<dim3(4, 64, 1), 256, SMEM_PI>>>(
        xn_hi, xn_lo, 512, 0, 0,
        ffw_hi, ffw_lo, 512, 0, 0,
        ff, nullptr, nullptr, 512, 0, 0,
        512, 1, 1.0f, ff_b, nullptr);

    // 11) final = LN(x_n + ff) -> d_out
    ln_kernel2<<<8192, 128>>>(xn, ff, ln_w, ln_b, out_final, nullptr, nullptr);
}

// round 8
// speedup vs baseline: 3.2347x; 1.0935x over previous
#include <cuda_runtime.h>
#include <cuda_bf16.h>
#include <cuda_fp16.h>
#include <cstdint>

#define EPS 1e-5f
typedef __nv_bfloat16 bf16;

// ================= scratch (no allocation allowed) =================
__device__ bf16  g_qin_hi [8192L * 512];
__device__ bf16  g_qin_lo [8192L * 512];
__device__ bf16  g_kvin_hi[8192L * 512];
__device__ bf16  g_kvin_lo[8192L * 512];
__device__ bf16  g_inw_hi [1536L * 512];
__device__ bf16  g_inw_lo [1536L * 512];
__device__ bf16  g_outw_hi[512L * 512];
__device__ bf16  g_outw_lo[512L * 512];
__device__ bf16  g_ffw_hi [512L * 512];
__device__ bf16  g_ffw_lo [512L * 512];
__device__ bf16  g_q_hi   [8192L * 512];
__device__ bf16  g_q_lo   [8192L * 512];
__device__ float g_v      [8192L * 512];
__device__ bf16  g_k_hi   [8192L * 512];
__device__ bf16  g_k_lo   [8192L * 512];
__device__ bf16  g_vt_hi  [8L * 512 * 1024];
__device__ bf16  g_vt_lo  [8L * 512 * 1024];
__device__ __half g_p     [64LL * 1024 * 1024];   // unnormalized exp, fp16, 128 MB
__device__ float g_m      [64L * 8 * 1024];       // m used per (z, tile, qrow)
__device__ float2 g_ml    [64L * 1024];           // final (m, l) per (z, qrow)
__device__ float g_c      [64L * 8 * 1024];       // corr = exp(m_used-m)/l
__device__ bf16  g_ctx_hi [8192L * 512];
__device__ bf16  g_ctx_lo [8192L * 512];
__device__ float g_x      [8192L * 512];
__device__ float g_xn     [8192L * 512];
__device__ bf16  g_xn_hi  [8192L * 512];
__device__ bf16  g_xn_lo  [8192L * 512];
__device__ float g_ff     [8192L * 512];

// ================= helpers =================
__device__ __forceinline__ uint32_t smem_u32(const void* p){
    uint32_t a;
    asm("{ .reg .u64 t; cvta.to.shared.u64 t, %1; cvt.u32.u64 %0, t; }" : "=r"(a) : "l"(p));
    return a;
}
#define CP_ASYNC16(dst, src) \
    asm volatile("cp.async.cg.shared.global [%0], [%1], 16;" :: "r"(dst), "l"(src))
#define CP_COMMIT() asm volatile("cp.async.commit_group;" ::: "memory")
#define CP_WAIT(n)  asm volatile("cp.async.wait_group %0;" :: "n"(n) : "memory")

__device__ __forceinline__ void ldsm4(uint32_t addr, uint32_t& r0, uint32_t& r1,
                                      uint32_t& r2, uint32_t& r3){
    asm volatile("ldmatrix.sync.aligned.m8n8.x4.shared.b16 {%0,%1,%2,%3}, [%4];"
                 : "=r"(r0), "=r"(r1), "=r"(r2), "=r"(r3) : "r"(addr));
}
__device__ __forceinline__ void mma16816(float* d, const uint32_t* a, const uint32_t* b){
    asm volatile("mma.sync.aligned.m16n8k16.row.col.f32.bf16.bf16.f32 "
                 "{%0,%1,%2,%3},{%4,%5,%6,%7},{%8,%9},{%0,%1,%2,%3};"
                 : "+f"(d[0]), "+f"(d[1]), "+f"(d[2]), "+f"(d[3])
                 : "r"(a[0]), "r"(a[1]), "r"(a[2]), "r"(a[3]), "r"(b[0]), "r"(b[1]));
}
__device__ __forceinline__ void split1(float v, bf16& h, bf16& l){
    h = __float2bfloat16_rn(v);
    l = __float2bfloat16_rn(v - __bfloat162float(h));
}
__device__ __forceinline__ uint32_t pack_bf2(bf16 a, bf16 b){
    return (uint32_t)__bfloat16_as_ushort(a) | ((uint32_t)__bfloat16_as_ushort(b) << 16);
}

// ================= shared GEMM mainloop (macro-free via template lambdas) ======
// C = scale * (A @ B^T + bias) (+resid). 128x128 tile, BK=32, 3 MMA phases.
struct GemmOut {
    float* C; bf16 *Chi, *Clo;
    const float* bias; const float* resid;
    float scale;
};

__device__ __forceinline__ void gemm_core(
    const bf16* Ah, const bf16* Al, long lda,
    const bf16* Bh, const bf16* Bl, long ldb,
    int K, char* smem, int tid, float* acc /*2*8*4*/)
{
    constexpr int ROWB = 80;
    constexpr int ASZ = 128 * ROWB;
    constexpr int BSZ = 128 * ROWB;
    constexpr int STAGE = 2 * ASZ + 2 * BSZ;
    const int wid = tid >> 5, lane = tid & 31;
    const int wm = (wid & 3) * 32, wn = (wid >> 2) * 64;
    const uint32_t sb = smem_u32(smem);

    auto loadc = [&](int kc, int s){
        long k0 = (long)kc * 32;
        uint32_t base = sb + s * STAGE;
        #pragma unroll
        for (int i = 0; i < 2; i++) {
            int id = tid + i * 256; int r = id >> 2, c = id & 3;
            CP_ASYNC16(base + r * ROWB + c * 16,       Ah + (long)r * lda + k0 + c * 8);
            CP_ASYNC16(base + ASZ + r * ROWB + c * 16, Al + (long)r * lda + k0 + c * 8);
            CP_ASYNC16(base + 2*ASZ + r * ROWB + c * 16,       Bh + (long)r * ldb + k0 + c * 8);
            CP_ASYNC16(base + 2*ASZ + BSZ + r * ROWB + c * 16, Bl + (long)r * ldb + k0 + c * 8);
        }
        CP_COMMIT();
    };

    const int arow = (lane & 7) + ((lane & 8)  ? 8 : 0);
    const int acol = (lane & 16) ? 8 : 0;
    const int brow = (lane & 7) + ((lane & 16) ? 8 : 0);
    const int bcol = (lane & 8) ? 8 : 0;

    const int KC = K >> 5;
    loadc(0, 0);
    for (int kc = 0; kc < KC; kc++) {
        int s = kc & 1;
        if (kc + 1 < KC) { loadc(kc + 1, s ^ 1); CP_WAIT(1); }
        else             { CP_WAIT(0); }
        __syncthreads();
        uint32_t base = sb + s * STAGE;
        #pragma unroll
        for (int ph = 0; ph < 3; ph++) {
            uint32_t abuf = base + ((ph == 1) ? ASZ : 0);
            uint32_t bbuf = base + 2*ASZ + ((ph == 2) ? BSZ : 0);
            #pragma unroll
            for (int k16 = 0; k16 < 2; k16++) {
                uint32_t af[2][4];
                #pragma unroll
                for (int mi = 0; mi < 2; mi++)
                    ldsm4(abuf + (wm + mi * 16 + arow) * ROWB + (k16 * 16 + acol) * 2,
                          af[mi][0], af[mi][1], af[mi][2], af[mi][3]);
                uint32_t bfr[4][4];
                #pragma unroll
                for (int n2 = 0; n2 < 4; n2++)
                    ldsm4(bbuf + (wn + n2 * 16 + brow) * ROWB + (k16 * 16 + bcol) * 2,
                          bfr[n2][0], bfr[n2][1], bfr[n2][2], bfr[n2][3]);
                #pragma unroll
                for (int mi = 0; mi < 2; mi++)
                    #pragma unroll
                    for (int ni = 0; ni < 8; ni++)
                        mma16816(acc + (mi * 8 + ni) * 4, af[mi], bfr[ni >> 1] + (ni & 1) * 2);
            }
        }
        __syncthreads();
    }
}

__device__ __forceinline__ void gemm_epi(
    const float* acc, long bm, long bn, long ldc, long cbase,
    const GemmOut& o, int tid)
{
    const int wid = tid >> 5, lane = tid & 31;
    const int wm = (wid & 3) * 32, wn = (wid >> 2) * 64;
    #pragma unroll
    for (int mi = 0; mi < 2; mi++) {
        #pragma unroll
        for (int ni = 0; ni < 8; ni++) {
            const float* a4 = acc + (mi * 8 + ni) * 4;
            int n0 = (int)bn + wn + ni * 8 + (lane & 3) * 2;
            #pragma unroll
            for (int half = 0; half < 2; half++) {
                long m = bm + wm + mi * 16 + (lane >> 2) + half * 8;
                float v0 = a4[half * 2 + 0];
                float v1 = a4[half * 2 + 1];
                if (o.bias) { v0 += o.bias[n0]; v1 += o.bias[n0 + 1]; }
                v0 *= o.scale; v1 *= o.scale;
                if (o.resid) {
                    float2 rr = *(const float2*)(o.resid + cbase + m * ldc + n0);
                    v0 += rr.x; v1 += rr.y;
                }
                if (o.C) {
                    float2 ov; ov.x = v0; ov.y = v1;
                    *(float2*)(o.C + cbase + m * ldc + n0) = ov;
                }
                if (o.Chi) {
                    bf16 h0, l0, h1, l1;
                    split1(v0, h0, l0); split1(v1, h1, l1);
                    *(uint32_t*)(o.Chi + cbase + m * ldc + n0) = pack_bf2(h0, h1);
                    *(uint32_t*)(o.Clo + cbase + m * ldc + n0) = pack_bf2(l0, l1);
                }
            }
        }
    }
}

// ================= fused q/k/v projections: grid.z selects which =================
__global__ void __launch_bounds__(256)
proj_qkv(const bf16* __restrict__ qinh, const bf16* __restrict__ qinl,
         const bf16* __restrict__ kvinh, const bf16* __restrict__ kvinl,
         const bf16* __restrict__ inwh, const bf16* __restrict__ inwl,
         const float* __restrict__ in_b,
         bf16* __restrict__ qh, bf16* __restrict__ ql,
         bf16* __restrict__ kh, bf16* __restrict__ kl,
         float* __restrict__ v)
{
    extern __shared__ char smem[];
    const int tid = threadIdx.x;
    const int z = blockIdx.z;
    long bm = (long)blockIdx.y * 128;
    long bn = (long)blockIdx.x * 128;

    const bf16 *Ah, *Al;
    GemmOut o{nullptr, nullptr, nullptr, nullptr, nullptr, 1.0f};
    if (z == 0) { Ah = qinh;  Al = qinl;  o.Chi = qh; o.Clo = ql; o.scale = 0.125f; o.bias = in_b; }
    else if (z == 1) { Ah = kvinh; Al = kvinl; o.Chi = kh; o.Clo = kl; o.bias = in_b + 512; }
    else { Ah = kvinh; Al = kvinl; o.C = v; o.bias = in_b + 1024; }
    const bf16* Bh = inwh + (long)z * 512 * 512 + bn * 512;
    const bf16* Bl = inwl + (long)z * 512 * 512 + bn * 512;

    float acc[64];
    #pragma unroll
    for (int i = 0; i < 64; i++) acc[i] = 0.f;
    gemm_core(Ah + bm * 512, Al + bm * 512, 512, Bh, Bl, 512, 512, smem, tid, acc);
    gemm_epi(acc, bm, bn, 512, 0, o, tid);
}

// ================= generic GEMM (out-proj / ff) =================
__global__ void __launch_bounds__(256)
gemm_pi(const bf16* __restrict__ Ahi, const bf16* __restrict__ Alo,
        const bf16* __restrict__ Bhi, const bf16* __restrict__ Blo,
        float* __restrict__ C, bf16* __restrict__ Chi, bf16* __restrict__ Clo,
        float scale, const float* __restrict__ bias, const float* __restrict__ resid)
{
    extern __shared__ char smem[];
    const int tid = threadIdx.x;
    long bm = (long)blockIdx.y * 128;
    long bn = (long)blockIdx.x * 128;
    float acc[64];
    #pragma unroll
    for (int i = 0; i < 64; i++) acc[i] = 0.f;
    gemm_core(Ahi + bm * 512, Alo + bm * 512, 512,
              Bhi + bn * 512, Blo + bn * 512, 512, 512, smem, tid, acc);
    GemmOut o{C, Chi, Clo, bias, resid, scale};
    gemm_epi(acc, bm, bn, 512, 0, o, tid);
}

// ================= single-pass flash attention (P out as fp16) =================
__global__ void __launch_bounds__(256)
attn_flash(const bf16* __restrict__ qhi, const bf16* __restrict__ qlo,
           const bf16* __restrict__ khi, const bf16* __restrict__ klo,
           const bf16* __restrict__ vhi, const bf16* __restrict__ vlo,
           __half* __restrict__ P, float* __restrict__ Mbuf,
           float2* __restrict__ MLbuf,
           bf16* __restrict__ ctxhi, bf16* __restrict__ ctxlo)
{
    constexpr int PITCH  = 144;
    constexpr int PLANE  = 128 * PITCH;
    constexpr int VPITCH = 272;
    constexpr int VPLANE = 64 * VPITCH;
    extern __shared__ char smem[];
    const uint32_t sb  = smem_u32(smem);
    const uint32_t sQH = sb;
    const uint32_t sQL = sb + PLANE;
    const uint32_t sK0 = sb + 2 * PLANE;
    const uint32_t sV0 = sb + 6 * PLANE;
    float* stm = (float*)(smem + 6 * PLANE + 4 * VPLANE);        // [2][128]
    float* stl = (float*)(smem + 6 * PLANE + 4 * VPLANE + 1024);

    const int tid = threadIdx.x, wid = tid >> 5, lane = tid & 31;
    const int wm = (wid & 3) * 32, wn = (wid >> 2) * 64;
    const int g = wid >> 2;
    const int z = blockIdx.z, b_ = z >> 3, h_ = z & 7;
    const long qrow0 = (long)b_ * 1024 + blockIdx.x * 128;
    const bf16* Qh = qhi + qrow0 * 512 + h_ * 64;
    const bf16* Ql = qlo + qrow0 * 512 + h_ * 64;
    const bf16* Kh = khi + (long)b_ * 1024 * 512 + h_ * 64;
    const bf16* Kl = klo + (long)b_ * 1024 * 512 + h_ * 64;
    const bf16* Vh = vhi + (long)b_ * 512 * 1024 + (long)h_ * 64 * 1024;
    const bf16* Vl = vlo + (long)b_ * 512 * 1024 + (long)h_ * 64 * 1024;
    __half* Pz = P + ((long)z << 20) + (long)blockIdx.x * 128 * 1024;
    bf16* Chb = ctxhi + qrow0 * 512 + h_ * 64;
    bf16* Clb = ctxlo + qrow0 * 512 + h_ * 64;

    #pragma unroll
    for (int i = 0; i < 4; i++) {
        int id = tid + i * 256; int r = id >> 3, c = id & 7;
        CP_ASYNC16(sQH + r * PITCH + c * 16, Qh + (long)r * 512 + c * 8);
        CP_ASYNC16(sQL + r * PITCH + c * 16, Ql + (long)r * 512 + c * 8);
    }
    auto loadK = [&](int kt, int s){
        uint32_t dh = sK0 + s * 2 * PLANE, dl = dh + PLANE;
        const bf16* sh = Kh + (long)kt * 128 * 512;
        const bf16* sl = Kl + (long)kt * 128 * 512;
        #pragma unroll
        for (int i = 0; i < 4; i++) {
            int id = tid + i * 256; int r = id >> 3, c = id & 7;
            CP_ASYNC16(dh + r * PITCH + c * 16, sh + (long)r * 512 + c * 8);
            CP_ASYNC16(dl + r * PITCH + c * 16, sl + (long)r * 512 + c * 8);
        }
    };
    auto loadV = [&](int kt, int s){
        uint32_t dh = sV0 + s * 2 * VPLANE, dl = dh + VPLANE;
        const bf16* sh = Vh + (long)kt * 128;
        const bf16* sl = Vl + (long)kt * 128;
        #pragma unroll
        for (int i = 0; i < 4; i++) {
            int id = tid + i * 256; int r = id >> 4, c = id & 15;
            CP_ASYNC16(dh + r * VPITCH + c * 16, sh + (long)r * 1024 + c * 8);
            CP_ASYNC16(dl + r * VPITCH + c * 16, sl + (long)r * 1024 + c * 8);
        }
    };
    loadK(0, 0); loadV(0, 0);
    CP_COMMIT();

    const int arow = (lane & 7) + ((lane & 8)  ? 8 : 0);
    const int acol = (lane & 16) ? 8 : 0;
    const int brow = (lane & 7) + ((lane & 16) ? 8 : 0);
    const int bcol = (lane & 8) ? 8 : 0;

    float m_t[4], l_t[4];
    #pragma unroll
    for (int i = 0; i < 4; i++) { m_t[i] = -1e30f; l_t[i] = 0.f; }

    float oac[64];
    #pragma unroll
    for (int i = 0; i < 64; i++) oac[i] = 0.f;

    float acc[64];

    for (int t = 0; t < 8; t++) {
        int s = t & 1;
        if (t + 1 < 8) {
            loadK(t + 1, s ^ 1); loadV(t + 1, s ^ 1);
            CP_COMMIT(); CP_WAIT(1);
        } else {
            CP_WAIT(0);
        }
        __syncthreads();

        #pragma unroll
        for (int i = 0; i < 64; i++) acc[i] = 0.f;
        uint32_t kbase = sK0 + s * 2 * PLANE;
        #pragma unroll
        for (int ph = 0; ph < 3; ph++) {
            uint32_t abuf = (ph == 1) ? sQL : sQH;
            uint32_t bbuf = kbase + ((ph == 2) ? PLANE : 0);
            #pragma unroll
            for (int k16 = 0; k16 < 4; k16++) {
                uint32_t af[2][4];
                #pragma unroll
                for (int mi = 0; mi < 2; mi++)
                    ldsm4(abuf + (wm + mi * 16 + arow) * PITCH + (k16 * 16 + acol) * 2,
                          af[mi][0], af[mi][1], af[mi][2], af[mi][3]);
                uint32_t bfr[4][4];
                #pragma unroll
                for (int n2 = 0; n2 < 4; n2++)
                    ldsm4(bbuf + (wn + n2 * 16 + brow) * PITCH + (k16 * 16 + bcol) * 2,
                          bfr[n2][0], bfr[n2][1], bfr[n2][2], bfr[n2][3]);
                #pragma unroll
                for (int mi = 0; mi < 2; mi++)
                    #pragma unroll
                    for (int ni = 0; ni < 8; ni++)
                        mma16816(acc + (mi * 8 + ni) * 4, af[mi], bfr[ni >> 1] + (ni & 1) * 2);
            }
        }

        float tmax[4];
        #pragma unroll
        for (int mi = 0; mi < 2; mi++)
            #pragma unroll
            for (int half = 0; half < 2; half++) {
                int idx = mi * 2 + half;
                float vm = -1e30f;
                #pragma unroll
                for (int ni = 0; ni < 8; ni++) {
                    const float* a2 = acc + (mi * 8 + ni) * 4 + half * 2;
                    vm = fmaxf(vm, fmaxf(a2[0], a2[1]));
                }
                vm = fmaxf(vm, __shfl_xor_sync(0xffffffffu, vm, 1));
                vm = fmaxf(vm, __shfl_xor_sync(0xffffffffu, vm, 2));
                tmax[idx] = vm;
            }
        if ((lane & 3) == 0) {
            #pragma unroll
            for (int mi = 0; mi < 2; mi++)
                #pragma unroll
                for (int half = 0; half < 2; half++) {
                    int row = wm + mi * 16 + half * 8 + (lane >> 2);
                    stm[g * 128 + row] = tmax[mi * 2 + half];
                }
        }
        __syncthreads();

        float alpha[4], mnew[4];
        #pragma unroll
        for (int mi = 0; mi < 2; mi++)
            #pragma unroll
            for (int half = 0; half < 2; half++) {
                int idx = mi * 2 + half;
                int row = wm + mi * 16 + half * 8 + (lane >> 2);
                float tm = fmaxf(stm[row], stm[128 + row]);
                float mn = fmaxf(m_t[idx], tm);
                alpha[idx] = __expf(m_t[idx] - mn);
                mnew[idx] = mn;
                m_t[idx] = mn;
            }
        if (g == 0 && (lane & 3) == 0) {
            #pragma unroll
            for (int mi = 0; mi < 2; mi++)
                #pragma unroll
                for (int half = 0; half < 2; half++) {
                    int row = wm + mi * 16 + half * 8 + (lane >> 2);
                    Mbuf[(((long)z * 8 + t) << 10) + blockIdx.x * 128 + row] = mnew[mi * 2 + half];
                }
        }

        #pragma unroll
        for (int mi = 0; mi < 2; mi++)
            #pragma unroll
            for (int ni = 0; ni < 8; ni++)
                #pragma unroll
                for (int half = 0; half < 2; half++) {
                    float* o2 = oac + (mi * 8 + ni) * 4 + half * 2;
                    float a = alpha[mi * 2 + half];
                    o2[0] *= a; o2[1] *= a;
                }

        #pragma unroll
        for (int mi = 0; mi < 2; mi++)
            #pragma unroll
            for (int half = 0; half < 2; half++) {
                int idx = mi * 2 + half;
                float sum = 0.f;
                #pragma unroll
                for (int ni = 0; ni < 8; ni++) {
                    float* a2 = acc + (mi * 8 + ni) * 4 + half * 2;
                    a2[0] = __expf(a2[0] - mnew[idx]);
                    a2[1] = __expf(a2[1] - mnew[idx]);
                    sum += a2[0] + a2[1];
                }
                l_t[idx] = l_t[idx] * alpha[idx] + sum;
            }
        // write P'' as fp16
        #pragma unroll
        for (int mi = 0; mi < 2; mi++)
            #pragma unroll
            for (int ni = 0; ni < 8; ni++)
                #pragma unroll
                for (int half = 0; half < 2; half++) {
                    int row = wm + mi * 16 + half * 8 + (lane >> 2);
                    int n0 = t * 128 + wn + ni * 8 + (lane & 3) * 2;
                    const float* a2 = acc + (mi * 8 + ni) * 4 + half * 2;
                    __half2 o2 = __floats2half2_rn(a2[0], a2[1]);
                    *(__half2*)(Pz + (long)row * 1024 + n0) = o2;
                }

        uint32_t vb = sV0 + s * 2 * VPLANE;
        #pragma unroll
        for (int j = 0; j < 4; j++) {
            uint32_t ah[2][4], al[2][4];
            #pragma unroll
            for (int mi = 0; mi < 2; mi++) {
                const float* t0 = acc + (mi * 8 + 2 * j) * 4;
                const float* t1 = acc + (mi * 8 + 2 * j + 1) * 4;
                #pragma unroll
                for (int r = 0; r < 2; r++) {
                    bf16 h0, l0, h1, l1;
                    split1(t0[r * 2 + 0], h0, l0);
                    split1(t0[r * 2 + 1], h1, l1);
                    ah[mi][r] = pack_bf2(h0, h1);
                    al[mi][r] = pack_bf2(l0, l1);
                    bf16 g0, m0, g1, m1;
                    split1(t1[r * 2 + 0], g0, m0);
                    split1(t1[r * 2 + 1], g1, m1);
                    ah[mi][2 + r] = pack_bf2(g0, g1);
                    al[mi][2 + r] = pack_bf2(m0, m1);
                }
            }
            uint32_t bfr[4][4];
            #pragma unroll
            for (int n2 = 0; n2 < 4; n2++)
                ldsm4(vb + (n2 * 16 + brow) * VPITCH + (wn + j * 16 + bcol) * 2,
                      bfr[n2][0], bfr[n2][1], bfr[n2][2], bfr[n2][3]);
            #pragma unroll
            for (int mi = 0; mi < 2; mi++)
                #pragma unroll
                for (int ni = 0; ni < 8; ni++) {
                    mma16816(oac + (mi * 8 + ni) * 4, ah[mi], bfr[ni >> 1] + (ni & 1) * 2);
                    mma16816(oac + (mi * 8 + ni) * 4, al[mi], bfr[ni >> 1] + (ni & 1) * 2);
                }
            #pragma unroll
            for (int n2 = 0; n2 < 4; n2++)
                ldsm4(vb + VPLANE + (n2 * 16 + brow) * VPITCH + (wn + j * 16 + bcol) * 2,
                      bfr[n2][0], bfr[n2][1], bfr[n2][2], bfr[n2][3]);
            #pragma unroll
            for (int mi = 0; mi < 2; mi++)
                #pragma unroll
                for (int ni = 0; ni < 8; ni++)
                    mma16816(oac + (mi * 8 + ni) * 4, ah[mi], bfr[ni >> 1] + (ni & 1) * 2);
        }
        __syncthreads();
    }

    #pragma unroll
    for (int idx = 0; idx < 4; idx++) {
        l_t[idx] += __shfl_xor_sync(0xffffffffu, l_t[idx], 1);
        l_t[idx] += __shfl_xor_sync(0xffffffffu, l_t[idx], 2);
    }
    if ((lane & 3) == 0) {
        #pragma unroll
        for (int mi = 0; mi < 2; mi++)
            #pragma unroll
            for (int half = 0; half < 2; half++) {
                int row = wm + mi * 16 + half * 8 + (lane >> 2);
                stl[g * 128 + row] = l_t[mi * 2 + half];
            }
    }
    __syncthreads();
    float invl[4];
    #pragma unroll
    for (int mi = 0; mi < 2; mi++)
        #pragma unroll
        for (int half = 0; half < 2; half++) {
            int idx = mi * 2 + half;
            int row = wm + mi * 16 + half * 8 + (lane >> 2);
            float l = stl[row] + stl[128 + row];
            invl[idx] = 1.f / l;
            if (g == 0 && (lane & 3) == 0) {
                float2 ml; ml.x = m_t[idx]; ml.y = l;
                MLbuf[(long)z * 1024 + blockIdx.x * 128 + row] = ml;
            }
        }
    __syncthreads();

    float* ored = (float*)smem;
    if (g == 0) {
        #pragma unroll
        for (int mi = 0; mi < 2; mi++)
            #pragma unroll
            for (int ni = 0; ni < 8; ni++)
                #pragma unroll
                for (int half = 0; half < 2; half++) {
                    int row = wm + mi * 16 + half * 8 + (lane >> 2);
                    int col = ni * 8 + (lane & 3) * 2;
                    const float* a2 = oac + (mi * 8 + ni) * 4 + half * 2;
                    ored[row * 66 + col]     = a2[0];
                    ored[row * 66 + col + 1] = a2[1];
                }
    }
    __syncthreads();
    if (g == 1) {
        #pragma unroll
        for (int mi = 0; mi < 2; mi++)
            #pragma unroll
            for (int ni = 0; ni < 8; ni++)
                #pragma unroll
                for (int half = 0; half < 2; half++) {
                    int idx = mi * 2 + half;
                    int row = wm + mi * 16 + half * 8 + (lane >> 2);
                    int col = ni * 8 + (lane & 3) * 2;
                    const float* a2 = oac + (mi * 8 + ni) * 4 + half * 2;
                    float v0 = (ored[row * 66 + col]     + a2[0]) * invl[idx];
                    float v1 = (ored[row * 66 + col + 1] + a2[1]) * invl[idx];
                    bf16 h0, l0, h1, l1;
                    split1(v0, h0, l0); split1(v1, h1, l1);
                    *(uint32_t*)(Chb + (long)row * 512 + col) = pack_bf2(h0, h1);
                    *(uint32_t*)(Clb + (long)row * 512 + col) = pack_bf2(l0, l1);
                }
    }
}

// ================= corr factors: c = exp(m_used - m_fin) / l =================
__global__ void corr_kernel(const float* __restrict__ Mbuf,
                            const float2* __restrict__ MLbuf,
                            float* __restrict__ C)
{
    long i = (long)blockIdx.x * 256 + threadIdx.x;
    long z = i >> 13, q = i & 1023;
    float2 ml = MLbuf[z * 1024 + q];
    C[i] = __expf(Mbuf[i] - ml.x) / ml.y;
}

// ================= LayerNorm =================
__global__ void ln_kernel2(const float* __restrict__ x, const float* __restrict__ x2,
                           const float* __restrict__ w, const float* __restrict__ bb,
                           float* __restrict__ outf, bf16* __restrict__ ohi, bf16* __restrict__ olo)
{
    int row = blockIdx.x;
    int t = threadIdx.x;
    float4 v = ((const float4*)(x + (long)row * 512))[t];
    if (x2) {
        float4 v2 = ((const float4*)(x2 + (long)row * 512))[t];
        v.x += v2.x; v.y += v2.y; v.z += v2.z; v.w += v2.w;
    }
    float s  = v.x + v.y + v.z + v.w;
    float sq = v.x*v.x + v.y*v.y + v.z*v.z + v.w*v.w;
    #pragma unroll
    for (int o = 16; o > 0; o >>= 1) {
        s  += __shfl_xor_sync(0xffffffffu, s,  o);
        sq += __shfl_xor_sync(0xffffffffu, sq, o);
    }
    __shared__ float ss[4], ssq[4];
    int wid = t >> 5, lane = t & 31;
    if (lane == 0) { ss[wid] = s; ssq[wid] = sq; }
    __syncthreads();
    s  = ss[0]  + ss[1]  + ss[2]  + ss[3];
    sq = ssq[0] + ssq[1] + ssq[2] + ssq[3];
    float mu  = s * (1.0f / 512.0f);
    float var = sq * (1.0f / 512.0f) - mu * mu;
    float inv = rsqrtf(var + EPS);
    float4 wv = ((const float4*)w)[t];
    float4 bv = ((const float4*)bb)[t];
    float o4[4];
    o4[0] = (v.x - mu) * inv * wv.x + bv.x;
    o4[1] = (v.y - mu) * inv * wv.y + bv.y;
    o4[2] = (v.z - mu) * inv * wv.z + bv.z;
    o4[3] = (v.w - mu) * inv * wv.w + bv.w;
    long base = (long)row * 512 + t * 4;
    if (outf) *(float4*)(outf + base) = *(float4*)o4;
    if (ohi) {
        unsigned short hs[4], ls[4];
        #pragma unroll
        for (int j = 0; j < 4; j++) {
            bf16 h, l; split1(o4[j], h, l);
            hs[j] = __bfloat16_as_ushort(h);
            ls[j] = __bfloat16_as_ushort(l);
        }
        *(uint2*)(ohi + base) = *(uint2*)hs;
        *(uint2*)(olo + base) = *(uint2*)ls;
    }
}

// ================= split fp32 -> bf16 hi/lo =================
__global__ void split_kernel(const float* __restrict__ x, bf16* __restrict__ hi,
                             bf16* __restrict__ lo)
{
    long i = ((long)blockIdx.x * 256 + threadIdx.x) * 4;
    float4 v = *(const float4*)(x + i);
    float a[4] = {v.x, v.y, v.z, v.w};
    unsigned short hs[4], ls[4];
    #pragma unroll
    for (int j = 0; j < 4; j++) {
        bf16 h, l; split1(a[j], h, l);
        hs[j] = __bfloat16_as_ushort(h);
        ls[j] = __bfloat16_as_ushort(l);
    }
    *(uint2*)(hi + i) = *(uint2*)hs;
    *(uint2*)(lo + i) = *(uint2*)ls;
}

// transpose V: vt[b][n][s] = v[b*1024+s][n], split to hi/lo
__global__ void transpose_v_kernel(const float* __restrict__ v,
                                   bf16* __restrict__ vhi, bf16* __restrict__ vlo)
{
    __shared__ float t[32][33];
    int b = blockIdx.z;
    int s0 = blockIdx.x * 32, n0 = blockIdx.y * 32;
    int tx = threadIdx.x, ty = threadIdx.y;
    #pragma unroll
    for (int i = 0; i < 4; i++) {
        int s = s0 + ty + i * 8;
        t[ty + i * 8][tx] = v[((long)b * 1024 + s) * 512 + n0 + tx];
    }
    __syncthreads();
    #pragma unroll
    for (int i = 0; i < 4; i++) {
        int n = n0 + ty + i * 8;
        float vv = t[tx][ty + i * 8];
        bf16 h, l; split1(vv, h, l);
        long o = (long)b * 512 * 1024 + (long)n * 1024 + s0 + tx;
        vhi[o] = h; vlo[o] = l;
    }
}

// ================= attn_weights = (1/8) sum_h c * P'' (fp16 P) =================
__global__ void mean_corr(const __half* __restrict__ P, const float* __restrict__ C,
                          float* __restrict__ out)
{
    long i = ((long)blockIdx.x * 256 + threadIdx.x) * 4;   // over 8M
    long b = i >> 20;
    long rem = i & 1048575;
    long q = rem >> 10;
    long k = rem & 1023;
    long t = k >> 7;
    const __half* p = P + (b << 23) + rem;
    float4 s = {0.f, 0.f, 0.f, 0.f};
    #pragma unroll
    for (int h = 0; h < 8; h++) {
        long z = b * 8 + h;
        float c = C[((z * 8 + t) << 10) + q];
        const __half2* p2 = (const __half2*)(p + ((long)h << 20));
        float2 v0 = __half22float2(p2[0]);
        float2 v1 = __half22float2(p2[1]);
        s.x += c * v0.x; s.y += c * v0.y; s.z += c * v1.x; s.w += c * v1.y;
    }
    s.x *= 0.125f; s.y *= 0.125f; s.z *= 0.125f; s.w *= 0.125f;
    *(float4*)(out + i) = s;
}

// ================= launch =================
extern "C" void kernel_launch(void* const* d_in, const int* in_sizes, int n_in,
                              void* d_out, int out_size)
{
    (void)in_sizes; (void)n_in; (void)out_size;
    const float* Zab   = (const float*)d_in[0];
    const float* Za    = (const float*)d_in[1];
    const float* ln_w  = (const float*)d_in[2];
    const float* ln_b  = (const float*)d_in[3];
    const float* in_w  = (const float*)d_in[4];
    const float* in_b  = (const float*)d_in[5];
    const float* out_w = (const float*)d_in[6];
    const float* out_b = (const float*)d_in[7];
    const float* ff_w  = (const float*)d_in[8];
    const float* ff_b  = (const float*)d_in[9];

    float* out_final = (float*)d_out;
    float* out_attnw = (float*)d_out + 8192L * 512;

    bf16 *qin_hi, *qin_lo, *kvin_hi, *kvin_lo, *inw_hi, *inw_lo;
    bf16 *outw_hi, *outw_lo, *ffw_hi, *ffw_lo, *q_hi, *q_lo;
    bf16 *k_hi, *k_lo, *vt_hi, *vt_lo, *ctx_hi, *ctx_lo, *xn_hi, *xn_lo;
    float *v, *x, *xn, *ff, *mb, *cb;
    __half* p;
    float2 *mlb;
    cudaGetSymbolAddress((void**)&qin_hi,  g_qin_hi);
    cudaGetSymbolAddress((void**)&qin_lo,  g_qin_lo);
    cudaGetSymbolAddress((void**)&kvin_hi, g_kvin_hi);
    cudaGetSymbolAddress((void**)&kvin_lo, g_kvin_lo);
    cudaGetSymbolAddress((void**)&inw_hi,  g_inw_hi);
    cudaGetSymbolAddress((void**)&inw_lo,  g_inw_lo);
    cudaGetSymbolAddress((void**)&outw_hi, g_outw_hi);
    cudaGetSymbolAddress((void**)&outw_lo, g_outw_lo);
    cudaGetSymbolAddress((void**)&ffw_hi,  g_ffw_hi);
    cudaGetSymbolAddress((void**)&ffw_lo,  g_ffw_lo);
    cudaGetSymbolAddress((void**)&q_hi,    g_q_hi);
    cudaGetSymbolAddress((void**)&q_lo,    g_q_lo);
    cudaGetSymbolAddress((void**)&k_hi,    g_k_hi);
    cudaGetSymbolAddress((void**)&k_lo,    g_k_lo);
    cudaGetSymbolAddress((void**)&vt_hi,   g_vt_hi);
    cudaGetSymbolAddress((void**)&vt_lo,   g_vt_lo);
    cudaGetSymbolAddress((void**)&ctx_hi,  g_ctx_hi);
    cudaGetSymbolAddress((void**)&ctx_lo,  g_ctx_lo);
    cudaGetSymbolAddress((void**)&xn_hi,   g_xn_hi);
    cudaGetSymbolAddress((void**)&xn_lo,   g_xn_lo);
    cudaGetSymbolAddress((void**)&v,   g_v);
    cudaGetSymbolAddress((void**)&p,   g_p);
    cudaGetSymbolAddress((void**)&x,   g_x);
    cudaGetSymbolAddress((void**)&xn,  g_xn);
    cudaGetSymbolAddress((void**)&ff,  g_ff);
    cudaGetSymbolAddress((void**)&mb,  g_m);
    cudaGetSymbolAddress((void**)&mlb, g_ml);
    cudaGetSymbolAddress((void**)&cb,  g_c);

    const int SMEM_PI  = 2 * (2 * 128 * 80 + 2 * 128 * 80);           // 81920
    const int SMEM_ATT = 6 * 128 * 144 + 4 * 64 * 272 + 2048;         // 182272
    cudaFuncSetAttribute((const void*)proj_qkv,
                         cudaFuncAttributeMaxDynamicSharedMemorySize, SMEM_PI);
    cudaFuncSetAttribute((const void*)gemm_pi,
                         cudaFuncAttributeMaxDynamicSharedMemorySize, SMEM_PI);
    cudaFuncSetAttribute((const void*)attn_flash,
                         cudaFuncAttributeMaxDynamicSharedMemorySize, SMEM_ATT);

    // 1) LN of inputs -> bf16 hi/lo
    ln_kernel2<<<8192, 128>>>(Zab, nullptr, ln_w, ln_b, nullptr, qin_hi, qin_lo);
    ln_kernel2<<<8192, 128>>>(Za,  nullptr, ln_w, ln_b, nullptr, kvin_hi, kvin_lo);

    // 2) split weights
    split_kernel<<<768, 256>>>(in_w,  inw_hi,  inw_lo);
    split_kernel<<<256, 256>>>(out_w, outw_hi, outw_lo);
    split_kernel<<<256, 256>>>(ff_w,  ffw_hi,  ffw_lo);

    // 3) fused q/k/v projections (one launch, grid.z selects)
    proj_qkv<<<dim3(4, 64, 3), 256, SMEM_PI>>>(
        qin_hi, qin_lo, kvin_hi, kvin_lo, inw_hi, inw_lo, in_b,
        q_hi, q_lo, k_hi, k_lo, v);

    // 4) V -> transposed hi/lo
    transpose_v_kernel<<<dim3(32, 16, 8), dim3(32, 8)>>>(v, vt_hi, vt_lo);

    // 5) single-pass flash attention -> P'' fp16, m/ml bufs, ctx hi/lo
    attn_flash<<<dim3(8, 1, 64), 256, SMEM_ATT>>>(
        q_hi, q_lo, k_hi, k_lo, vt_hi, vt_lo, p, mb, mlb, ctx_hi, ctx_lo);

    // 6) corr factors, then attn_weights = (1/8) sum_h c * P''
    corr_kernel<<<2048, 256>>>(mb, mlb, cb);
    mean_corr<<<8192, 256>>>(p, cb, out_attnw);

    // 7) x = ctx @ Wo^T + bo + Zab
    gemm_pi<<<dim3(4, 64, 1), 256, SMEM_PI>>>(
        ctx_hi, ctx_lo, outw_hi, outw_lo,
        x, nullptr, nullptr, 1.0f, out_b, Zab);

    // 8) x_n = LN(x)
    ln_kernel2<<<8192, 128>>>(x, nullptr, ln_w, ln_b, xn, xn_hi, xn_lo);

    // 9) ff = x_n @ ff_w^T + ff_b
    gemm_pi<<<dim3(4, 64, 1), 256, SMEM_PI>>>(
        xn_hi, xn_lo, ffw_hi, ffw_lo,
        ff, nullptr, nullptr, 1.0f, ff_b, nullptr);

    // 10) final = LN(x_n + ff) -> d_out
    ln_kernel2<<<8192, 128>>>(xn, ff, ln_w, ln_b, out_final, nullptr, nullptr);
}